// round 6
// baseline (speedup 1.0000x reference)
#include <cuda_runtime.h>
#include <cuda_bf16.h>
#include <cstdint>

#define NB   32      // batch
#define LL   512     // sequence length
#define DIN  512
#define DQK  128
#define DS   256
#define DMLP 128
#define LLSQ (LL*LL) // 262144

// ---------------- device scratch (static: allocation-free) ----------------
__device__ float g_q[NB * LL * DQK];     // 8.4 MB
__device__ float g_k[NB * LL * DQK];
__device__ float g_v[NB * LL * DQK];
__device__ float g_h[NB * DMLP];
__device__ float g_bias[NB * LLSQ];      // 33.5 MB

// =====================================================================
// Projection GEMM:  Y[M,128] = X[M,512] @ W[512,128] + b
// M = B*L = 16384.  Tile 64x128, 256 threads, 8x4 micro-tile per thread.
// which: 0 -> g_q, 1 -> g_k, 2 -> g_v
// =====================================================================
__global__ __launch_bounds__(256) void proj_kernel(const float* __restrict__ X,
                                                   const float* __restrict__ W,
                                                   const float* __restrict__ bias,
                                                   int which) {
    __shared__ float As[64][16];    // [m][k]
    __shared__ float Bs[16][128];   // [k][n]

    float* __restrict__ Y = (which == 0) ? g_q : (which == 1) ? g_k : g_v;

    const int t = threadIdx.x;
    const int block_row = blockIdx.x * 64;
    const int rr = t >> 5;          // 0..7 : rows rr*8 .. rr*8+7 (uniform in warp)
    const int cr = t & 31;          // 0..31: cols cr*4 .. cr*4+3

    float acc[8][4];
#pragma unroll
    for (int i = 0; i < 8; i++)
#pragma unroll
        for (int j = 0; j < 4; j++) acc[i][j] = 0.f;

    const int xr  = t >> 2;         // 0..63
    const int xk4 = (t & 3) * 4;    // 0,4,8,12
    const int wk  = t >> 5;         // 0..7
    const int wc  = (t & 31) * 4;

    for (int k0 = 0; k0 < DIN; k0 += 16) {
        *(float4*)&As[xr][xk4] =
            *(const float4*)&X[(size_t)(block_row + xr) * DIN + k0 + xk4];
        *(float4*)&Bs[wk][wc] =
            *(const float4*)&W[(size_t)(k0 + wk) * DQK + wc];
        *(float4*)&Bs[wk + 8][wc] =
            *(const float4*)&W[(size_t)(k0 + wk + 8) * DQK + wc];
        __syncthreads();

#pragma unroll
        for (int kk = 0; kk < 16; kk += 4) {
            float4 a4[8];
#pragma unroll
            for (int i = 0; i < 8; i++) a4[i] = *(float4*)&As[rr * 8 + i][kk];
#pragma unroll
            for (int u = 0; u < 4; u++) {
                float4 b4 = *(float4*)&Bs[kk + u][cr * 4];
#pragma unroll
                for (int i = 0; i < 8; i++) {
                    float a = (&a4[i].x)[u];
                    acc[i][0] = fmaf(a, b4.x, acc[i][0]);
                    acc[i][1] = fmaf(a, b4.y, acc[i][1]);
                    acc[i][2] = fmaf(a, b4.z, acc[i][2]);
                    acc[i][3] = fmaf(a, b4.w, acc[i][3]);
                }
            }
        }
        __syncthreads();
    }

    float4 bv = *(const float4*)&bias[cr * 4];
#pragma unroll
    for (int i = 0; i < 8; i++) {
        float4 o = make_float4(acc[i][0] + bv.x, acc[i][1] + bv.y,
                               acc[i][2] + bv.z, acc[i][3] + bv.w);
        *(float4*)&Y[(size_t)(block_row + rr * 8 + i) * DQK + cr * 4] = o;
    }
}

// =====================================================================
// Bias MLP stage 1: h = relu(sf @ Wb1 + bb1)   [32,256]@[256,128]
// =====================================================================
__global__ __launch_bounds__(128) void mlp1_kernel(const float* __restrict__ sf,
                                                   const float* __restrict__ Wb1,
                                                   const float* __restrict__ bb1) {
    __shared__ float s[DS];
    const int b = blockIdx.x, t = threadIdx.x;
    s[t]       = sf[b * DS + t];
    s[t + 128] = sf[b * DS + t + 128];
    __syncthreads();
    float acc = bb1[t];
#pragma unroll 4
    for (int k = 0; k < DS; k++) acc = fmaf(s[k], Wb1[(size_t)k * DMLP + t], acc);
    g_h[b * DMLP + t] = fmaxf(acc, 0.f);
}

// =====================================================================
// Bias MLP stage 2: bias = h @ Wb2 + bb2  -> g_bias[32][262144]
// One thread per output column, 32 batch accumulators, k unrolled x4.
// =====================================================================
__global__ __launch_bounds__(256) void bias_kernel(const float* __restrict__ Wb2,
                                                   const float* __restrict__ bb2) {
    __shared__ float hs[NB * DMLP];   // 16 KB
    const int t = threadIdx.x;
    for (int i = t; i < NB * DMLP; i += 256) hs[i] = g_h[i];
    __syncthreads();

    const int n = blockIdx.x * 256 + t;
    const float bb = bb2[n];
    float acc[NB];
#pragma unroll
    for (int b = 0; b < NB; b++) acc[b] = bb;

    for (int k = 0; k < DMLP; k += 4) {
        float w0 = Wb2[(size_t)(k + 0) * LLSQ + n];
        float w1 = Wb2[(size_t)(k + 1) * LLSQ + n];
        float w2 = Wb2[(size_t)(k + 2) * LLSQ + n];
        float w3 = Wb2[(size_t)(k + 3) * LLSQ + n];
#pragma unroll
        for (int b = 0; b < NB; b++) {
            float4 h4 = *(float4*)&hs[b * DMLP + k];
            float a = acc[b];
            a = fmaf(h4.x, w0, a);
            a = fmaf(h4.y, w1, a);
            a = fmaf(h4.z, w2, a);
            a = fmaf(h4.w, w3, a);
            acc[b] = a;
        }
    }
#pragma unroll
    for (int b = 0; b < NB; b++) g_bias[(size_t)b * LLSQ + n] = acc[b];
}

// =====================================================================
// Fused attention:
//   S = QK^T / sqrt(128); masked positions -> 1e-9 (pre-softmax, faithful)
//   A = softmax(S) + bias  (bias added AFTER softmax)
//   out = A @ V
// One CTA per (batch, 64-row tile). Scores tile fully resident in smem.
// Mask is read as 32-bit words (nonzero == true): correct for both an
// int32-coerced and a float32-coerced bool array.
// Dynamic smem layout:
//   [0, 32768)       Qs   [64][128] f32
//   [32768, 163840)  Ss   [64][512] f32
//   [163840, 197632) Kts  [128][66] f32 (transposed K tile, padded)
//                    / Vs [64][128] f32 (reused buffer)
// =====================================================================
#define SM_Q   0
#define SM_S   32768
#define SM_KV  163840
#define KV_PAD 66
#define ATTN_SMEM 197632

__global__ __launch_bounds__(256) void attn_kernel(const unsigned int* __restrict__ mask,
                                                   float* __restrict__ out) {
    extern __shared__ char smem[];
    float (*Qs)[DQK]     = (float (*)[DQK])(smem + SM_Q);
    float (*Ss)[LL]      = (float (*)[LL])(smem + SM_S);
    float (*Kts)[KV_PAD] = (float (*)[KV_PAD])(smem + SM_KV);
    float (*Vs)[DQK]     = (float (*)[DQK])(smem + SM_KV);

    const int t    = threadIdx.x;
    const int lane = t & 31;
    const int warp = t >> 5;            // 0..7, uniform row group per warp
    const int b    = blockIdx.y;
    const int row0 = blockIdx.x * 64;

    const float* __restrict__ qb = g_q + (size_t)b * LL * DQK;
    const float* __restrict__ kb = g_k + (size_t)b * LL * DQK;
    const float* __restrict__ vb = g_v + (size_t)b * LL * DQK;

    // ---- load Q tile [64][128]
    for (int i = t; i < 64 * 32; i += 256) {
        int r = i >> 5, c4 = (i & 31) * 4;
        *(float4*)&Qs[r][c4] = *(const float4*)&qb[(size_t)(row0 + r) * DQK + c4];
    }

    const float inv_scale = 0.08838834764831845f;   // 1/sqrt(128)

    // ---- stage 1: scores
    for (int ct = 0; ct < 8; ct++) {
        __syncthreads();   // guard Kts reuse (and Qs load on first pass)
        for (int i = t; i < 64 * 32; i += 256) {
            int r = i >> 5, c4 = (i & 31) * 4;
            float4 k4 = *(const float4*)&kb[(size_t)(ct * 64 + r) * DQK + c4];
            Kts[c4 + 0][r] = k4.x; Kts[c4 + 1][r] = k4.y;
            Kts[c4 + 2][r] = k4.z; Kts[c4 + 3][r] = k4.w;
        }
        __syncthreads();

        float acc[8][2];
#pragma unroll
        for (int i = 0; i < 8; i++) { acc[i][0] = 0.f; acc[i][1] = 0.f; }

        for (int d = 0; d < DQK; d += 4) {
            float4 a4[8];
#pragma unroll
            for (int i = 0; i < 8; i++) a4[i] = *(float4*)&Qs[warp * 8 + i][d];
#pragma unroll
            for (int u = 0; u < 4; u++) {
                float2 b2 = *(float2*)&Kts[d + u][lane * 2];
#pragma unroll
                for (int i = 0; i < 8; i++) {
                    float a = (&a4[i].x)[u];
                    acc[i][0] = fmaf(a, b2.x, acc[i][0]);
                    acc[i][1] = fmaf(a, b2.y, acc[i][1]);
                }
            }
        }
        // apply scale + mask, store to Ss
        const int cg = ct * 64 + lane * 2;
#pragma unroll
        for (int i = 0; i < 8; i++) {
            const int rg = row0 + warp * 8 + i;
            const unsigned int* mrow = mask + (size_t)(b * LL + rg) * LL + cg;
            float v0 = (mrow[0] != 0u) ? 1e-9f : acc[i][0] * inv_scale;
            float v1 = (mrow[1] != 0u) ? 1e-9f : acc[i][1] * inv_scale;
            *(float2*)&Ss[warp * 8 + i][cg] = make_float2(v0, v1);
        }
    }
    __syncthreads();

    // ---- softmax per row + bias add (bias AFTER softmax)
    for (int j = 0; j < 8; j++) {
        const int r = warp * 8 + j;
        float mx = -1e30f;
        for (int m = lane; m < LL; m += 32) mx = fmaxf(mx, Ss[r][m]);
#pragma unroll
        for (int o = 16; o > 0; o >>= 1) mx = fmaxf(mx, __shfl_xor_sync(0xffffffffu, mx, o));
        float sum = 0.f;
        for (int m = lane; m < LL; m += 32) {
            float e = __expf(Ss[r][m] - mx);
            Ss[r][m] = e;
            sum += e;
        }
#pragma unroll
        for (int o = 16; o > 0; o >>= 1) sum += __shfl_xor_sync(0xffffffffu, sum, o);
        const float inv = 1.0f / sum;
        const float* __restrict__ brow = g_bias + (size_t)(b * LL + row0 + r) * LL;
        for (int m = lane; m < LL; m += 32) Ss[r][m] = Ss[r][m] * inv + brow[m];
    }
    __syncthreads();

    // ---- stage 2: out = A @ V
    float acc2[8][4];
#pragma unroll
    for (int i = 0; i < 8; i++)
#pragma unroll
        for (int j = 0; j < 4; j++) acc2[i][j] = 0.f;

    for (int mt = 0; mt < 8; mt++) {
        for (int i = t; i < 64 * 32; i += 256) {
            int r = i >> 5, c4 = (i & 31) * 4;
            *(float4*)&Vs[r][c4] = *(const float4*)&vb[(size_t)(mt * 64 + r) * DQK + c4];
        }
        __syncthreads();
        for (int m = 0; m < 64; m += 4) {
            float4 a4[8];
#pragma unroll
            for (int i = 0; i < 8; i++)
                a4[i] = *(float4*)&Ss[warp * 8 + i][mt * 64 + m];
#pragma unroll
            for (int u = 0; u < 4; u++) {
                float4 b4 = *(float4*)&Vs[m + u][lane * 4];
#pragma unroll
                for (int i = 0; i < 8; i++) {
                    float a = (&a4[i].x)[u];
                    acc2[i][0] = fmaf(a, b4.x, acc2[i][0]);
                    acc2[i][1] = fmaf(a, b4.y, acc2[i][1]);
                    acc2[i][2] = fmaf(a, b4.z, acc2[i][2]);
                    acc2[i][3] = fmaf(a, b4.w, acc2[i][3]);
                }
            }
        }
        __syncthreads();
    }

#pragma unroll
    for (int i = 0; i < 8; i++) {
        *(float4*)&out[(size_t)(b * LL + row0 + warp * 8 + i) * DQK + lane * 4] =
            make_float4(acc2[i][0], acc2[i][1], acc2[i][2], acc2[i][3]);
    }
}

// =====================================================================
// Launch: 6 kernel launches, graph-capturable, allocation-free.
// Input order per metadata: query, key, value, sf, atten_mask,
//   Wq, bq, Wk, bk, Wv, bv, Wb1, bb1, Wb2, bb2
// =====================================================================
extern "C" void kernel_launch(void* const* d_in, const int* in_sizes, int n_in,
                              void* d_out, int out_size) {
    const float* query = (const float*)d_in[0];
    const float* key_  = (const float*)d_in[1];
    const float* value = (const float*)d_in[2];
    const float* sf    = (const float*)d_in[3];
    const unsigned int* mask = (const unsigned int*)d_in[4];
    const float* Wq  = (const float*)d_in[5];
    const float* bq  = (const float*)d_in[6];
    const float* Wk  = (const float*)d_in[7];
    const float* bk  = (const float*)d_in[8];
    const float* Wv  = (const float*)d_in[9];
    const float* bv  = (const float*)d_in[10];
    const float* Wb1 = (const float*)d_in[11];
    const float* bb1 = (const float*)d_in[12];
    const float* Wb2 = (const float*)d_in[13];
    const float* bb2 = (const float*)d_in[14];
    float* out = (float*)d_out;

    (void)in_sizes; (void)n_in; (void)out_size;

    proj_kernel<<<NB * LL / 64, 256>>>(query, Wq, bq, 0);
    proj_kernel<<<NB * LL / 64, 256>>>(key_,  Wk, bk, 1);
    proj_kernel<<<NB * LL / 64, 256>>>(value, Wv, bv, 2);
    mlp1_kernel<<<NB, 128>>>(sf, Wb1, bb1);
    bias_kernel<<<LLSQ / 256, 256>>>(Wb2, bb2);

    cudaFuncSetAttribute(attn_kernel,
                         cudaFuncAttributeMaxDynamicSharedMemorySize, ATTN_SMEM);
    attn_kernel<<<dim3(LL / 64, NB), 256, ATTN_SMEM>>>(mask, out);
}

// round 7
// speedup vs baseline: 1.1212x; 1.1212x over previous
#include <cuda_runtime.h>
#include <cuda_bf16.h>
#include <cstdint>

#define NB   32      // batch
#define LL   512     // sequence length
#define DIN  512
#define DQK  128
#define DS   256
#define DMLP 128
#define LLSQ (LL*LL) // 262144

// ---------------- device scratch (static: allocation-free) ----------------
__device__ float g_q[NB * LL * DQK];     // 8.4 MB
__device__ float g_k[NB * LL * DQK];
__device__ float g_v[NB * LL * DQK];
__device__ float g_h[NB * DMLP];
__device__ float g_bias[NB * LLSQ];      // 33.5 MB

// =====================================================================
// Merged projection GEMM:  Y[M,128] = X[M,512] @ W[512,128] + b  (x3)
// grid = (256, 3): blockIdx.y selects {q,k,v}. Tile 64x128, 256 thr,
// 8x4 micro-tile. A-operand smem reads are warp-broadcast.
// =====================================================================
__global__ __launch_bounds__(256) void proj3_kernel(
        const float* __restrict__ Xq, const float* __restrict__ Xk,
        const float* __restrict__ Xv,
        const float* __restrict__ Wq, const float* __restrict__ Wk,
        const float* __restrict__ Wv,
        const float* __restrict__ bq, const float* __restrict__ bk,
        const float* __restrict__ bv) {
    __shared__ float As[64][16];    // [m][k]
    __shared__ float Bs[16][128];   // [k][n]

    const float* X; const float* W; const float* Bb; float* Y;
    if (blockIdx.y == 0)      { X = Xq; W = Wq; Bb = bq; Y = g_q; }
    else if (blockIdx.y == 1) { X = Xk; W = Wk; Bb = bk; Y = g_k; }
    else                      { X = Xv; W = Wv; Bb = bv; Y = g_v; }

    const int t = threadIdx.x;
    const int block_row = blockIdx.x * 64;
    const int rr = t >> 5;          // 0..7 : rows rr*8 .. rr*8+7 (warp-uniform)
    const int cr = t & 31;          // 0..31: cols cr*4 .. cr*4+3

    float acc[8][4];
#pragma unroll
    for (int i = 0; i < 8; i++)
#pragma unroll
        for (int j = 0; j < 4; j++) acc[i][j] = 0.f;

    const int xr  = t >> 2;         // 0..63
    const int xk4 = (t & 3) * 4;    // 0,4,8,12
    const int wk  = t >> 5;         // 0..7
    const int wc  = (t & 31) * 4;

    for (int k0 = 0; k0 < DIN; k0 += 16) {
        *(float4*)&As[xr][xk4] =
            *(const float4*)&X[(size_t)(block_row + xr) * DIN + k0 + xk4];
        *(float4*)&Bs[wk][wc] =
            *(const float4*)&W[(size_t)(k0 + wk) * DQK + wc];
        *(float4*)&Bs[wk + 8][wc] =
            *(const float4*)&W[(size_t)(k0 + wk + 8) * DQK + wc];
        __syncthreads();

#pragma unroll
        for (int kk = 0; kk < 16; kk += 4) {
            float4 a4[8];
#pragma unroll
            for (int i = 0; i < 8; i++) a4[i] = *(float4*)&As[rr * 8 + i][kk];
#pragma unroll
            for (int u = 0; u < 4; u++) {
                float4 b4 = *(float4*)&Bs[kk + u][cr * 4];
#pragma unroll
                for (int i = 0; i < 8; i++) {
                    float a = (&a4[i].x)[u];
                    acc[i][0] = fmaf(a, b4.x, acc[i][0]);
                    acc[i][1] = fmaf(a, b4.y, acc[i][1]);
                    acc[i][2] = fmaf(a, b4.z, acc[i][2]);
                    acc[i][3] = fmaf(a, b4.w, acc[i][3]);
                }
            }
        }
        __syncthreads();
    }

    float4 bvv = *(const float4*)&Bb[cr * 4];
#pragma unroll
    for (int i = 0; i < 8; i++) {
        float4 o = make_float4(acc[i][0] + bvv.x, acc[i][1] + bvv.y,
                               acc[i][2] + bvv.z, acc[i][3] + bvv.w);
        *(float4*)&Y[(size_t)(block_row + rr * 8 + i) * DQK + cr * 4] = o;
    }
}

// =====================================================================
// Bias MLP stage 1: h = relu(sf @ Wb1 + bb1)   [32,256]@[256,128]
// One warp per output element, 4096 warps = 512 CTAs -> full-chip.
// =====================================================================
__global__ __launch_bounds__(256) void mlp1_kernel(const float* __restrict__ sf,
                                                   const float* __restrict__ Wb1,
                                                   const float* __restrict__ bb1) {
    const int gw   = blockIdx.x * 8 + (threadIdx.x >> 5);   // 0..4095
    const int lane = threadIdx.x & 31;
    const int b    = gw >> 7;          // 0..31
    const int n    = gw & 127;         // 0..127

    float s = 0.f;
#pragma unroll
    for (int kk = 0; kk < 8; kk++) {
        int k = kk * 32 + lane;
        s = fmaf(sf[b * DS + k], Wb1[(size_t)k * DMLP + n], s);
    }
#pragma unroll
    for (int o = 16; o > 0; o >>= 1) s += __shfl_xor_sync(0xffffffffu, s, o);
    if (lane == 0) g_h[b * DMLP + n] = fmaxf(s + bb1[n], 0.f);
}

// =====================================================================
// Bias MLP stage 2: bias = h @ Wb2 + bb2  -> g_bias[32][262144]
// =====================================================================
__global__ __launch_bounds__(256) void bias_kernel(const float* __restrict__ Wb2,
                                                   const float* __restrict__ bb2) {
    __shared__ float hs[NB * DMLP];   // 16 KB
    const int t = threadIdx.x;
    for (int i = t; i < NB * DMLP; i += 256) hs[i] = g_h[i];
    __syncthreads();

    const int n = blockIdx.x * 256 + t;
    const float bb = bb2[n];
    float acc[NB];
#pragma unroll
    for (int b = 0; b < NB; b++) acc[b] = bb;

    for (int k = 0; k < DMLP; k += 4) {
        float w0 = Wb2[(size_t)(k + 0) * LLSQ + n];
        float w1 = Wb2[(size_t)(k + 1) * LLSQ + n];
        float w2 = Wb2[(size_t)(k + 2) * LLSQ + n];
        float w3 = Wb2[(size_t)(k + 3) * LLSQ + n];
#pragma unroll
        for (int b = 0; b < NB; b++) {
            float4 h4 = *(float4*)&hs[b * DMLP + k];
            float a = acc[b];
            a = fmaf(h4.x, w0, a);
            a = fmaf(h4.y, w1, a);
            a = fmaf(h4.z, w2, a);
            a = fmaf(h4.w, w3, a);
            acc[b] = a;
        }
    }
#pragma unroll
    for (int b = 0; b < NB; b++) g_bias[(size_t)b * LLSQ + n] = acc[b];
}

// =====================================================================
// Fused attention, occupancy-2 version:
//   32 query rows per CTA -> smem 115712 B -> 2 CTAs/SM (16 warps).
//   S = QK^T/sqrt(128), mask -> 1e-9; A = softmax(S) + bias; out = A@V.
// grid = (16, 32) = 512 CTAs, 256 threads, warp owns 4 rows.
// smem: Qs[32][128] @0 (16384) | Ss[32][512] @16384 (65536)
//       Kts[128][66] / Vs[64][128] union @81920 (33792)
// =====================================================================
#define SM_Q   0
#define SM_S   16384
#define SM_KV  81920
#define KV_PAD 66
#define ATTN_SMEM 115712

__global__ __launch_bounds__(256) void attn_kernel(const unsigned int* __restrict__ mask,
                                                   float* __restrict__ out) {
    extern __shared__ char smem[];
    float (*Qs)[DQK]     = (float (*)[DQK])(smem + SM_Q);
    float (*Ss)[LL]      = (float (*)[LL])(smem + SM_S);
    float (*Kts)[KV_PAD] = (float (*)[KV_PAD])(smem + SM_KV);
    float (*Vs)[DQK]     = (float (*)[DQK])(smem + SM_KV);

    const int t    = threadIdx.x;
    const int lane = t & 31;
    const int warp = t >> 5;            // 0..7, owns rows warp*4..warp*4+3
    const int b    = blockIdx.y;
    const int row0 = blockIdx.x * 32;

    const float* __restrict__ qb = g_q + (size_t)b * LL * DQK;
    const float* __restrict__ kb = g_k + (size_t)b * LL * DQK;
    const float* __restrict__ vb = g_v + (size_t)b * LL * DQK;

    // ---- load Q tile [32][128]
    for (int i = t; i < 32 * 32; i += 256) {
        int r = i >> 5, c4 = (i & 31) * 4;
        *(float4*)&Qs[r][c4] = *(const float4*)&qb[(size_t)(row0 + r) * DQK + c4];
    }

    const float inv_scale = 0.08838834764831845f;   // 1/sqrt(128)

    // ---- stage 1: scores, K in 8 tiles of 64 key-rows
    for (int ct = 0; ct < 8; ct++) {
        __syncthreads();   // guard Kts reuse (and Qs load on first pass)
        for (int i = t; i < 64 * 32; i += 256) {
            int r = i >> 5, c4 = (i & 31) * 4;
            float4 k4 = *(const float4*)&kb[(size_t)(ct * 64 + r) * DQK + c4];
            Kts[c4 + 0][r] = k4.x; Kts[c4 + 1][r] = k4.y;
            Kts[c4 + 2][r] = k4.z; Kts[c4 + 3][r] = k4.w;
        }
        __syncthreads();

        float acc[4][2];
#pragma unroll
        for (int i = 0; i < 4; i++) { acc[i][0] = 0.f; acc[i][1] = 0.f; }

        for (int d = 0; d < DQK; d += 4) {
            float4 a4[4];
#pragma unroll
            for (int i = 0; i < 4; i++) a4[i] = *(float4*)&Qs[warp * 4 + i][d];
#pragma unroll
            for (int u = 0; u < 4; u++) {
                float2 b2 = *(float2*)&Kts[d + u][lane * 2];
#pragma unroll
                for (int i = 0; i < 4; i++) {
                    float a = (&a4[i].x)[u];
                    acc[i][0] = fmaf(a, b2.x, acc[i][0]);
                    acc[i][1] = fmaf(a, b2.y, acc[i][1]);
                }
            }
        }
        const int cg = ct * 64 + lane * 2;
#pragma unroll
        for (int i = 0; i < 4; i++) {
            const int rg = row0 + warp * 4 + i;
            const unsigned int* mrow = mask + (size_t)(b * LL + rg) * LL + cg;
            float v0 = (mrow[0] != 0u) ? 1e-9f : acc[i][0] * inv_scale;
            float v1 = (mrow[1] != 0u) ? 1e-9f : acc[i][1] * inv_scale;
            *(float2*)&Ss[warp * 4 + i][cg] = make_float2(v0, v1);
        }
    }

    // ---- softmax per row + bias add (rows are warp-private; no sync needed)
#pragma unroll
    for (int j = 0; j < 4; j++) {
        const int r = warp * 4 + j;
        float mx = -1e30f;
        for (int m = lane; m < LL; m += 32) mx = fmaxf(mx, Ss[r][m]);
#pragma unroll
        for (int o = 16; o > 0; o >>= 1) mx = fmaxf(mx, __shfl_xor_sync(0xffffffffu, mx, o));
        float sum = 0.f;
        for (int m = lane; m < LL; m += 32) {
            float e = __expf(Ss[r][m] - mx);
            Ss[r][m] = e;
            sum += e;
        }
#pragma unroll
        for (int o = 16; o > 0; o >>= 1) sum += __shfl_xor_sync(0xffffffffu, sum, o);
        const float inv = 1.0f / sum;
        const float* __restrict__ brow = g_bias + (size_t)(b * LL + row0 + r) * LL;
        for (int m = lane; m < LL; m += 32) Ss[r][m] = Ss[r][m] * inv + brow[m];
    }

    // ---- stage 2: out = A @ V, V in 8 tiles of 64 rows
    float acc2[4][4];
#pragma unroll
    for (int i = 0; i < 4; i++)
#pragma unroll
        for (int j = 0; j < 4; j++) acc2[i][j] = 0.f;

    for (int mt = 0; mt < 8; mt++) {
        __syncthreads();   // prev compute (or stage-1 Kts reads) done before Vs overwrite
        for (int i = t; i < 64 * 32; i += 256) {
            int r = i >> 5, c4 = (i & 31) * 4;
            *(float4*)&Vs[r][c4] = *(const float4*)&vb[(size_t)(mt * 64 + r) * DQK + c4];
        }
        __syncthreads();
        for (int m = 0; m < 64; m += 4) {
            float4 a4[4];
#pragma unroll
            for (int i = 0; i < 4; i++)
                a4[i] = *(float4*)&Ss[warp * 4 + i][mt * 64 + m];
#pragma unroll
            for (int u = 0; u < 4; u++) {
                float4 b4 = *(float4*)&Vs[m + u][lane * 4];
#pragma unroll
                for (int i = 0; i < 4; i++) {
                    float a = (&a4[i].x)[u];
                    acc2[i][0] = fmaf(a, b4.x, acc2[i][0]);
                    acc2[i][1] = fmaf(a, b4.y, acc2[i][1]);
                    acc2[i][2] = fmaf(a, b4.z, acc2[i][2]);
                    acc2[i][3] = fmaf(a, b4.w, acc2[i][3]);
                }
            }
        }
    }

#pragma unroll
    for (int i = 0; i < 4; i++) {
        *(float4*)&out[(size_t)(b * LL + row0 + warp * 4 + i) * DQK + lane * 4] =
            make_float4(acc2[i][0], acc2[i][1], acc2[i][2], acc2[i][3]);
    }
}

// =====================================================================
// Launch: 4 kernel launches, graph-capturable, allocation-free.
// =====================================================================
extern "C" void kernel_launch(void* const* d_in, const int* in_sizes, int n_in,
                              void* d_out, int out_size) {
    const float* query = (const float*)d_in[0];
    const float* key_  = (const float*)d_in[1];
    const float* value = (const float*)d_in[2];
    const float* sf    = (const float*)d_in[3];
    const unsigned int* mask = (const unsigned int*)d_in[4];
    const float* Wq  = (const float*)d_in[5];
    const float* bq  = (const float*)d_in[6];
    const float* Wk  = (const float*)d_in[7];
    const float* bk  = (const float*)d_in[8];
    const float* Wv  = (const float*)d_in[9];
    const float* bv  = (const float*)d_in[10];
    const float* Wb1 = (const float*)d_in[11];
    const float* bb1 = (const float*)d_in[12];
    const float* Wb2 = (const float*)d_in[13];
    const float* bb2 = (const float*)d_in[14];
    float* out = (float*)d_out;

    (void)in_sizes; (void)n_in; (void)out_size;

    proj3_kernel<<<dim3(NB * LL / 64, 3), 256>>>(query, key_, value,
                                                 Wq, Wk, Wv, bq, bk, bv);
    mlp1_kernel<<<512, 256>>>(sf, Wb1, bb1);
    bias_kernel<<<LLSQ / 256, 256>>>(Wb2, bb2);

    cudaFuncSetAttribute(attn_kernel,
                         cudaFuncAttributeMaxDynamicSharedMemorySize, ATTN_SMEM);
    attn_kernel<<<dim3(LL / 32, NB), 256, ATTN_SMEM>>>(mask, out);
}

// round 9
// speedup vs baseline: 1.2719x; 1.1344x over previous
#include <cuda_runtime.h>
#include <cuda_bf16.h>
#include <mma.h>
#include <cstdint>

using namespace nvcuda;

#define NB   32      // batch
#define LL   512     // sequence length
#define DIN  512
#define DQK  128
#define DS   256
#define DMLP 128
#define LLSQ (LL*LL) // 262144

// ---------------- device scratch (static: allocation-free) ----------------
__device__ float g_q[NB * LL * DQK];     // 8.4 MB
__device__ float g_k[NB * LL * DQK];
__device__ float g_v[NB * LL * DQK];
__device__ float g_h[NB * DMLP];
__device__ float g_bias[NB * LLSQ];      // 33.5 MB

// =====================================================================
// WMMA bf16 split-GEMM projection:  Y[M,128] = X[M,512] @ W[512,128] + b
// fp32 = hi(bf16) + lo(bf16); C += Ahi*Bhi + Ahi*Blo + Alo*Bhi (fp32 acc).
// grid = (256, 3): bx = 64-row M tile, by selects {q,k,v}.
// 8 warps as 4(M) x 2(N); warp tile 16x64 = 4 C frags (16x16x16).
// K chunks of 32 (2 wmma k-steps).
// smem (dynamic, union):
//   tiles: Ahi[64][40] Alo[64][40] bf16 (10240 B)
//          Bhi[32][136] Blo[32][136] bf16 (17408 B)   total 27648 B
//   epilogue: Cs[64][132] f32 (33792 B)
// =====================================================================
#define PAD_A 40
#define PAD_B 136
#define PAD_C 132
#define PROJ_SMEM 33792

__device__ __forceinline__ void split2(float x, float y,
                                       __nv_bfloat162& hi, __nv_bfloat162& lo) {
    __nv_bfloat16 hx = __float2bfloat16(x);
    __nv_bfloat16 hy = __float2bfloat16(y);
    hi = __halves2bfloat162(hx, hy);
    lo = __halves2bfloat162(__float2bfloat16(x - __bfloat162float(hx)),
                            __float2bfloat16(y - __bfloat162float(hy)));
}

__global__ __launch_bounds__(256, 2) void proj3_wmma(
        const float* __restrict__ Xq, const float* __restrict__ Xk,
        const float* __restrict__ Xv,
        const float* __restrict__ Wq, const float* __restrict__ Wk,
        const float* __restrict__ Wv,
        const float* __restrict__ bq, const float* __restrict__ bk,
        const float* __restrict__ bv) {
    extern __shared__ char sm[];
    __nv_bfloat16* Ahi = (__nv_bfloat16*)sm;            // [64][40]
    __nv_bfloat16* Alo = Ahi + 64 * PAD_A;
    __nv_bfloat16* Bhi = Alo + 64 * PAD_A;              // [32][136]
    __nv_bfloat16* Blo = Bhi + 32 * PAD_B;
    float* Cs = (float*)sm;                             // [64][132] (union)

    const float* X; const float* W; const float* Bb; float* Y;
    if (blockIdx.y == 0)      { X = Xq; W = Wq; Bb = bq; Y = g_q; }
    else if (blockIdx.y == 1) { X = Xk; W = Wk; Bb = bk; Y = g_k; }
    else                      { X = Xv; W = Wv; Bb = bv; Y = g_v; }

    const int t = threadIdx.x;
    const int warp = t >> 5;
    const int wm = warp & 3;        // 0..3 : M offset wm*16
    const int wn = warp >> 2;       // 0..1 : N offset wn*64
    const int row0 = blockIdx.x * 64;

    wmma::fragment<wmma::accumulator, 16, 16, 16, float> c[4];
#pragma unroll
    for (int nf = 0; nf < 4; nf++) wmma::fill_fragment(c[nf], 0.0f);

    for (int kc = 0; kc < 16; kc++) {
        const int k0 = kc * 32;

        // ---- gmem -> regs (prefetch before barrier)
        float4 xa[2], wbv[4];
#pragma unroll
        for (int j = 0; j < 2; j++) {
            int idx = t + j * 256;             // 0..511
            int r = idx >> 3, c4 = (idx & 7) * 4;
            xa[j] = *(const float4*)&X[(size_t)(row0 + r) * DIN + k0 + c4];
        }
#pragma unroll
        for (int j = 0; j < 4; j++) {
            int idx = t + j * 256;             // 0..1023
            int k = idx >> 5, n4 = (idx & 31) * 4;
            wbv[j] = *(const float4*)&W[(size_t)(k0 + k) * DQK + n4];
        }

        __syncthreads();   // previous chunk's wmma loads done before overwrite

        // ---- split fp32 -> hi/lo bf16, store tiles
#pragma unroll
        for (int j = 0; j < 2; j++) {
            int idx = t + j * 256;
            int r = idx >> 3, c4 = (idx & 7) * 4;
            __nv_bfloat162 h0, l0, h1, l1;
            split2(xa[j].x, xa[j].y, h0, l0);
            split2(xa[j].z, xa[j].w, h1, l1);
            *(__nv_bfloat162*)&Ahi[r * PAD_A + c4]     = h0;
            *(__nv_bfloat162*)&Ahi[r * PAD_A + c4 + 2] = h1;
            *(__nv_bfloat162*)&Alo[r * PAD_A + c4]     = l0;
            *(__nv_bfloat162*)&Alo[r * PAD_A + c4 + 2] = l1;
        }
#pragma unroll
        for (int j = 0; j < 4; j++) {
            int idx = t + j * 256;
            int k = idx >> 5, n4 = (idx & 31) * 4;
            __nv_bfloat162 h0, l0, h1, l1;
            split2(wbv[j].x, wbv[j].y, h0, l0);
            split2(wbv[j].z, wbv[j].w, h1, l1);
            *(__nv_bfloat162*)&Bhi[k * PAD_B + n4]     = h0;
            *(__nv_bfloat162*)&Bhi[k * PAD_B + n4 + 2] = h1;
            *(__nv_bfloat162*)&Blo[k * PAD_B + n4]     = l0;
            *(__nv_bfloat162*)&Blo[k * PAD_B + n4 + 2] = l1;
        }
        __syncthreads();

        // ---- wmma compute: 2 k-steps x 4 n-frags x 3 products
#pragma unroll
        for (int ks = 0; ks < 32; ks += 16) {
            wmma::fragment<wmma::matrix_a, 16, 16, 16, __nv_bfloat16,
                           wmma::row_major> ah, al;
            wmma::load_matrix_sync(ah, Ahi + (wm * 16) * PAD_A + ks, PAD_A);
            wmma::load_matrix_sync(al, Alo + (wm * 16) * PAD_A + ks, PAD_A);
#pragma unroll
            for (int nf = 0; nf < 4; nf++) {
                wmma::fragment<wmma::matrix_b, 16, 16, 16, __nv_bfloat16,
                               wmma::row_major> bh, bl;
                const int nc = wn * 64 + nf * 16;
                wmma::load_matrix_sync(bh, Bhi + ks * PAD_B + nc, PAD_B);
                wmma::load_matrix_sync(bl, Blo + ks * PAD_B + nc, PAD_B);
                wmma::mma_sync(c[nf], ah, bh, c[nf]);
                wmma::mma_sync(c[nf], ah, bl, c[nf]);
                wmma::mma_sync(c[nf], al, bh, c[nf]);
            }
        }
    }

    // ---- epilogue through smem: +bias, coalesced fp32 store
    __syncthreads();   // tiles no longer needed
#pragma unroll
    for (int nf = 0; nf < 4; nf++)
        wmma::store_matrix_sync(Cs + (wm * 16) * PAD_C + wn * 64 + nf * 16,
                                c[nf], PAD_C, wmma::mem_row_major);
    __syncthreads();

#pragma unroll
    for (int j = 0; j < 8; j++) {
        int idx = t + j * 256;                 // 0..2047
        int r = idx >> 5, c4 = (idx & 31) * 4;
        float4 v = *(float4*)&Cs[r * PAD_C + c4];
        float4 bvv = *(const float4*)&Bb[c4];
        v.x += bvv.x; v.y += bvv.y; v.z += bvv.z; v.w += bvv.w;
        *(float4*)&Y[(size_t)(row0 + r) * DQK + c4] = v;
    }
}

// =====================================================================
// Bias MLP stage 1: h = relu(sf @ Wb1 + bb1)   [32,256]@[256,128]
// =====================================================================
__global__ __launch_bounds__(256) void mlp1_kernel(const float* __restrict__ sf,
                                                   const float* __restrict__ Wb1,
                                                   const float* __restrict__ bb1) {
    const int gw   = blockIdx.x * 8 + (threadIdx.x >> 5);   // 0..4095
    const int lane = threadIdx.x & 31;
    const int b    = gw >> 7;          // 0..31
    const int n    = gw & 127;         // 0..127

    float s = 0.f;
#pragma unroll
    for (int kk = 0; kk < 8; kk++) {
        int k = kk * 32 + lane;
        s = fmaf(sf[b * DS + k], Wb1[(size_t)k * DMLP + n], s);
    }
#pragma unroll
    for (int o = 16; o > 0; o >>= 1) s += __shfl_xor_sync(0xffffffffu, s, o);
    if (lane == 0) g_h[b * DMLP + n] = fmaxf(s + bb1[n], 0.f);
}

// =====================================================================
// Bias MLP stage 2: bias = h @ Wb2 + bb2  -> g_bias[32][262144]
// =====================================================================
__global__ __launch_bounds__(256) void bias_kernel(const float* __restrict__ Wb2,
                                                   const float* __restrict__ bb2) {
    __shared__ float hs[NB * DMLP];   // 16 KB
    const int t = threadIdx.x;
    for (int i = t; i < NB * DMLP; i += 256) hs[i] = g_h[i];
    __syncthreads();

    const int n = blockIdx.x * 256 + t;
    const float bb = bb2[n];
    float acc[NB];
#pragma unroll
    for (int b = 0; b < NB; b++) acc[b] = bb;

    for (int k = 0; k < DMLP; k += 4) {
        float w0 = Wb2[(size_t)(k + 0) * LLSQ + n];
        float w1 = Wb2[(size_t)(k + 1) * LLSQ + n];
        float w2 = Wb2[(size_t)(k + 2) * LLSQ + n];
        float w3 = Wb2[(size_t)(k + 3) * LLSQ + n];
#pragma unroll
        for (int b = 0; b < NB; b++) {
            float4 h4 = *(float4*)&hs[b * DMLP + k];
            float a = acc[b];
            a = fmaf(h4.x, w0, a);
            a = fmaf(h4.y, w1, a);
            a = fmaf(h4.z, w2, a);
            a = fmaf(h4.w, w3, a);
            acc[b] = a;
        }
    }
#pragma unroll
    for (int b = 0; b < NB; b++) g_bias[(size_t)b * LLSQ + n] = acc[b];
}

// =====================================================================
// Fused attention (unchanged from R7, 207us): occ-2, 32 q-rows per CTA.
// =====================================================================
#define SM_Q   0
#define SM_S   16384
#define SM_KV  81920
#define KV_PAD 66
#define ATTN_SMEM 115712

__global__ __launch_bounds__(256) void attn_kernel(const unsigned int* __restrict__ mask,
                                                   float* __restrict__ out) {
    extern __shared__ char smem[];
    float (*Qs)[DQK]     = (float (*)[DQK])(smem + SM_Q);
    float (*Ss)[LL]      = (float (*)[LL])(smem + SM_S);
    float (*Kts)[KV_PAD] = (float (*)[KV_PAD])(smem + SM_KV);
    float (*Vs)[DQK]     = (float (*)[DQK])(smem + SM_KV);

    const int t    = threadIdx.x;
    const int lane = t & 31;
    const int warp = t >> 5;
    const int b    = blockIdx.y;
    const int row0 = blockIdx.x * 32;

    const float* __restrict__ qb = g_q + (size_t)b * LL * DQK;
    const float* __restrict__ kb = g_k + (size_t)b * LL * DQK;
    const float* __restrict__ vb = g_v + (size_t)b * LL * DQK;

    for (int i = t; i < 32 * 32; i += 256) {
        int r = i >> 5, c4 = (i & 31) * 4;
        *(float4*)&Qs[r][c4] = *(const float4*)&qb[(size_t)(row0 + r) * DQK + c4];
    }

    const float inv_scale = 0.08838834764831845f;

    for (int ct = 0; ct < 8; ct++) {
        __syncthreads();
        for (int i = t; i < 64 * 32; i += 256) {
            int r = i >> 5, c4 = (i & 31) * 4;
            float4 k4 = *(const float4*)&kb[(size_t)(ct * 64 + r) * DQK + c4];
            Kts[c4 + 0][r] = k4.x; Kts[c4 + 1][r] = k4.y;
            Kts[c4 + 2][r] = k4.z; Kts[c4 + 3][r] = k4.w;
        }
        __syncthreads();

        float acc[4][2];
#pragma unroll
        for (int i = 0; i < 4; i++) { acc[i][0] = 0.f; acc[i][1] = 0.f; }

        for (int d = 0; d < DQK; d += 4) {
            float4 a4[4];
#pragma unroll
            for (int i = 0; i < 4; i++) a4[i] = *(float4*)&Qs[warp * 4 + i][d];
#pragma unroll
            for (int u = 0; u < 4; u++) {
                float2 b2 = *(float2*)&Kts[d + u][lane * 2];
#pragma unroll
                for (int i = 0; i < 4; i++) {
                    float a = (&a4[i].x)[u];
                    acc[i][0] = fmaf(a, b2.x, acc[i][0]);
                    acc[i][1] = fmaf(a, b2.y, acc[i][1]);
                }
            }
        }
        const int cg = ct * 64 + lane * 2;
#pragma unroll
        for (int i = 0; i < 4; i++) {
            const int rg = row0 + warp * 4 + i;
            const unsigned int* mrow = mask + (size_t)(b * LL + rg) * LL + cg;
            float v0 = (mrow[0] != 0u) ? 1e-9f : acc[i][0] * inv_scale;
            float v1 = (mrow[1] != 0u) ? 1e-9f : acc[i][1] * inv_scale;
            *(float2*)&Ss[warp * 4 + i][cg] = make_float2(v0, v1);
        }
    }

#pragma unroll
    for (int j = 0; j < 4; j++) {
        const int r = warp * 4 + j;
        float mx = -1e30f;
        for (int m = lane; m < LL; m += 32) mx = fmaxf(mx, Ss[r][m]);
#pragma unroll
        for (int o = 16; o > 0; o >>= 1) mx = fmaxf(mx, __shfl_xor_sync(0xffffffffu, mx, o));
        float sum = 0.f;
        for (int m = lane; m < LL; m += 32) {
            float e = __expf(Ss[r][m] - mx);
            Ss[r][m] = e;
            sum += e;
        }
#pragma unroll
        for (int o = 16; o > 0; o >>= 1) sum += __shfl_xor_sync(0xffffffffu, sum, o);
        const float inv = 1.0f / sum;
        const float* __restrict__ brow = g_bias + (size_t)(b * LL + row0 + r) * LL;
        for (int m = lane; m < LL; m += 32) Ss[r][m] = Ss[r][m] * inv + brow[m];
    }

    float acc2[4][4];
#pragma unroll
    for (int i = 0; i < 4; i++)
#pragma unroll
        for (int j = 0; j < 4; j++) acc2[i][j] = 0.f;

    for (int mt = 0; mt < 8; mt++) {
        __syncthreads();
        for (int i = t; i < 64 * 32; i += 256) {
            int r = i >> 5, c4 = (i & 31) * 4;
            *(float4*)&Vs[r][c4] = *(const float4*)&vb[(size_t)(mt * 64 + r) * DQK + c4];
        }
        __syncthreads();
        for (int m = 0; m < 64; m += 4) {
            float4 a4[4];
#pragma unroll
            for (int i = 0; i < 4; i++)
                a4[i] = *(float4*)&Ss[warp * 4 + i][mt * 64 + m];
#pragma unroll
            for (int u = 0; u < 4; u++) {
                float4 b4 = *(float4*)&Vs[m + u][lane * 4];
#pragma unroll
                for (int i = 0; i < 4; i++) {
                    float a = (&a4[i].x)[u];
                    acc2[i][0] = fmaf(a, b4.x, acc2[i][0]);
                    acc2[i][1] = fmaf(a, b4.y, acc2[i][1]);
                    acc2[i][2] = fmaf(a, b4.z, acc2[i][2]);
                    acc2[i][3] = fmaf(a, b4.w, acc2[i][3]);
                }
            }
        }
    }

#pragma unroll
    for (int i = 0; i < 4; i++) {
        *(float4*)&out[(size_t)(b * LL + row0 + warp * 4 + i) * DQK + lane * 4] =
            make_float4(acc2[i][0], acc2[i][1], acc2[i][2], acc2[i][3]);
    }
}

// =====================================================================
// Launch
// =====================================================================
extern "C" void kernel_launch(void* const* d_in, const int* in_sizes, int n_in,
                              void* d_out, int out_size) {
    const float* query = (const float*)d_in[0];
    const float* key_  = (const float*)d_in[1];
    const float* value = (const float*)d_in[2];
    const float* sf    = (const float*)d_in[3];
    const unsigned int* mask = (const unsigned int*)d_in[4];
    const float* Wq  = (const float*)d_in[5];
    const float* bq  = (const float*)d_in[6];
    const float* Wk  = (const float*)d_in[7];
    const float* bk  = (const float*)d_in[8];
    const float* Wv  = (const float*)d_in[9];
    const float* bv  = (const float*)d_in[10];
    const float* Wb1 = (const float*)d_in[11];
    const float* bb1 = (const float*)d_in[12];
    const float* Wb2 = (const float*)d_in[13];
    const float* bb2 = (const float*)d_in[14];
    float* out = (float*)d_out;

    (void)in_sizes; (void)n_in; (void)out_size;

    proj3_wmma<<<dim3(NB * LL / 64, 3), 256, PROJ_SMEM>>>(query, key_, value,
                                                          Wq, Wk, Wv, bq, bk, bv);
    mlp1_kernel<<<512, 256>>>(sf, Wb1, bb1);
    bias_kernel<<<LLSQ / 256, 256>>>(Wb2, bb2);

    cudaFuncSetAttribute(attn_kernel,
                         cudaFuncAttributeMaxDynamicSharedMemorySize, ATTN_SMEM);
    attn_kernel<<<dim3(LL / 32, NB), 256, ATTN_SMEM>>>(mask, out);
}

// round 12
// speedup vs baseline: 1.5938x; 1.2530x over previous
#include <cuda_runtime.h>
#include <cuda_bf16.h>
#include <mma.h>
#include <cstdint>

using namespace nvcuda;

#define NB   32      // batch
#define LL   512     // sequence length
#define DIN  512
#define DQK  128
#define DS   256
#define DMLP 128
#define LLSQ (LL*LL) // 262144

// ---------------- device scratch (static: allocation-free) ----------------
__device__ float g_q[NB * LL * DQK];     // 8.4 MB
__device__ float g_k[NB * LL * DQK];
__device__ float g_v[NB * LL * DQK];
__device__ float g_h[NB * DMLP];
__device__ float g_bias[NB * LLSQ];      // 33.5 MB

__device__ __forceinline__ void split2(float x, float y,
                                       __nv_bfloat162& hi, __nv_bfloat162& lo) {
    __nv_bfloat16 hx = __float2bfloat16(x);
    __nv_bfloat16 hy = __float2bfloat16(y);
    hi = __halves2bfloat162(hx, hy);
    lo = __halves2bfloat162(__float2bfloat16(x - __bfloat162float(hx)),
                            __float2bfloat16(y - __bfloat162float(hy)));
}

// =====================================================================
// WMMA bf16 split-GEMM projection:  Y[M,128] = X[M,512] @ W[512,128] + b
// (unchanged from R9: 428us version)
// =====================================================================
#define PAD_A 40
#define PAD_B 136
#define PAD_C 132
#define PROJ_SMEM 33792

__global__ __launch_bounds__(256, 2) void proj3_wmma(
        const float* __restrict__ Xq, const float* __restrict__ Xk,
        const float* __restrict__ Xv,
        const float* __restrict__ Wq, const float* __restrict__ Wk,
        const float* __restrict__ Wv,
        const float* __restrict__ bq, const float* __restrict__ bk,
        const float* __restrict__ bv) {
    extern __shared__ char sm[];
    __nv_bfloat16* Ahi = (__nv_bfloat16*)sm;            // [64][40]
    __nv_bfloat16* Alo = Ahi + 64 * PAD_A;
    __nv_bfloat16* Bhi = Alo + 64 * PAD_A;              // [32][136]
    __nv_bfloat16* Blo = Bhi + 32 * PAD_B;
    float* Cs = (float*)sm;                             // [64][132] (union)

    const float* X; const float* W; const float* Bb; float* Y;
    if (blockIdx.y == 0)      { X = Xq; W = Wq; Bb = bq; Y = g_q; }
    else if (blockIdx.y == 1) { X = Xk; W = Wk; Bb = bk; Y = g_k; }
    else                      { X = Xv; W = Wv; Bb = bv; Y = g_v; }

    const int t = threadIdx.x;
    const int warp = t >> 5;
    const int wm = warp & 3;
    const int wn = warp >> 2;
    const int row0 = blockIdx.x * 64;

    wmma::fragment<wmma::accumulator, 16, 16, 16, float> c[4];
#pragma unroll
    for (int nf = 0; nf < 4; nf++) wmma::fill_fragment(c[nf], 0.0f);

    for (int kc = 0; kc < 16; kc++) {
        const int k0 = kc * 32;

        float4 xa[2], wbv[4];
#pragma unroll
        for (int j = 0; j < 2; j++) {
            int idx = t + j * 256;
            int r = idx >> 3, c4 = (idx & 7) * 4;
            xa[j] = *(const float4*)&X[(size_t)(row0 + r) * DIN + k0 + c4];
        }
#pragma unroll
        for (int j = 0; j < 4; j++) {
            int idx = t + j * 256;
            int k = idx >> 5, n4 = (idx & 31) * 4;
            wbv[j] = *(const float4*)&W[(size_t)(k0 + k) * DQK + n4];
        }

        __syncthreads();

#pragma unroll
        for (int j = 0; j < 2; j++) {
            int idx = t + j * 256;
            int r = idx >> 3, c4 = (idx & 7) * 4;
            __nv_bfloat162 h0, l0, h1, l1;
            split2(xa[j].x, xa[j].y, h0, l0);
            split2(xa[j].z, xa[j].w, h1, l1);
            *(__nv_bfloat162*)&Ahi[r * PAD_A + c4]     = h0;
            *(__nv_bfloat162*)&Ahi[r * PAD_A + c4 + 2] = h1;
            *(__nv_bfloat162*)&Alo[r * PAD_A + c4]     = l0;
            *(__nv_bfloat162*)&Alo[r * PAD_A + c4 + 2] = l1;
        }
#pragma unroll
        for (int j = 0; j < 4; j++) {
            int idx = t + j * 256;
            int k = idx >> 5, n4 = (idx & 31) * 4;
            __nv_bfloat162 h0, l0, h1, l1;
            split2(wbv[j].x, wbv[j].y, h0, l0);
            split2(wbv[j].z, wbv[j].w, h1, l1);
            *(__nv_bfloat162*)&Bhi[k * PAD_B + n4]     = h0;
            *(__nv_bfloat162*)&Bhi[k * PAD_B + n4 + 2] = h1;
            *(__nv_bfloat162*)&Blo[k * PAD_B + n4]     = l0;
            *(__nv_bfloat162*)&Blo[k * PAD_B + n4 + 2] = l1;
        }
        __syncthreads();

#pragma unroll
        for (int ks = 0; ks < 32; ks += 16) {
            wmma::fragment<wmma::matrix_a, 16, 16, 16, __nv_bfloat16,
                           wmma::row_major> ah, al;
            wmma::load_matrix_sync(ah, Ahi + (wm * 16) * PAD_A + ks, PAD_A);
            wmma::load_matrix_sync(al, Alo + (wm * 16) * PAD_A + ks, PAD_A);
#pragma unroll
            for (int nf = 0; nf < 4; nf++) {
                wmma::fragment<wmma::matrix_b, 16, 16, 16, __nv_bfloat16,
                               wmma::row_major> bh, bl;
                const int nc = wn * 64 + nf * 16;
                wmma::load_matrix_sync(bh, Bhi + ks * PAD_B + nc, PAD_B);
                wmma::load_matrix_sync(bl, Blo + ks * PAD_B + nc, PAD_B);
                wmma::mma_sync(c[nf], ah, bh, c[nf]);
                wmma::mma_sync(c[nf], ah, bl, c[nf]);
                wmma::mma_sync(c[nf], al, bh, c[nf]);
            }
        }
    }

    __syncthreads();
#pragma unroll
    for (int nf = 0; nf < 4; nf++)
        wmma::store_matrix_sync(Cs + (wm * 16) * PAD_C + wn * 64 + nf * 16,
                                c[nf], PAD_C, wmma::mem_row_major);
    __syncthreads();

#pragma unroll
    for (int j = 0; j < 8; j++) {
        int idx = t + j * 256;
        int r = idx >> 5, c4 = (idx & 31) * 4;
        float4 v = *(float4*)&Cs[r * PAD_C + c4];
        float4 bvv = *(const float4*)&Bb[c4];
        v.x += bvv.x; v.y += bvv.y; v.z += bvv.z; v.w += bvv.w;
        *(float4*)&Y[(size_t)(row0 + r) * DQK + c4] = v;
    }
}

// =====================================================================
// Bias MLP stage 1 (unchanged)
// =====================================================================
__global__ __launch_bounds__(256) void mlp1_kernel(const float* __restrict__ sf,
                                                   const float* __restrict__ Wb1,
                                                   const float* __restrict__ bb1) {
    const int gw   = blockIdx.x * 8 + (threadIdx.x >> 5);
    const int lane = threadIdx.x & 31;
    const int b    = gw >> 7;
    const int n    = gw & 127;

    float s = 0.f;
#pragma unroll
    for (int kk = 0; kk < 8; kk++) {
        int k = kk * 32 + lane;
        s = fmaf(sf[b * DS + k], Wb1[(size_t)k * DMLP + n], s);
    }
#pragma unroll
    for (int o = 16; o > 0; o >>= 1) s += __shfl_xor_sync(0xffffffffu, s, o);
    if (lane == 0) g_h[b * DMLP + n] = fmaxf(s + bb1[n], 0.f);
}

// =====================================================================
// Bias MLP stage 2 (unchanged)
// =====================================================================
__global__ __launch_bounds__(256) void bias_kernel(const float* __restrict__ Wb2,
                                                   const float* __restrict__ bb2) {
    __shared__ float hs[NB * DMLP];
    const int t = threadIdx.x;
    for (int i = t; i < NB * DMLP; i += 256) hs[i] = g_h[i];
    __syncthreads();

    const int n = blockIdx.x * 256 + t;
    const float bb = bb2[n];
    float acc[NB];
#pragma unroll
    for (int b = 0; b < NB; b++) acc[b] = bb;

    for (int k = 0; k < DMLP; k += 4) {
        float w0 = Wb2[(size_t)(k + 0) * LLSQ + n];
        float w1 = Wb2[(size_t)(k + 1) * LLSQ + n];
        float w2 = Wb2[(size_t)(k + 2) * LLSQ + n];
        float w3 = Wb2[(size_t)(k + 3) * LLSQ + n];
#pragma unroll
        for (int b = 0; b < NB; b++) {
            float4 h4 = *(float4*)&hs[b * DMLP + k];
            float a = acc[b];
            a = fmaf(h4.x, w0, a);
            a = fmaf(h4.y, w1, a);
            a = fmaf(h4.z, w2, a);
            a = fmaf(h4.w, w3, a);
            acc[b] = a;
        }
    }
#pragma unroll
    for (int b = 0; b < NB; b++) g_bias[(size_t)b * LLSQ + n] = acc[b];
}

// =====================================================================
// WMMA fused attention. Per CTA: 32 q-rows of one batch.
//   Stage 1: S = Q Kt (plain bf16 wmma; raw dots to Ss f32).
//   Fused pass: scale + mask(1e-9) + softmax + (+bias) in fp32.
//   Stage 2: out = A @ V with hi/lo bf16 split on BOTH operands.
// smem layout (bytes):
//   Ss   f32 [32][512]           @0       65536
//   Qsm  bf16 [32][136]          @65536    8704
//   Ksm  bf16 [64][136] (stage1) @74240   17408
//     / Vhi bf16 [32][136] @74240, Vlo @82944 (stage2 union)
//   Abhi bf16 [32][72]           @91648    4608
//   Ablo bf16 [32][72]           @96256    4608
// total 100864 -> 2 CTAs/SM.
// =====================================================================
#define AT_SS   0
#define AT_Q    65536
#define AT_KV   74240
#define AT_VLO  82944
#define AT_ABH  91648
#define AT_ABL  96256
#define ATTN_SMEM 100864
#define QPAD 136
#define APAD 72

__global__ __launch_bounds__(256) void attn_wmma(const unsigned int* __restrict__ mask,
                                                 float* __restrict__ out) {
    extern __shared__ char sm[];
    float*         Ss   = (float*)(sm + AT_SS);           // [32][512]
    __nv_bfloat16* Qsm  = (__nv_bfloat16*)(sm + AT_Q);    // [32][136]
    __nv_bfloat16* Ksm  = (__nv_bfloat16*)(sm + AT_KV);   // [64][136]
    __nv_bfloat16* Vhi  = (__nv_bfloat16*)(sm + AT_KV);   // [32][136]
    __nv_bfloat16* Vlo  = (__nv_bfloat16*)(sm + AT_VLO);  // [32][136]
    __nv_bfloat16* Abhi = (__nv_bfloat16*)(sm + AT_ABH);  // [32][72]
    __nv_bfloat16* Ablo = (__nv_bfloat16*)(sm + AT_ABL);  // [32][72]

    const int t    = threadIdx.x;
    const int lane = t & 31;
    const int warp = t >> 5;
    const int b    = blockIdx.y;
    const int row0 = blockIdx.x * 32;

    const float* __restrict__ qb = g_q + (size_t)b * LL * DQK;
    const float* __restrict__ kb = g_k + (size_t)b * LL * DQK;
    const float* __restrict__ vb = g_v + (size_t)b * LL * DQK;

    // ---- Q [32][128] f32 -> bf16 smem
#pragma unroll
    for (int j = 0; j < 4; j++) {
        int idx = t + j * 256;                    // 0..1023
        int r = idx >> 5, c4 = (idx & 31) * 4;
        float4 q4 = *(const float4*)&qb[(size_t)(row0 + r) * DQK + c4];
        *(__nv_bfloat162*)&Qsm[r * QPAD + c4] =
            __halves2bfloat162(__float2bfloat16(q4.x), __float2bfloat16(q4.y));
        *(__nv_bfloat162*)&Qsm[r * QPAD + c4 + 2] =
            __halves2bfloat162(__float2bfloat16(q4.z), __float2bfloat16(q4.w));
    }
    __syncthreads();

    // ---- hoist Q a-fragments (reused across all 8 key tiles)
    const int wm = warp & 1;      // row group 16
    const int wn = warp >> 1;     // col group 16 within 64-key tile
    wmma::fragment<wmma::matrix_a, 16, 16, 16, __nv_bfloat16,
                   wmma::row_major> qa[8];
#pragma unroll
    for (int ks = 0; ks < 8; ks++)
        wmma::load_matrix_sync(qa[ks], Qsm + (wm * 16) * QPAD + ks * 16, QPAD);

    // ---- stage 1: S tiles of 64 keys
    for (int ct = 0; ct < 8; ct++) {
        __syncthreads();   // prior tile's mma reads done before Ksm overwrite
#pragma unroll
        for (int j = 0; j < 8; j++) {
            int idx = t + j * 256;                // 0..2047
            int r = idx >> 5, c4 = (idx & 31) * 4;
            float4 k4 = *(const float4*)&kb[(size_t)(ct * 64 + r) * DQK + c4];
            *(__nv_bfloat162*)&Ksm[r * QPAD + c4] =
                __halves2bfloat162(__float2bfloat16(k4.x), __float2bfloat16(k4.y));
            *(__nv_bfloat162*)&Ksm[r * QPAD + c4 + 2] =
                __halves2bfloat162(__float2bfloat16(k4.z), __float2bfloat16(k4.w));
        }
        __syncthreads();

        wmma::fragment<wmma::accumulator, 16, 16, 16, float> c1;
        wmma::fill_fragment(c1, 0.0f);
#pragma unroll
        for (int ks = 0; ks < 8; ks++) {
            wmma::fragment<wmma::matrix_b, 16, 16, 16, __nv_bfloat16,
                           wmma::col_major> kf;
            wmma::load_matrix_sync(kf, Ksm + (wn * 16) * QPAD + ks * 16, QPAD);
            wmma::mma_sync(c1, qa[ks], kf, c1);
        }
        wmma::store_matrix_sync(Ss + (wm * 16) * LL + ct * 64 + wn * 16,
                                c1, LL, wmma::mem_row_major);
    }
    __syncthreads();

    // ---- fused scale + mask + softmax + bias  (warp owns 4 rows)
    const float inv_scale = 0.08838834764831845f;   // 1/sqrt(128)
#pragma unroll
    for (int j = 0; j < 4; j++) {
        const int r = warp * 4 + j;
        const unsigned int* mrow = mask + (size_t)(b * LL + row0 + r) * LL;
        float mx = -1e30f;
        for (int m = lane; m < LL; m += 32) {
            float s = (mrow[m] != 0u) ? 1e-9f : Ss[r * LL + m] * inv_scale;
            Ss[r * LL + m] = s;
            mx = fmaxf(mx, s);
        }
#pragma unroll
        for (int o = 16; o > 0; o >>= 1) mx = fmaxf(mx, __shfl_xor_sync(0xffffffffu, mx, o));
        float sum = 0.f;
        for (int m = lane; m < LL; m += 32) {
            float e = __expf(Ss[r * LL + m] - mx);
            Ss[r * LL + m] = e;
            sum += e;
        }
#pragma unroll
        for (int o = 16; o > 0; o >>= 1) sum += __shfl_xor_sync(0xffffffffu, sum, o);
        const float inv = 1.0f / sum;
        const float* __restrict__ brow = g_bias + (size_t)(b * LL + row0 + r) * LL;
        for (int m = lane; m < LL; m += 32)
            Ss[r * LL + m] = Ss[r * LL + m] * inv + brow[m];
    }

    // ---- stage 2: out = A @ V, V tiles of 32 keys, split both operands
    const int wn2 = warp >> 1;    // col group 32 (4 groups)
    wmma::fragment<wmma::accumulator, 16, 16, 16, float> o2[2];
    wmma::fill_fragment(o2[0], 0.0f);
    wmma::fill_fragment(o2[1], 0.0f);

    for (int mt = 0; mt < 16; mt++) {
        __syncthreads();   // prior tile's mma reads done before overwrite
        // A block [32][32] f32 -> hi/lo bf16
#pragma unroll
        for (int j = 0; j < 2; j++) {
            int idx = t + j * 256;                // 0..511
            int r = idx >> 4, c2 = (idx & 15) * 2;
            float2 s2 = *(float2*)&Ss[r * LL + mt * 32 + c2];
            __nv_bfloat162 hi, lo;
            split2(s2.x, s2.y, hi, lo);
            *(__nv_bfloat162*)&Abhi[r * APAD + c2] = hi;
            *(__nv_bfloat162*)&Ablo[r * APAD + c2] = lo;
        }
        // V tile [32][128] f32 -> hi/lo bf16
#pragma unroll
        for (int j = 0; j < 4; j++) {
            int idx = t + j * 256;                // 0..1023
            int r = idx >> 5, c4 = (idx & 31) * 4;
            float4 v4 = *(const float4*)&vb[(size_t)(mt * 32 + r) * DQK + c4];
            __nv_bfloat162 h0, l0, h1, l1;
            split2(v4.x, v4.y, h0, l0);
            split2(v4.z, v4.w, h1, l1);
            *(__nv_bfloat162*)&Vhi[r * QPAD + c4]     = h0;
            *(__nv_bfloat162*)&Vhi[r * QPAD + c4 + 2] = h1;
            *(__nv_bfloat162*)&Vlo[r * QPAD + c4]     = l0;
            *(__nv_bfloat162*)&Vlo[r * QPAD + c4 + 2] = l1;
        }
        __syncthreads();

#pragma unroll
        for (int ks = 0; ks < 2; ks++) {
            wmma::fragment<wmma::matrix_a, 16, 16, 16, __nv_bfloat16,
                           wmma::row_major> ah, al;
            wmma::load_matrix_sync(ah, Abhi + (wm * 16) * APAD + ks * 16, APAD);
            wmma::load_matrix_sync(al, Ablo + (wm * 16) * APAD + ks * 16, APAD);
#pragma unroll
            for (int nf = 0; nf < 2; nf++) {
                wmma::fragment<wmma::matrix_b, 16, 16, 16, __nv_bfloat16,
                               wmma::row_major> vh, vl;
                const int nc = wn2 * 32 + nf * 16;
                wmma::load_matrix_sync(vh, Vhi + (ks * 16) * QPAD + nc, QPAD);
                wmma::load_matrix_sync(vl, Vlo + (ks * 16) * QPAD + nc, QPAD);
                wmma::mma_sync(o2[nf], ah, vh, o2[nf]);
                wmma::mma_sync(o2[nf], ah, vl, o2[nf]);
                wmma::mma_sync(o2[nf], al, vh, o2[nf]);
            }
        }
    }

    // ---- store result fragments directly to gmem
#pragma unroll
    for (int nf = 0; nf < 2; nf++)
        wmma::store_matrix_sync(
            &out[(size_t)(b * LL + row0 + wm * 16) * DQK + wn2 * 32 + nf * 16],
            o2[nf], DQK, wmma::mem_row_major);
}

// =====================================================================
// Launch
// =====================================================================
extern "C" void kernel_launch(void* const* d_in, const int* in_sizes, int n_in,
                              void* d_out, int out_size) {
    const float* query = (const float*)d_in[0];
    const float* key_  = (const float*)d_in[1];
    const float* value = (const float*)d_in[2];
    const float* sf    = (const float*)d_in[3];
    const unsigned int* mask = (const unsigned int*)d_in[4];
    const float* Wq  = (const float*)d_in[5];
    const float* bq  = (const float*)d_in[6];
    const float* Wk  = (const float*)d_in[7];
    const float* bk  = (const float*)d_in[8];
    const float* Wv  = (const float*)d_in[9];
    const float* bv  = (const float*)d_in[10];
    const float* Wb1 = (const float*)d_in[11];
    const float* bb1 = (const float*)d_in[12];
    const float* Wb2 = (const float*)d_in[13];
    const float* bb2 = (const float*)d_in[14];
    float* out = (float*)d_out;

    (void)in_sizes; (void)n_in; (void)out_size;

    proj3_wmma<<<dim3(NB * LL / 64, 3), 256, PROJ_SMEM>>>(query, key_, value,
                                                          Wq, Wk, Wv, bq, bk, bv);
    mlp1_kernel<<<512, 256>>>(sf, Wb1, bb1);
    bias_kernel<<<LLSQ / 256, 256>>>(Wb2, bb2);

    cudaFuncSetAttribute(attn_wmma,
                         cudaFuncAttributeMaxDynamicSharedMemorySize, ATTN_SMEM);
    attn_wmma<<<dim3(LL / 32, NB), 256, ATTN_SMEM>>>(mask, out);
}

// round 13
// speedup vs baseline: 1.9847x; 1.2453x over previous
#include <cuda_runtime.h>
#include <cuda_bf16.h>
#include <mma.h>
#include <cstdint>

using namespace nvcuda;

#define NB   32      // batch
#define LL   512     // sequence length
#define DIN  512
#define DQK  128
#define DS   256
#define DMLP 128
#define LLSQ (LL*LL) // 262144

// ---------------- device scratch (static: allocation-free) ----------------
__device__ __nv_bfloat16 g_qb [NB * LL * DQK];   // bf16 q
__device__ __nv_bfloat16 g_kb [NB * LL * DQK];   // bf16 k
__device__ __nv_bfloat16 g_vhi[NB * LL * DQK];   // v hi
__device__ __nv_bfloat16 g_vlo[NB * LL * DQK];   // v lo
__device__ __nv_bfloat16 g_whi[3 * DIN * DQK];   // Wq|Wk|Wv hi
__device__ __nv_bfloat16 g_wlo[3 * DIN * DQK];   // Wq|Wk|Wv lo
__device__ __nv_bfloat16 g_hhi[NB * DMLP];
__device__ __nv_bfloat16 g_hlo[NB * DMLP];
__device__ float g_bias[NB * LLSQ];              // 33.5 MB

__device__ __forceinline__ void split2(float x, float y,
                                       __nv_bfloat162& hi, __nv_bfloat162& lo) {
    __nv_bfloat16 hx = __float2bfloat16(x);
    __nv_bfloat16 hy = __float2bfloat16(y);
    hi = __halves2bfloat162(hx, hy);
    lo = __halves2bfloat162(__float2bfloat16(x - __bfloat162float(hx)),
                            __float2bfloat16(y - __bfloat162float(hy)));
}

// =====================================================================
// prep_w: split Wq/Wk/Wv fp32 -> bf16 hi/lo once. grid (256,3) x 256.
// =====================================================================
__global__ __launch_bounds__(256) void prep_w(const float* __restrict__ Wq,
                                              const float* __restrict__ Wk,
                                              const float* __restrict__ Wv) {
    const float* src = (blockIdx.y == 0) ? Wq : (blockIdx.y == 1) ? Wk : Wv;
    int i = blockIdx.x * 256 + threadIdx.x;          // 0..65535
    float v = src[i];
    __nv_bfloat16 h = __float2bfloat16(v);
    g_whi[blockIdx.y * (DIN * DQK) + i] = h;
    g_wlo[blockIdx.y * (DIN * DQK) + i] = __float2bfloat16(v - __bfloat162float(h));
}

// =====================================================================
// WMMA bf16 split-GEMM projection: Y = X @ W + b  (x3)
// W comes pre-split (bf16 hi/lo). Epilogue writes bf16 outputs:
//   by==0 -> g_qb, by==1 -> g_kb, by==2 -> g_vhi/g_vlo (split).
// =====================================================================
#define PAD_A 40
#define PAD_B 136
#define PAD_C 132
#define PROJ_SMEM 33792

__global__ __launch_bounds__(256, 2) void proj3_wmma(
        const float* __restrict__ Xq, const float* __restrict__ Xk,
        const float* __restrict__ Xv,
        const float* __restrict__ bq, const float* __restrict__ bk,
        const float* __restrict__ bv) {
    extern __shared__ char sm[];
    __nv_bfloat16* Ahi = (__nv_bfloat16*)sm;            // [64][40]
    __nv_bfloat16* Alo = Ahi + 64 * PAD_A;
    __nv_bfloat16* Bhi = Alo + 64 * PAD_A;              // [32][136]
    __nv_bfloat16* Blo = Bhi + 32 * PAD_B;
    float* Cs = (float*)sm;                             // [64][132] (union)

    const int by = blockIdx.y;
    const float* X  = (by == 0) ? Xq : (by == 1) ? Xk : Xv;
    const float* Bb = (by == 0) ? bq : (by == 1) ? bk : bv;
    const __nv_bfloat16* whi = g_whi + by * (DIN * DQK);
    const __nv_bfloat16* wlo = g_wlo + by * (DIN * DQK);

    const int t = threadIdx.x;
    const int warp = t >> 5;
    const int wm = warp & 3;
    const int wn = warp >> 2;
    const int row0 = blockIdx.x * 64;

    wmma::fragment<wmma::accumulator, 16, 16, 16, float> c[4];
#pragma unroll
    for (int nf = 0; nf < 4; nf++) wmma::fill_fragment(c[nf], 0.0f);

    for (int kc = 0; kc < 16; kc++) {
        const int k0 = kc * 32;

        float4 xa[2];
        uint4 wh[2], wl[2];
#pragma unroll
        for (int j = 0; j < 2; j++) {
            int idx = t + j * 256;
            int r = idx >> 3, c4 = (idx & 7) * 4;
            xa[j] = *(const float4*)&X[(size_t)(row0 + r) * DIN + k0 + c4];
        }
#pragma unroll
        for (int j = 0; j < 2; j++) {
            int idx = t + j * 256;               // 0..511 (32 rows x 16 uint4)
            int k = idx >> 4, c8 = (idx & 15) * 8;
            wh[j] = *(const uint4*)&whi[(size_t)(k0 + k) * DQK + c8];
            wl[j] = *(const uint4*)&wlo[(size_t)(k0 + k) * DQK + c8];
        }

        __syncthreads();

#pragma unroll
        for (int j = 0; j < 2; j++) {
            int idx = t + j * 256;
            int r = idx >> 3, c4 = (idx & 7) * 4;
            __nv_bfloat162 h0, l0, h1, l1;
            split2(xa[j].x, xa[j].y, h0, l0);
            split2(xa[j].z, xa[j].w, h1, l1);
            *(__nv_bfloat162*)&Ahi[r * PAD_A + c4]     = h0;
            *(__nv_bfloat162*)&Ahi[r * PAD_A + c4 + 2] = h1;
            *(__nv_bfloat162*)&Alo[r * PAD_A + c4]     = l0;
            *(__nv_bfloat162*)&Alo[r * PAD_A + c4 + 2] = l1;
        }
#pragma unroll
        for (int j = 0; j < 2; j++) {
            int idx = t + j * 256;
            int k = idx >> 4, c8 = (idx & 15) * 8;
            *(uint4*)&Bhi[k * PAD_B + c8] = wh[j];
            *(uint4*)&Blo[k * PAD_B + c8] = wl[j];
        }
        __syncthreads();

#pragma unroll
        for (int ks = 0; ks < 32; ks += 16) {
            wmma::fragment<wmma::matrix_a, 16, 16, 16, __nv_bfloat16,
                           wmma::row_major> ah, al;
            wmma::load_matrix_sync(ah, Ahi + (wm * 16) * PAD_A + ks, PAD_A);
            wmma::load_matrix_sync(al, Alo + (wm * 16) * PAD_A + ks, PAD_A);
#pragma unroll
            for (int nf = 0; nf < 4; nf++) {
                wmma::fragment<wmma::matrix_b, 16, 16, 16, __nv_bfloat16,
                               wmma::row_major> bh, bl;
                const int nc = wn * 64 + nf * 16;
                wmma::load_matrix_sync(bh, Bhi + ks * PAD_B + nc, PAD_B);
                wmma::load_matrix_sync(bl, Blo + ks * PAD_B + nc, PAD_B);
                wmma::mma_sync(c[nf], ah, bh, c[nf]);
                wmma::mma_sync(c[nf], ah, bl, c[nf]);
                wmma::mma_sync(c[nf], al, bh, c[nf]);
            }
        }
    }

    __syncthreads();
#pragma unroll
    for (int nf = 0; nf < 4; nf++)
        wmma::store_matrix_sync(Cs + (wm * 16) * PAD_C + wn * 64 + nf * 16,
                                c[nf], PAD_C, wmma::mem_row_major);
    __syncthreads();

    // epilogue: +bias, convert to bf16 outputs
#pragma unroll
    for (int j = 0; j < 8; j++) {
        int idx = t + j * 256;
        int r = idx >> 5, c4 = (idx & 31) * 4;
        float4 v = *(float4*)&Cs[r * PAD_C + c4];
        float4 bvv = *(const float4*)&Bb[c4];
        v.x += bvv.x; v.y += bvv.y; v.z += bvv.z; v.w += bvv.w;
        size_t o = (size_t)(row0 + r) * DQK + c4;
        if (by == 2) {
            __nv_bfloat162 h0, l0, h1, l1;
            split2(v.x, v.y, h0, l0);
            split2(v.z, v.w, h1, l1);
            *(__nv_bfloat162*)&g_vhi[o]     = h0;
            *(__nv_bfloat162*)&g_vhi[o + 2] = h1;
            *(__nv_bfloat162*)&g_vlo[o]     = l0;
            *(__nv_bfloat162*)&g_vlo[o + 2] = l1;
        } else {
            __nv_bfloat16* Yb = (by == 0) ? g_qb : g_kb;
            *(__nv_bfloat162*)&Yb[o] =
                __halves2bfloat162(__float2bfloat16(v.x), __float2bfloat16(v.y));
            *(__nv_bfloat162*)&Yb[o + 2] =
                __halves2bfloat162(__float2bfloat16(v.z), __float2bfloat16(v.w));
        }
    }
}

// =====================================================================
// Bias MLP stage 1: h = relu(sf @ Wb1 + bb1) -> bf16 hi/lo
// =====================================================================
__global__ __launch_bounds__(256) void mlp1_kernel(const float* __restrict__ sf,
                                                   const float* __restrict__ Wb1,
                                                   const float* __restrict__ bb1) {
    const int gw   = blockIdx.x * 8 + (threadIdx.x >> 5);
    const int lane = threadIdx.x & 31;
    const int b    = gw >> 7;
    const int n    = gw & 127;

    float s = 0.f;
#pragma unroll
    for (int kk = 0; kk < 8; kk++) {
        int k = kk * 32 + lane;
        s = fmaf(sf[b * DS + k], Wb1[(size_t)k * DMLP + n], s);
    }
#pragma unroll
    for (int o = 16; o > 0; o >>= 1) s += __shfl_xor_sync(0xffffffffu, s, o);
    if (lane == 0) {
        float val = fmaxf(s + bb1[n], 0.f);
        __nv_bfloat16 h = __float2bfloat16(val);
        g_hhi[b * DMLP + n] = h;
        g_hlo[b * DMLP + n] = __float2bfloat16(val - __bfloat162float(h));
    }
}

// =====================================================================
// Bias MLP stage 2 via WMMA split: bias = h @ Wb2 + bb2
// grid 2048 CTAs, N tile = 128 cols. M=32(batch), K=128.
// smem: Whi[128][136] @0 (34816) | Wlo @34816 | Ahh[32][136] @69632 (8704)
//       | Ahl @78336 (8704) | Cs f32 [32][136] union @69632 (17408)
// total 87040.
// =====================================================================
#define BW_WHI 0
#define BW_WLO 34816
#define BW_AHH 69632
#define BW_AHL 78336
#define BW_SMEM 87040
#define HPAD 136

__global__ __launch_bounds__(256, 2) void bias_wmma(const float* __restrict__ Wb2,
                                                    const float* __restrict__ bb2) {
    extern __shared__ char sm[];
    __nv_bfloat16* Whi = (__nv_bfloat16*)(sm + BW_WHI);
    __nv_bfloat16* Wlo = (__nv_bfloat16*)(sm + BW_WLO);
    __nv_bfloat16* Ahh = (__nv_bfloat16*)(sm + BW_AHH);
    __nv_bfloat16* Ahl = (__nv_bfloat16*)(sm + BW_AHL);
    float*         Cs  = (float*)(sm + BW_AHH);          // union, after MMA

    const int t = threadIdx.x;
    const int warp = t >> 5;
    const int wm = warp & 1;        // M group 16
    const int wn = warp >> 1;       // N group 32
    const int n0 = blockIdx.x * 128;

    // h [32][128] bf16 hi/lo -> smem
#pragma unroll
    for (int j = 0; j < 2; j++) {
        int idx = t + j * 256;                 // 0..511
        int r = idx >> 4, c8 = (idx & 15) * 8;
        *(uint4*)&Ahh[r * HPAD + c8] = *(const uint4*)&g_hhi[r * DMLP + c8];
        *(uint4*)&Ahl[r * HPAD + c8] = *(const uint4*)&g_hlo[r * DMLP + c8];
    }
    // Wb2 tile [128][128] f32 -> split hi/lo smem
#pragma unroll
    for (int j = 0; j < 16; j++) {
        int idx = t + j * 256;                 // 0..4095 float4
        int k = idx >> 5, n4 = (idx & 31) * 4;
        float4 w = *(const float4*)&Wb2[(size_t)k * LLSQ + n0 + n4];
        __nv_bfloat162 h0, l0, h1, l1;
        split2(w.x, w.y, h0, l0);
        split2(w.z, w.w, h1, l1);
        *(__nv_bfloat162*)&Whi[k * HPAD + n4]     = h0;
        *(__nv_bfloat162*)&Whi[k * HPAD + n4 + 2] = h1;
        *(__nv_bfloat162*)&Wlo[k * HPAD + n4]     = l0;
        *(__nv_bfloat162*)&Wlo[k * HPAD + n4 + 2] = l1;
    }
    __syncthreads();

    wmma::fragment<wmma::accumulator, 16, 16, 16, float> c2[2];
    wmma::fill_fragment(c2[0], 0.0f);
    wmma::fill_fragment(c2[1], 0.0f);

#pragma unroll
    for (int ks = 0; ks < 8; ks++) {
        wmma::fragment<wmma::matrix_a, 16, 16, 16, __nv_bfloat16,
                       wmma::row_major> ah, al;
        wmma::load_matrix_sync(ah, Ahh + (wm * 16) * HPAD + ks * 16, HPAD);
        wmma::load_matrix_sync(al, Ahl + (wm * 16) * HPAD + ks * 16, HPAD);
#pragma unroll
        for (int nf = 0; nf < 2; nf++) {
            wmma::fragment<wmma::matrix_b, 16, 16, 16, __nv_bfloat16,
                           wmma::row_major> bh, bl;
            const int nc = wn * 32 + nf * 16;
            wmma::load_matrix_sync(bh, Whi + (ks * 16) * HPAD + nc, HPAD);
            wmma::load_matrix_sync(bl, Wlo + (ks * 16) * HPAD + nc, HPAD);
            wmma::mma_sync(c2[nf], ah, bh, c2[nf]);
            wmma::mma_sync(c2[nf], ah, bl, c2[nf]);
            wmma::mma_sync(c2[nf], al, bh, c2[nf]);
        }
    }

    __syncthreads();   // h tiles no longer needed before Cs overwrite
#pragma unroll
    for (int nf = 0; nf < 2; nf++)
        wmma::store_matrix_sync(Cs + (wm * 16) * HPAD + wn * 32 + nf * 16,
                                c2[nf], HPAD, wmma::mem_row_major);
    __syncthreads();

#pragma unroll
    for (int j = 0; j < 4; j++) {
        int idx = t + j * 256;                 // 0..1023 float4
        int r = idx >> 5, c4 = (idx & 31) * 4;
        float4 v = *(float4*)&Cs[r * HPAD + c4];
        float4 b2 = *(const float4*)&bb2[n0 + c4];
        v.x += b2.x; v.y += b2.y; v.z += b2.z; v.w += b2.w;
        *(float4*)&g_bias[(size_t)r * LLSQ + n0 + c4] = v;
    }
}

// =====================================================================
// WMMA fused attention, all-bf16 operand feeds (pure smem copies).
//   Stage 1: S = Q Kt (bf16), 8 tiles of 64 keys.
//   Fused scale+mask+softmax+bias in fp32 (Ss padded 520).
//   Stage 2: out = A @ V hi/lo split, 8 tiles of 64 keys.
// smem: Ss f32 [32][520] @0 (66560)
//       KV union @66560: Qsm[32][136] / Ksm[64][136] / Vhi[64][136]
//                        + Vlo[64][136] @83968              (34816)
//       Abhi[32][72] @101376 (4608) | Ablo @105984 (4608)
// total 110592 -> 2 CTAs/SM.
// =====================================================================
#define SSPAD 520
#define AT_KV   66560
#define AT_VLO  83968
#define AT_ABH  101376
#define AT_ABL  105984
#define ATTN_SMEM 110592
#define QPAD 136
#define APAD 72

__global__ __launch_bounds__(256) void attn_wmma(const unsigned int* __restrict__ mask,
                                                 float* __restrict__ out) {
    extern __shared__ char sm[];
    float*         Ss   = (float*)sm;                     // [32][520]
    __nv_bfloat16* Qsm  = (__nv_bfloat16*)(sm + AT_KV);   // [32][136]
    __nv_bfloat16* Ksm  = (__nv_bfloat16*)(sm + AT_KV);   // [64][136]
    __nv_bfloat16* Vhi  = (__nv_bfloat16*)(sm + AT_KV);   // [64][136]
    __nv_bfloat16* Vlo  = (__nv_bfloat16*)(sm + AT_VLO);  // [64][136]
    __nv_bfloat16* Abhi = (__nv_bfloat16*)(sm + AT_ABH);  // [32][72]
    __nv_bfloat16* Ablo = (__nv_bfloat16*)(sm + AT_ABL);  // [32][72]

    const int t    = threadIdx.x;
    const int lane = t & 31;
    const int warp = t >> 5;
    const int b    = blockIdx.y;
    const int row0 = blockIdx.x * 32;

    const __nv_bfloat16* __restrict__ qb = g_qb + (size_t)(b * LL + row0) * DQK;
    const __nv_bfloat16* __restrict__ kb = g_kb + (size_t)b * LL * DQK;
    const __nv_bfloat16* __restrict__ vh = g_vhi + (size_t)b * LL * DQK;
    const __nv_bfloat16* __restrict__ vl = g_vlo + (size_t)b * LL * DQK;

    // ---- Q bf16 copy [32][128] -> smem
#pragma unroll
    for (int j = 0; j < 2; j++) {
        int idx = t + j * 256;                 // 0..511 uint4
        int r = idx >> 4, c8 = (idx & 15) * 8;
        *(uint4*)&Qsm[r * QPAD + c8] = *(const uint4*)&qb[r * DQK + c8];
    }
    __syncthreads();

    const int wm = warp & 1;      // row group 16
    const int wn = warp >> 1;     // col group 16 within 64-key tile
    wmma::fragment<wmma::matrix_a, 16, 16, 16, __nv_bfloat16,
                   wmma::row_major> qa[8];
#pragma unroll
    for (int ks = 0; ks < 8; ks++)
        wmma::load_matrix_sync(qa[ks], Qsm + (wm * 16) * QPAD + ks * 16, QPAD);

    // ---- stage 1
    for (int ct = 0; ct < 8; ct++) {
        __syncthreads();   // qa loads / prior tile mma done before Ksm overwrite
#pragma unroll
        for (int j = 0; j < 4; j++) {
            int idx = t + j * 256;             // 0..1023 uint4
            int r = idx >> 4, c8 = (idx & 15) * 8;
            *(uint4*)&Ksm[r * QPAD + c8] =
                *(const uint4*)&kb[(size_t)(ct * 64 + r) * DQK + c8];
        }
        __syncthreads();

        wmma::fragment<wmma::accumulator, 16, 16, 16, float> c1;
        wmma::fill_fragment(c1, 0.0f);
#pragma unroll
        for (int ks = 0; ks < 8; ks++) {
            wmma::fragment<wmma::matrix_b, 16, 16, 16, __nv_bfloat16,
                           wmma::col_major> kf;
            wmma::load_matrix_sync(kf, Ksm + (wn * 16) * QPAD + ks * 16, QPAD);
            wmma::mma_sync(c1, qa[ks], kf, c1);
        }
        wmma::store_matrix_sync(Ss + (wm * 16) * SSPAD + ct * 64 + wn * 16,
                                c1, SSPAD, wmma::mem_row_major);
    }
    __syncthreads();

    // ---- fused scale + mask + softmax + bias (warp owns 4 rows)
    const float inv_scale = 0.08838834764831845f;   // 1/sqrt(128)
#pragma unroll
    for (int j = 0; j < 4; j++) {
        const int r = warp * 4 + j;
        const unsigned int* mrow = mask + (size_t)(b * LL + row0 + r) * LL;
        float mx = -1e30f;
        for (int m = lane; m < LL; m += 32) {
            float s = (mrow[m] != 0u) ? 1e-9f : Ss[r * SSPAD + m] * inv_scale;
            Ss[r * SSPAD + m] = s;
            mx = fmaxf(mx, s);
        }
#pragma unroll
        for (int o = 16; o > 0; o >>= 1) mx = fmaxf(mx, __shfl_xor_sync(0xffffffffu, mx, o));
        float sum = 0.f;
        for (int m = lane; m < LL; m += 32) {
            float e = __expf(Ss[r * SSPAD + m] - mx);
            Ss[r * SSPAD + m] = e;
            sum += e;
        }
#pragma unroll
        for (int o = 16; o > 0; o >>= 1) sum += __shfl_xor_sync(0xffffffffu, sum, o);
        const float inv = 1.0f / sum;
        const float* __restrict__ brow = g_bias + (size_t)(b * LL + row0 + r) * LL;
        for (int m = lane; m < LL; m += 32)
            Ss[r * SSPAD + m] = Ss[r * SSPAD + m] * inv + brow[m];
    }

    // ---- stage 2: 8 tiles of 64 keys; split A, copy pre-split V
    const int wn2 = warp >> 1;    // col group 32 (4 groups)
    wmma::fragment<wmma::accumulator, 16, 16, 16, float> o2[2];
    wmma::fill_fragment(o2[0], 0.0f);
    wmma::fill_fragment(o2[1], 0.0f);

    for (int mt = 0; mt < 8; mt++) {
        __syncthreads();   // prior tile reads done before overwrite
        // A block [32][64] f32 -> hi/lo bf16
#pragma unroll
        for (int j = 0; j < 4; j++) {
            int idx = t + j * 256;             // 0..1023 float2
            int r = idx >> 5, c2 = (idx & 31) * 2;
            float2 s2 = *(float2*)&Ss[r * SSPAD + mt * 64 + c2];
            __nv_bfloat162 hi, lo;
            split2(s2.x, s2.y, hi, lo);
            *(__nv_bfloat162*)&Abhi[r * APAD + c2] = hi;
            *(__nv_bfloat162*)&Ablo[r * APAD + c2] = lo;
        }
        // V tile [64][128] hi/lo bf16 copies
#pragma unroll
        for (int j = 0; j < 4; j++) {
            int idx = t + j * 256;             // 0..1023 uint4
            int r = idx >> 4, c8 = (idx & 15) * 8;
            size_t o = (size_t)(mt * 64 + r) * DQK + c8;
            *(uint4*)&Vhi[r * QPAD + c8] = *(const uint4*)&vh[o];
            *(uint4*)&Vlo[r * QPAD + c8] = *(const uint4*)&vl[o];
        }
        __syncthreads();

#pragma unroll
        for (int ks = 0; ks < 4; ks++) {
            wmma::fragment<wmma::matrix_a, 16, 16, 16, __nv_bfloat16,
                           wmma::row_major> ah, al;
            wmma::load_matrix_sync(ah, Abhi + (wm * 16) * APAD + ks * 16, APAD);
            wmma::load_matrix_sync(al, Ablo + (wm * 16) * APAD + ks * 16, APAD);
#pragma unroll
            for (int nf = 0; nf < 2; nf++) {
                wmma::fragment<wmma::matrix_b, 16, 16, 16, __nv_bfloat16,
                               wmma::row_major> vhf, vlf;
                const int nc = wn2 * 32 + nf * 16;
                wmma::load_matrix_sync(vhf, Vhi + (ks * 16) * QPAD + nc, QPAD);
                wmma::load_matrix_sync(vlf, Vlo + (ks * 16) * QPAD + nc, QPAD);
                wmma::mma_sync(o2[nf], ah, vhf, o2[nf]);
                wmma::mma_sync(o2[nf], ah, vlf, o2[nf]);
                wmma::mma_sync(o2[nf], al, vhf, o2[nf]);
            }
        }
    }

#pragma unroll
    for (int nf = 0; nf < 2; nf++)
        wmma::store_matrix_sync(
            &out[(size_t)(b * LL + row0 + wm * 16) * DQK + wn2 * 32 + nf * 16],
            o2[nf], DQK, wmma::mem_row_major);
}

// =====================================================================
// Launch
// =====================================================================
extern "C" void kernel_launch(void* const* d_in, const int* in_sizes, int n_in,
                              void* d_out, int out_size) {
    const float* query = (const float*)d_in[0];
    const float* key_  = (const float*)d_in[1];
    const float* value = (const float*)d_in[2];
    const float* sf    = (const float*)d_in[3];
    const unsigned int* mask = (const unsigned int*)d_in[4];
    const float* Wq  = (const float*)d_in[5];
    const float* bq  = (const float*)d_in[6];
    const float* Wk  = (const float*)d_in[7];
    const float* bk  = (const float*)d_in[8];
    const float* Wv  = (const float*)d_in[9];
    const float* bv  = (const float*)d_in[10];
    const float* Wb1 = (const float*)d_in[11];
    const float* bb1 = (const float*)d_in[12];
    const float* Wb2 = (const float*)d_in[13];
    const float* bb2 = (const float*)d_in[14];
    float* out = (float*)d_out;

    (void)in_sizes; (void)n_in; (void)out_size;

    prep_w<<<dim3(256, 3), 256>>>(Wq, Wk, Wv);
    proj3_wmma<<<dim3(NB * LL / 64, 3), 256, PROJ_SMEM>>>(query, key_, value,
                                                          bq, bk, bv);
    mlp1_kernel<<<512, 256>>>(sf, Wb1, bb1);

    cudaFuncSetAttribute(bias_wmma,
                         cudaFuncAttributeMaxDynamicSharedMemorySize, BW_SMEM);
    bias_wmma<<<LLSQ / 128, 256, BW_SMEM>>>(Wb2, bb2);

    cudaFuncSetAttribute(attn_wmma,
                         cudaFuncAttributeMaxDynamicSharedMemorySize, ATTN_SMEM);
    attn_wmma<<<dim3(LL / 32, NB), 256, ATTN_SMEM>>>(mask, out);
}

// round 14
// speedup vs baseline: 2.1746x; 1.0957x over previous
#include <cuda_runtime.h>
#include <cuda_bf16.h>
#include <mma.h>
#include <cstdint>

using namespace nvcuda;

#define NB   32      // batch
#define LL   512     // sequence length
#define DIN  512
#define DQK  128
#define DS   256
#define DMLP 128
#define LLSQ (LL*LL) // 262144

// ---------------- device scratch (static: allocation-free) ----------------
__device__ __nv_bfloat16 g_qb [NB * LL * DQK];   // bf16 q
__device__ __nv_bfloat16 g_kb [NB * LL * DQK];   // bf16 k
__device__ __nv_bfloat16 g_vhi[NB * LL * DQK];   // v hi
__device__ __nv_bfloat16 g_vlo[NB * LL * DQK];   // v lo
__device__ __nv_bfloat16 g_whi[3 * DIN * DQK];   // Wq|Wk|Wv hi
__device__ __nv_bfloat16 g_wlo[3 * DIN * DQK];   // Wq|Wk|Wv lo
__device__ __nv_bfloat16 g_hhi[NB * DMLP];
__device__ __nv_bfloat16 g_hlo[NB * DMLP];
__device__ float g_bias[NB * LLSQ];              // 33.5 MB

__device__ __forceinline__ void split2(float x, float y,
                                       __nv_bfloat162& hi, __nv_bfloat162& lo) {
    __nv_bfloat16 hx = __float2bfloat16(x);
    __nv_bfloat16 hy = __float2bfloat16(y);
    hi = __halves2bfloat162(hx, hy);
    lo = __halves2bfloat162(__float2bfloat16(x - __bfloat162float(hx)),
                            __float2bfloat16(y - __bfloat162float(hy)));
}

// =====================================================================
// prep_w: split Wq/Wk/Wv fp32 -> bf16 hi/lo once. grid (256,3) x 256.
// =====================================================================
__global__ __launch_bounds__(256) void prep_w(const float* __restrict__ Wq,
                                              const float* __restrict__ Wk,
                                              const float* __restrict__ Wv) {
    const float* src = (blockIdx.y == 0) ? Wq : (blockIdx.y == 1) ? Wk : Wv;
    int i = blockIdx.x * 256 + threadIdx.x;          // 0..65535
    float v = src[i];
    __nv_bfloat16 h = __float2bfloat16(v);
    g_whi[blockIdx.y * (DIN * DQK) + i] = h;
    g_wlo[blockIdx.y * (DIN * DQK) + i] = __float2bfloat16(v - __bfloat162float(h));
}

// =====================================================================
// WMMA bf16 split-GEMM projection (unchanged from R13)
// =====================================================================
#define PAD_A 40
#define PAD_B 136
#define PAD_C 132
#define PROJ_SMEM 33792

__global__ __launch_bounds__(256, 2) void proj3_wmma(
        const float* __restrict__ Xq, const float* __restrict__ Xk,
        const float* __restrict__ Xv,
        const float* __restrict__ bq, const float* __restrict__ bk,
        const float* __restrict__ bv) {
    extern __shared__ char sm[];
    __nv_bfloat16* Ahi = (__nv_bfloat16*)sm;            // [64][40]
    __nv_bfloat16* Alo = Ahi + 64 * PAD_A;
    __nv_bfloat16* Bhi = Alo + 64 * PAD_A;              // [32][136]
    __nv_bfloat16* Blo = Bhi + 32 * PAD_B;
    float* Cs = (float*)sm;                             // [64][132] (union)

    const int by = blockIdx.y;
    const float* X  = (by == 0) ? Xq : (by == 1) ? Xk : Xv;
    const float* Bb = (by == 0) ? bq : (by == 1) ? bk : bv;
    const __nv_bfloat16* whi = g_whi + by * (DIN * DQK);
    const __nv_bfloat16* wlo = g_wlo + by * (DIN * DQK);

    const int t = threadIdx.x;
    const int warp = t >> 5;
    const int wm = warp & 3;
    const int wn = warp >> 2;
    const int row0 = blockIdx.x * 64;

    wmma::fragment<wmma::accumulator, 16, 16, 16, float> c[4];
#pragma unroll
    for (int nf = 0; nf < 4; nf++) wmma::fill_fragment(c[nf], 0.0f);

    for (int kc = 0; kc < 16; kc++) {
        const int k0 = kc * 32;

        float4 xa[2];
        uint4 wh[2], wl[2];
#pragma unroll
        for (int j = 0; j < 2; j++) {
            int idx = t + j * 256;
            int r = idx >> 3, c4 = (idx & 7) * 4;
            xa[j] = *(const float4*)&X[(size_t)(row0 + r) * DIN + k0 + c4];
        }
#pragma unroll
        for (int j = 0; j < 2; j++) {
            int idx = t + j * 256;
            int k = idx >> 4, c8 = (idx & 15) * 8;
            wh[j] = *(const uint4*)&whi[(size_t)(k0 + k) * DQK + c8];
            wl[j] = *(const uint4*)&wlo[(size_t)(k0 + k) * DQK + c8];
        }

        __syncthreads();

#pragma unroll
        for (int j = 0; j < 2; j++) {
            int idx = t + j * 256;
            int r = idx >> 3, c4 = (idx & 7) * 4;
            __nv_bfloat162 h0, l0, h1, l1;
            split2(xa[j].x, xa[j].y, h0, l0);
            split2(xa[j].z, xa[j].w, h1, l1);
            *(__nv_bfloat162*)&Ahi[r * PAD_A + c4]     = h0;
            *(__nv_bfloat162*)&Ahi[r * PAD_A + c4 + 2] = h1;
            *(__nv_bfloat162*)&Alo[r * PAD_A + c4]     = l0;
            *(__nv_bfloat162*)&Alo[r * PAD_A + c4 + 2] = l1;
        }
#pragma unroll
        for (int j = 0; j < 2; j++) {
            int idx = t + j * 256;
            int k = idx >> 4, c8 = (idx & 15) * 8;
            *(uint4*)&Bhi[k * PAD_B + c8] = wh[j];
            *(uint4*)&Blo[k * PAD_B + c8] = wl[j];
        }
        __syncthreads();

#pragma unroll
        for (int ks = 0; ks < 32; ks += 16) {
            wmma::fragment<wmma::matrix_a, 16, 16, 16, __nv_bfloat16,
                           wmma::row_major> ah, al;
            wmma::load_matrix_sync(ah, Ahi + (wm * 16) * PAD_A + ks, PAD_A);
            wmma::load_matrix_sync(al, Alo + (wm * 16) * PAD_A + ks, PAD_A);
#pragma unroll
            for (int nf = 0; nf < 4; nf++) {
                wmma::fragment<wmma::matrix_b, 16, 16, 16, __nv_bfloat16,
                               wmma::row_major> bh, bl;
                const int nc = wn * 64 + nf * 16;
                wmma::load_matrix_sync(bh, Bhi + ks * PAD_B + nc, PAD_B);
                wmma::load_matrix_sync(bl, Blo + ks * PAD_B + nc, PAD_B);
                wmma::mma_sync(c[nf], ah, bh, c[nf]);
                wmma::mma_sync(c[nf], ah, bl, c[nf]);
                wmma::mma_sync(c[nf], al, bh, c[nf]);
            }
        }
    }

    __syncthreads();
#pragma unroll
    for (int nf = 0; nf < 4; nf++)
        wmma::store_matrix_sync(Cs + (wm * 16) * PAD_C + wn * 64 + nf * 16,
                                c[nf], PAD_C, wmma::mem_row_major);
    __syncthreads();

#pragma unroll
    for (int j = 0; j < 8; j++) {
        int idx = t + j * 256;
        int r = idx >> 5, c4 = (idx & 31) * 4;
        float4 v = *(float4*)&Cs[r * PAD_C + c4];
        float4 bvv = *(const float4*)&Bb[c4];
        v.x += bvv.x; v.y += bvv.y; v.z += bvv.z; v.w += bvv.w;
        size_t o = (size_t)(row0 + r) * DQK + c4;
        if (by == 2) {
            __nv_bfloat162 h0, l0, h1, l1;
            split2(v.x, v.y, h0, l0);
            split2(v.z, v.w, h1, l1);
            *(__nv_bfloat162*)&g_vhi[o]     = h0;
            *(__nv_bfloat162*)&g_vhi[o + 2] = h1;
            *(__nv_bfloat162*)&g_vlo[o]     = l0;
            *(__nv_bfloat162*)&g_vlo[o + 2] = l1;
        } else {
            __nv_bfloat16* Yb = (by == 0) ? g_qb : g_kb;
            *(__nv_bfloat162*)&Yb[o] =
                __halves2bfloat162(__float2bfloat16(v.x), __float2bfloat16(v.y));
            *(__nv_bfloat162*)&Yb[o + 2] =
                __halves2bfloat162(__float2bfloat16(v.z), __float2bfloat16(v.w));
        }
    }
}

// =====================================================================
// Bias MLP stage 1 (unchanged)
// =====================================================================
__global__ __launch_bounds__(256) void mlp1_kernel(const float* __restrict__ sf,
                                                   const float* __restrict__ Wb1,
                                                   const float* __restrict__ bb1) {
    const int gw   = blockIdx.x * 8 + (threadIdx.x >> 5);
    const int lane = threadIdx.x & 31;
    const int b    = gw >> 7;
    const int n    = gw & 127;

    float s = 0.f;
#pragma unroll
    for (int kk = 0; kk < 8; kk++) {
        int k = kk * 32 + lane;
        s = fmaf(sf[b * DS + k], Wb1[(size_t)k * DMLP + n], s);
    }
#pragma unroll
    for (int o = 16; o > 0; o >>= 1) s += __shfl_xor_sync(0xffffffffu, s, o);
    if (lane == 0) {
        float val = fmaxf(s + bb1[n], 0.f);
        __nv_bfloat16 h = __float2bfloat16(val);
        g_hhi[b * DMLP + n] = h;
        g_hlo[b * DMLP + n] = __float2bfloat16(val - __bfloat162float(h));
    }
}

// =====================================================================
// Bias MLP stage 2 via WMMA split (unchanged from R13)
// =====================================================================
#define BW_WHI 0
#define BW_WLO 34816
#define BW_AHH 69632
#define BW_AHL 78336
#define BW_SMEM 87040
#define HPAD 136

__global__ __launch_bounds__(256, 2) void bias_wmma(const float* __restrict__ Wb2,
                                                    const float* __restrict__ bb2) {
    extern __shared__ char sm[];
    __nv_bfloat16* Whi = (__nv_bfloat16*)(sm + BW_WHI);
    __nv_bfloat16* Wlo = (__nv_bfloat16*)(sm + BW_WLO);
    __nv_bfloat16* Ahh = (__nv_bfloat16*)(sm + BW_AHH);
    __nv_bfloat16* Ahl = (__nv_bfloat16*)(sm + BW_AHL);
    float*         Cs  = (float*)(sm + BW_AHH);          // union, after MMA

    const int t = threadIdx.x;
    const int warp = t >> 5;
    const int wm = warp & 1;
    const int wn = warp >> 1;
    const int n0 = blockIdx.x * 128;

#pragma unroll
    for (int j = 0; j < 2; j++) {
        int idx = t + j * 256;
        int r = idx >> 4, c8 = (idx & 15) * 8;
        *(uint4*)&Ahh[r * HPAD + c8] = *(const uint4*)&g_hhi[r * DMLP + c8];
        *(uint4*)&Ahl[r * HPAD + c8] = *(const uint4*)&g_hlo[r * DMLP + c8];
    }
#pragma unroll
    for (int j = 0; j < 16; j++) {
        int idx = t + j * 256;
        int k = idx >> 5, n4 = (idx & 31) * 4;
        float4 w = *(const float4*)&Wb2[(size_t)k * LLSQ + n0 + n4];
        __nv_bfloat162 h0, l0, h1, l1;
        split2(w.x, w.y, h0, l0);
        split2(w.z, w.w, h1, l1);
        *(__nv_bfloat162*)&Whi[k * HPAD + n4]     = h0;
        *(__nv_bfloat162*)&Whi[k * HPAD + n4 + 2] = h1;
        *(__nv_bfloat162*)&Wlo[k * HPAD + n4]     = l0;
        *(__nv_bfloat162*)&Wlo[k * HPAD + n4 + 2] = l1;
    }
    __syncthreads();

    wmma::fragment<wmma::accumulator, 16, 16, 16, float> c2[2];
    wmma::fill_fragment(c2[0], 0.0f);
    wmma::fill_fragment(c2[1], 0.0f);

#pragma unroll
    for (int ks = 0; ks < 8; ks++) {
        wmma::fragment<wmma::matrix_a, 16, 16, 16, __nv_bfloat16,
                       wmma::row_major> ah, al;
        wmma::load_matrix_sync(ah, Ahh + (wm * 16) * HPAD + ks * 16, HPAD);
        wmma::load_matrix_sync(al, Ahl + (wm * 16) * HPAD + ks * 16, HPAD);
#pragma unroll
        for (int nf = 0; nf < 2; nf++) {
            wmma::fragment<wmma::matrix_b, 16, 16, 16, __nv_bfloat16,
                           wmma::row_major> bh, bl;
            const int nc = wn * 32 + nf * 16;
            wmma::load_matrix_sync(bh, Whi + (ks * 16) * HPAD + nc, HPAD);
            wmma::load_matrix_sync(bl, Wlo + (ks * 16) * HPAD + nc, HPAD);
            wmma::mma_sync(c2[nf], ah, bh, c2[nf]);
            wmma::mma_sync(c2[nf], ah, bl, c2[nf]);
            wmma::mma_sync(c2[nf], al, bh, c2[nf]);
        }
    }

    __syncthreads();
#pragma unroll
    for (int nf = 0; nf < 2; nf++)
        wmma::store_matrix_sync(Cs + (wm * 16) * HPAD + wn * 32 + nf * 16,
                                c2[nf], HPAD, wmma::mem_row_major);
    __syncthreads();

#pragma unroll
    for (int j = 0; j < 4; j++) {
        int idx = t + j * 256;
        int r = idx >> 5, c4 = (idx & 31) * 4;
        float4 v = *(float4*)&Cs[r * HPAD + c4];
        float4 b2 = *(const float4*)&bb2[n0 + c4];
        v.x += b2.x; v.y += b2.y; v.z += b2.z; v.w += b2.w;
        *(float4*)&g_bias[(size_t)r * LLSQ + n0 + c4] = v;
    }
}

// =====================================================================
// WMMA fused attention with register prefetch on K/V tiles.
// smem layout identical to R13 (110592 B, 2 CTAs/SM).
// =====================================================================
#define SSPAD 520
#define AT_KV   66560
#define AT_VLO  83968
#define AT_ABH  101376
#define AT_ABL  105984
#define ATTN_SMEM 110592
#define QPAD 136
#define APAD 72

__global__ __launch_bounds__(256, 2) void attn_wmma(const unsigned int* __restrict__ mask,
                                                    float* __restrict__ out) {
    extern __shared__ char sm[];
    float*         Ss   = (float*)sm;                     // [32][520]
    __nv_bfloat16* Qsm  = (__nv_bfloat16*)(sm + AT_KV);   // [32][136]
    __nv_bfloat16* Ksm  = (__nv_bfloat16*)(sm + AT_KV);   // [64][136]
    __nv_bfloat16* Vhi  = (__nv_bfloat16*)(sm + AT_KV);   // [64][136]
    __nv_bfloat16* Vlo  = (__nv_bfloat16*)(sm + AT_VLO);  // [64][136]
    __nv_bfloat16* Abhi = (__nv_bfloat16*)(sm + AT_ABH);  // [32][72]
    __nv_bfloat16* Ablo = (__nv_bfloat16*)(sm + AT_ABL);  // [32][72]

    const int t    = threadIdx.x;
    const int lane = t & 31;
    const int warp = t >> 5;
    const int b    = blockIdx.y;
    const int row0 = blockIdx.x * 32;

    const __nv_bfloat16* __restrict__ qb = g_qb + (size_t)(b * LL + row0) * DQK;
    const __nv_bfloat16* __restrict__ kb = g_kb + (size_t)b * LL * DQK;
    const __nv_bfloat16* __restrict__ vh = g_vhi + (size_t)b * LL * DQK;
    const __nv_bfloat16* __restrict__ vl = g_vlo + (size_t)b * LL * DQK;

    // ---- Q bf16 copy [32][128] -> smem
#pragma unroll
    for (int j = 0; j < 2; j++) {
        int idx = t + j * 256;
        int r = idx >> 4, c8 = (idx & 15) * 8;
        *(uint4*)&Qsm[r * QPAD + c8] = *(const uint4*)&qb[r * DQK + c8];
    }
    __syncthreads();

    const int wm = warp & 1;
    const int wn = warp >> 1;
    wmma::fragment<wmma::matrix_a, 16, 16, 16, __nv_bfloat16,
                   wmma::row_major> qa[8];
#pragma unroll
    for (int ks = 0; ks < 8; ks++)
        wmma::load_matrix_sync(qa[ks], Qsm + (wm * 16) * QPAD + ks * 16, QPAD);

    // ---- preload K tile 0 into regs
    uint4 kreg[4];
#pragma unroll
    for (int j = 0; j < 4; j++) {
        int idx = t + j * 256;
        int r = idx >> 4, c8 = (idx & 15) * 8;
        kreg[j] = *(const uint4*)&kb[(size_t)r * DQK + c8];
    }
    __syncthreads();   // all warps done reading Qsm (aliased by Ksm)

    // ---- stage 1: prefetch pipeline over 8 key tiles
    for (int ct = 0; ct < 8; ct++) {
#pragma unroll
        for (int j = 0; j < 4; j++) {
            int idx = t + j * 256;
            int r = idx >> 4, c8 = (idx & 15) * 8;
            *(uint4*)&Ksm[r * QPAD + c8] = kreg[j];
        }
        __syncthreads();
        if (ct < 7) {
#pragma unroll
            for (int j = 0; j < 4; j++) {
                int idx = t + j * 256;
                int r = idx >> 4, c8 = (idx & 15) * 8;
                kreg[j] = *(const uint4*)&kb[(size_t)((ct + 1) * 64 + r) * DQK + c8];
            }
        }

        wmma::fragment<wmma::accumulator, 16, 16, 16, float> c1;
        wmma::fill_fragment(c1, 0.0f);
#pragma unroll
        for (int ks = 0; ks < 8; ks++) {
            wmma::fragment<wmma::matrix_b, 16, 16, 16, __nv_bfloat16,
                           wmma::col_major> kf;
            wmma::load_matrix_sync(kf, Ksm + (wn * 16) * QPAD + ks * 16, QPAD);
            wmma::mma_sync(c1, qa[ks], kf, c1);
        }
        wmma::store_matrix_sync(Ss + (wm * 16) * SSPAD + ct * 64 + wn * 16,
                                c1, SSPAD, wmma::mem_row_major);
        __syncthreads();   // Ksm reads done before next STS
    }

    // ---- fused scale + mask + softmax + bias (warp owns 4 rows)
    const float inv_scale = 0.08838834764831845f;   // 1/sqrt(128)
#pragma unroll
    for (int j = 0; j < 4; j++) {
        const int r = warp * 4 + j;
        const unsigned int* mrow = mask + (size_t)(b * LL + row0 + r) * LL;
        float mx = -1e30f;
        for (int m = lane; m < LL; m += 32) {
            float s = (mrow[m] != 0u) ? 1e-9f : Ss[r * SSPAD + m] * inv_scale;
            Ss[r * SSPAD + m] = s;
            mx = fmaxf(mx, s);
        }
#pragma unroll
        for (int o = 16; o > 0; o >>= 1) mx = fmaxf(mx, __shfl_xor_sync(0xffffffffu, mx, o));
        float sum = 0.f;
        for (int m = lane; m < LL; m += 32) {
            float e = __expf(Ss[r * SSPAD + m] - mx);
            Ss[r * SSPAD + m] = e;
            sum += e;
        }
#pragma unroll
        for (int o = 16; o > 0; o >>= 1) sum += __shfl_xor_sync(0xffffffffu, sum, o);
        const float inv = 1.0f / sum;
        const float* __restrict__ brow = g_bias + (size_t)(b * LL + row0 + r) * LL;
        for (int m = lane; m < LL; m += 32)
            Ss[r * SSPAD + m] = Ss[r * SSPAD + m] * inv + brow[m];
    }

    // ---- preload V tile 0 into regs
    uint4 vhreg[4], vlreg[4];
#pragma unroll
    for (int j = 0; j < 4; j++) {
        int idx = t + j * 256;
        int r = idx >> 4, c8 = (idx & 15) * 8;
        vhreg[j] = *(const uint4*)&vh[(size_t)r * DQK + c8];
        vlreg[j] = *(const uint4*)&vl[(size_t)r * DQK + c8];
    }
    __syncthreads();   // softmax writes visible to all warps

    // ---- stage 2: prefetch pipeline over 8 V tiles (split A per tile)
    const int wn2 = warp >> 1;
    wmma::fragment<wmma::accumulator, 16, 16, 16, float> o2[2];
    wmma::fill_fragment(o2[0], 0.0f);
    wmma::fill_fragment(o2[1], 0.0f);

    for (int mt = 0; mt < 8; mt++) {
#pragma unroll
        for (int j = 0; j < 4; j++) {
            int idx = t + j * 256;
            int r = idx >> 4, c8 = (idx & 15) * 8;
            *(uint4*)&Vhi[r * QPAD + c8] = vhreg[j];
            *(uint4*)&Vlo[r * QPAD + c8] = vlreg[j];
        }
#pragma unroll
        for (int j = 0; j < 4; j++) {
            int idx = t + j * 256;
            int r = idx >> 5, c2 = (idx & 31) * 2;
            float2 s2 = *(float2*)&Ss[r * SSPAD + mt * 64 + c2];
            __nv_bfloat162 hi, lo;
            split2(s2.x, s2.y, hi, lo);
            *(__nv_bfloat162*)&Abhi[r * APAD + c2] = hi;
            *(__nv_bfloat162*)&Ablo[r * APAD + c2] = lo;
        }
        __syncthreads();
        if (mt < 7) {
#pragma unroll
            for (int j = 0; j < 4; j++) {
                int idx = t + j * 256;
                int r = idx >> 4, c8 = (idx & 15) * 8;
                size_t o = (size_t)((mt + 1) * 64 + r) * DQK + c8;
                vhreg[j] = *(const uint4*)&vh[o];
                vlreg[j] = *(const uint4*)&vl[o];
            }
        }

#pragma unroll
        for (int ks = 0; ks < 4; ks++) {
            wmma::fragment<wmma::matrix_a, 16, 16, 16, __nv_bfloat16,
                           wmma::row_major> ah, al;
            wmma::load_matrix_sync(ah, Abhi + (wm * 16) * APAD + ks * 16, APAD);
            wmma::load_matrix_sync(al, Ablo + (wm * 16) * APAD + ks * 16, APAD);
#pragma unroll
            for (int nf = 0; nf < 2; nf++) {
                wmma::fragment<wmma::matrix_b, 16, 16, 16, __nv_bfloat16,
                               wmma::row_major> vhf, vlf;
                const int nc = wn2 * 32 + nf * 16;
                wmma::load_matrix_sync(vhf, Vhi + (ks * 16) * QPAD + nc, QPAD);
                wmma::load_matrix_sync(vlf, Vlo + (ks * 16) * QPAD + nc, QPAD);
                wmma::mma_sync(o2[nf], ah, vhf, o2[nf]);
                wmma::mma_sync(o2[nf], ah, vlf, o2[nf]);
                wmma::mma_sync(o2[nf], al, vhf, o2[nf]);
            }
        }
        __syncthreads();   // Vhi/Vlo/Ab reads done before next overwrite
    }

#pragma unroll
    for (int nf = 0; nf < 2; nf++)
        wmma::store_matrix_sync(
            &out[(size_t)(b * LL + row0 + wm * 16) * DQK + wn2 * 32 + nf * 16],
            o2[nf], DQK, wmma::mem_row_major);
}

// =====================================================================
// Launch: two-stream fork/join captured via events.
//   stream 0 (capture origin): prep_w -> proj3 -> [join] -> attn
//   s_side:                    mlp1 -> bias_wmma
// Streams/events created on first (uncaptured, correctness) call;
// no device memory is allocated.
// =====================================================================
static cudaStream_t g_s1 = nullptr;
static cudaEvent_t  g_evFork = nullptr, g_evJoin = nullptr;

extern "C" void kernel_launch(void* const* d_in, const int* in_sizes, int n_in,
                              void* d_out, int out_size) {
    const float* query = (const float*)d_in[0];
    const float* key_  = (const float*)d_in[1];
    const float* value = (const float*)d_in[2];
    const float* sf    = (const float*)d_in[3];
    const unsigned int* mask = (const unsigned int*)d_in[4];
    const float* Wq  = (const float*)d_in[5];
    const float* bq  = (const float*)d_in[6];
    const float* Wk  = (const float*)d_in[7];
    const float* bk  = (const float*)d_in[8];
    const float* Wv  = (const float*)d_in[9];
    const float* bv  = (const float*)d_in[10];
    const float* Wb1 = (const float*)d_in[11];
    const float* bb1 = (const float*)d_in[12];
    const float* Wb2 = (const float*)d_in[13];
    const float* bb2 = (const float*)d_in[14];
    float* out = (float*)d_out;

    (void)in_sizes; (void)n_in; (void)out_size;

    if (g_s1 == nullptr) {
        cudaStreamCreateWithFlags(&g_s1, cudaStreamNonBlocking);
        cudaEventCreateWithFlags(&g_evFork, cudaEventDisableTiming);
        cudaEventCreateWithFlags(&g_evJoin, cudaEventDisableTiming);
        cudaFuncSetAttribute(bias_wmma,
                             cudaFuncAttributeMaxDynamicSharedMemorySize, BW_SMEM);
        cudaFuncSetAttribute(attn_wmma,
                             cudaFuncAttributeMaxDynamicSharedMemorySize, ATTN_SMEM);
    }

    // fork: side chain mlp1 -> bias (independent of proj chain)
    cudaEventRecord(g_evFork, (cudaStream_t)0);
    cudaStreamWaitEvent(g_s1, g_evFork, 0);
    mlp1_kernel<<<512, 256, 0, g_s1>>>(sf, Wb1, bb1);
    bias_wmma<<<LLSQ / 128, 256, BW_SMEM, g_s1>>>(Wb2, bb2);
    cudaEventRecord(g_evJoin, g_s1);

    // main chain on capture-origin stream
    prep_w<<<dim3(256, 3), 256>>>(Wq, Wk, Wv);
    proj3_wmma<<<dim3(NB * LL / 64, 3), 256, PROJ_SMEM>>>(query, key_, value,
                                                          bq, bk, bv);

    // join, then attention
    cudaStreamWaitEvent((cudaStream_t)0, g_evJoin, 0);
    attn_wmma<<<dim3(LL / 32, NB), 256, ATTN_SMEM>>>(mask, out);
}

// round 15
// speedup vs baseline: 2.2079x; 1.0153x over previous
#include <cuda_runtime.h>
#include <cuda_bf16.h>
#include <mma.h>
#include <cstdint>

using namespace nvcuda;

#define NB   32      // batch
#define LL   512     // sequence length
#define DIN  512
#define DQK  128
#define DS   256
#define DMLP 128
#define LLSQ (LL*LL) // 262144

// ---------------- device scratch (static: allocation-free) ----------------
__device__ __nv_bfloat16 g_qb [NB * LL * DQK];   // bf16 q
__device__ __nv_bfloat16 g_kb [NB * LL * DQK];   // bf16 k
__device__ __nv_bfloat16 g_vhi[NB * LL * DQK];   // v hi
__device__ __nv_bfloat16 g_vlo[NB * LL * DQK];   // v lo
__device__ __nv_bfloat16 g_whi[3 * DIN * DQK];   // Wq|Wk|Wv hi
__device__ __nv_bfloat16 g_wlo[3 * DIN * DQK];   // Wq|Wk|Wv lo
__device__ __nv_bfloat16 g_hhi[NB * DMLP];
__device__ __nv_bfloat16 g_hlo[NB * DMLP];
__device__ float g_bias[NB * LLSQ];              // 33.5 MB

__device__ __forceinline__ void split2(float x, float y,
                                       __nv_bfloat162& hi, __nv_bfloat162& lo) {
    __nv_bfloat16 hx = __float2bfloat16(x);
    __nv_bfloat16 hy = __float2bfloat16(y);
    hi = __halves2bfloat162(hx, hy);
    lo = __halves2bfloat162(__float2bfloat16(x - __bfloat162float(hx)),
                            __float2bfloat16(y - __bfloat162float(hy)));
}

// =====================================================================
// prep_w: split Wq/Wk/Wv fp32 -> bf16 hi/lo once. grid (256,3) x 256.
// =====================================================================
__global__ __launch_bounds__(256) void prep_w(const float* __restrict__ Wq,
                                              const float* __restrict__ Wk,
                                              const float* __restrict__ Wv) {
    const float* src = (blockIdx.y == 0) ? Wq : (blockIdx.y == 1) ? Wk : Wv;
    int i = blockIdx.x * 256 + threadIdx.x;          // 0..65535
    float v = src[i];
    __nv_bfloat16 h = __float2bfloat16(v);
    g_whi[blockIdx.y * (DIN * DQK) + i] = h;
    g_wlo[blockIdx.y * (DIN * DQK) + i] = __float2bfloat16(v - __bfloat162float(h));
}

// =====================================================================
// WMMA bf16 split-GEMM projection, DOUBLE-BUFFERED smem.
// Per K-chunk (32): LDG(next) -> MMA(cur) -> split/STS(next) -> 1 sync.
// Buffer layout (per buffer, 27648 B):
//   Ahi [64][40] @0 (5120) | Alo @5120 (5120)
//   Bhi [32][136] @10240 (8704) | Blo @18944 (8704)
// Two buffers = 55296 B. Epilogue Cs f32 [64][132] unions @0.
// =====================================================================
#define PAD_A 40
#define PAD_B 136
#define PAD_C 132
#define PROJ_BUF 27648
#define PROJ_SMEM (2 * PROJ_BUF)

__global__ __launch_bounds__(256, 2) void proj3_wmma(
        const float* __restrict__ Xq, const float* __restrict__ Xk,
        const float* __restrict__ Xv,
        const float* __restrict__ bq, const float* __restrict__ bk,
        const float* __restrict__ bv) {
    extern __shared__ char sm[];
    float* Cs = (float*)sm;                             // epilogue union

    const int by = blockIdx.y;
    const float* X  = (by == 0) ? Xq : (by == 1) ? Xk : Xv;
    const float* Bb = (by == 0) ? bq : (by == 1) ? bk : bv;
    const __nv_bfloat16* whi = g_whi + by * (DIN * DQK);
    const __nv_bfloat16* wlo = g_wlo + by * (DIN * DQK);

    const int t = threadIdx.x;
    const int warp = t >> 5;
    const int wm = warp & 3;
    const int wn = warp >> 2;
    const int row0 = blockIdx.x * 64;

    wmma::fragment<wmma::accumulator, 16, 16, 16, float> c[4];
#pragma unroll
    for (int nf = 0; nf < 4; nf++) wmma::fill_fragment(c[nf], 0.0f);

    float4 xa[2];
    uint4 wh[2], wl[2];

    // ---- prologue: LDG chunk 0, STS -> buf0
#pragma unroll
    for (int j = 0; j < 2; j++) {
        int idx = t + j * 256;
        int r = idx >> 3, c4 = (idx & 7) * 4;
        xa[j] = *(const float4*)&X[(size_t)(row0 + r) * DIN + c4];
    }
#pragma unroll
    for (int j = 0; j < 2; j++) {
        int idx = t + j * 256;
        int k = idx >> 4, c8 = (idx & 15) * 8;
        wh[j] = *(const uint4*)&whi[(size_t)k * DQK + c8];
        wl[j] = *(const uint4*)&wlo[(size_t)k * DQK + c8];
    }
    {
        __nv_bfloat16* Ahi = (__nv_bfloat16*)(sm + 0);
        __nv_bfloat16* Alo = (__nv_bfloat16*)(sm + 5120);
        __nv_bfloat16* Bhi = (__nv_bfloat16*)(sm + 10240);
        __nv_bfloat16* Blo = (__nv_bfloat16*)(sm + 18944);
#pragma unroll
        for (int j = 0; j < 2; j++) {
            int idx = t + j * 256;
            int r = idx >> 3, c4 = (idx & 7) * 4;
            __nv_bfloat162 h0, l0, h1, l1;
            split2(xa[j].x, xa[j].y, h0, l0);
            split2(xa[j].z, xa[j].w, h1, l1);
            *(__nv_bfloat162*)&Ahi[r * PAD_A + c4]     = h0;
            *(__nv_bfloat162*)&Ahi[r * PAD_A + c4 + 2] = h1;
            *(__nv_bfloat162*)&Alo[r * PAD_A + c4]     = l0;
            *(__nv_bfloat162*)&Alo[r * PAD_A + c4 + 2] = l1;
        }
#pragma unroll
        for (int j = 0; j < 2; j++) {
            int idx = t + j * 256;
            int k = idx >> 4, c8 = (idx & 15) * 8;
            *(uint4*)&Bhi[k * PAD_B + c8] = wh[j];
            *(uint4*)&Blo[k * PAD_B + c8] = wl[j];
        }
    }
    __syncthreads();

    // ---- main loop: 16 chunks, single sync per chunk
#pragma unroll 2
    for (int kc = 0; kc < 16; kc++) {
        const int cur = (kc & 1) * PROJ_BUF;
        const int nxt = ((kc + 1) & 1) * PROJ_BUF;

        if (kc < 15) {
            const int k0 = (kc + 1) * 32;
#pragma unroll
            for (int j = 0; j < 2; j++) {
                int idx = t + j * 256;
                int r = idx >> 3, c4 = (idx & 7) * 4;
                xa[j] = *(const float4*)&X[(size_t)(row0 + r) * DIN + k0 + c4];
            }
#pragma unroll
            for (int j = 0; j < 2; j++) {
                int idx = t + j * 256;
                int k = idx >> 4, c8 = (idx & 15) * 8;
                wh[j] = *(const uint4*)&whi[(size_t)(k0 + k) * DQK + c8];
                wl[j] = *(const uint4*)&wlo[(size_t)(k0 + k) * DQK + c8];
            }
        }

        // MMA on current buffer (data stored one iteration earlier)
        {
            __nv_bfloat16* Ahi = (__nv_bfloat16*)(sm + cur + 0);
            __nv_bfloat16* Alo = (__nv_bfloat16*)(sm + cur + 5120);
            __nv_bfloat16* Bhi = (__nv_bfloat16*)(sm + cur + 10240);
            __nv_bfloat16* Blo = (__nv_bfloat16*)(sm + cur + 18944);
#pragma unroll
            for (int ks = 0; ks < 32; ks += 16) {
                wmma::fragment<wmma::matrix_a, 16, 16, 16, __nv_bfloat16,
                               wmma::row_major> ah, al;
                wmma::load_matrix_sync(ah, Ahi + (wm * 16) * PAD_A + ks, PAD_A);
                wmma::load_matrix_sync(al, Alo + (wm * 16) * PAD_A + ks, PAD_A);
#pragma unroll
                for (int nf = 0; nf < 4; nf++) {
                    wmma::fragment<wmma::matrix_b, 16, 16, 16, __nv_bfloat16,
                                   wmma::row_major> bh, bl;
                    const int nc = wn * 64 + nf * 16;
                    wmma::load_matrix_sync(bh, Bhi + ks * PAD_B + nc, PAD_B);
                    wmma::load_matrix_sync(bl, Blo + ks * PAD_B + nc, PAD_B);
                    wmma::mma_sync(c[nf], ah, bh, c[nf]);
                    wmma::mma_sync(c[nf], ah, bl, c[nf]);
                    wmma::mma_sync(c[nf], al, bh, c[nf]);
                }
            }
        }

        // split + STS next chunk into the other buffer
        if (kc < 15) {
            __nv_bfloat16* Ahi = (__nv_bfloat16*)(sm + nxt + 0);
            __nv_bfloat16* Alo = (__nv_bfloat16*)(sm + nxt + 5120);
            __nv_bfloat16* Bhi = (__nv_bfloat16*)(sm + nxt + 10240);
            __nv_bfloat16* Blo = (__nv_bfloat16*)(sm + nxt + 18944);
#pragma unroll
            for (int j = 0; j < 2; j++) {
                int idx = t + j * 256;
                int r = idx >> 3, c4 = (idx & 7) * 4;
                __nv_bfloat162 h0, l0, h1, l1;
                split2(xa[j].x, xa[j].y, h0, l0);
                split2(xa[j].z, xa[j].w, h1, l1);
                *(__nv_bfloat162*)&Ahi[r * PAD_A + c4]     = h0;
                *(__nv_bfloat162*)&Ahi[r * PAD_A + c4 + 2] = h1;
                *(__nv_bfloat162*)&Alo[r * PAD_A + c4]     = l0;
                *(__nv_bfloat162*)&Alo[r * PAD_A + c4 + 2] = l1;
            }
#pragma unroll
            for (int j = 0; j < 2; j++) {
                int idx = t + j * 256;
                int k = idx >> 4, c8 = (idx & 15) * 8;
                *(uint4*)&Bhi[k * PAD_B + c8] = wh[j];
                *(uint4*)&Blo[k * PAD_B + c8] = wl[j];
            }
        }
        __syncthreads();
    }

    // ---- epilogue through smem: +bias, bf16 outputs
#pragma unroll
    for (int nf = 0; nf < 4; nf++)
        wmma::store_matrix_sync(Cs + (wm * 16) * PAD_C + wn * 64 + nf * 16,
                                c[nf], PAD_C, wmma::mem_row_major);
    __syncthreads();

#pragma unroll
    for (int j = 0; j < 8; j++) {
        int idx = t + j * 256;
        int r = idx >> 5, c4 = (idx & 31) * 4;
        float4 v = *(float4*)&Cs[r * PAD_C + c4];
        float4 bvv = *(const float4*)&Bb[c4];
        v.x += bvv.x; v.y += bvv.y; v.z += bvv.z; v.w += bvv.w;
        size_t o = (size_t)(row0 + r) * DQK + c4;
        if (by == 2) {
            __nv_bfloat162 h0, l0, h1, l1;
            split2(v.x, v.y, h0, l0);
            split2(v.z, v.w, h1, l1);
            *(__nv_bfloat162*)&g_vhi[o]     = h0;
            *(__nv_bfloat162*)&g_vhi[o + 2] = h1;
            *(__nv_bfloat162*)&g_vlo[o]     = l0;
            *(__nv_bfloat162*)&g_vlo[o + 2] = l1;
        } else {
            __nv_bfloat16* Yb = (by == 0) ? g_qb : g_kb;
            *(__nv_bfloat162*)&Yb[o] =
                __halves2bfloat162(__float2bfloat16(v.x), __float2bfloat16(v.y));
            *(__nv_bfloat162*)&Yb[o + 2] =
                __halves2bfloat162(__float2bfloat16(v.z), __float2bfloat16(v.w));
        }
    }
}

// =====================================================================
// Bias MLP stage 1 (unchanged)
// =====================================================================
__global__ __launch_bounds__(256) void mlp1_kernel(const float* __restrict__ sf,
                                                   const float* __restrict__ Wb1,
                                                   const float* __restrict__ bb1) {
    const int gw   = blockIdx.x * 8 + (threadIdx.x >> 5);
    const int lane = threadIdx.x & 31;
    const int b    = gw >> 7;
    const int n    = gw & 127;

    float s = 0.f;
#pragma unroll
    for (int kk = 0; kk < 8; kk++) {
        int k = kk * 32 + lane;
        s = fmaf(sf[b * DS + k], Wb1[(size_t)k * DMLP + n], s);
    }
#pragma unroll
    for (int o = 16; o > 0; o >>= 1) s += __shfl_xor_sync(0xffffffffu, s, o);
    if (lane == 0) {
        float val = fmaxf(s + bb1[n], 0.f);
        __nv_bfloat16 h = __float2bfloat16(val);
        g_hhi[b * DMLP + n] = h;
        g_hlo[b * DMLP + n] = __float2bfloat16(val - __bfloat162float(h));
    }
}

// =====================================================================
// Bias MLP stage 2 via WMMA split (unchanged)
// =====================================================================
#define BW_WHI 0
#define BW_WLO 34816
#define BW_AHH 69632
#define BW_AHL 78336
#define BW_SMEM 87040
#define HPAD 136

__global__ __launch_bounds__(256, 2) void bias_wmma(const float* __restrict__ Wb2,
                                                    const float* __restrict__ bb2) {
    extern __shared__ char sm[];
    __nv_bfloat16* Whi = (__nv_bfloat16*)(sm + BW_WHI);
    __nv_bfloat16* Wlo = (__nv_bfloat16*)(sm + BW_WLO);
    __nv_bfloat16* Ahh = (__nv_bfloat16*)(sm + BW_AHH);
    __nv_bfloat16* Ahl = (__nv_bfloat16*)(sm + BW_AHL);
    float*         Cs  = (float*)(sm + BW_AHH);          // union, after MMA

    const int t = threadIdx.x;
    const int warp = t >> 5;
    const int wm = warp & 1;
    const int wn = warp >> 1;
    const int n0 = blockIdx.x * 128;

#pragma unroll
    for (int j = 0; j < 2; j++) {
        int idx = t + j * 256;
        int r = idx >> 4, c8 = (idx & 15) * 8;
        *(uint4*)&Ahh[r * HPAD + c8] = *(const uint4*)&g_hhi[r * DMLP + c8];
        *(uint4*)&Ahl[r * HPAD + c8] = *(const uint4*)&g_hlo[r * DMLP + c8];
    }
#pragma unroll
    for (int j = 0; j < 16; j++) {
        int idx = t + j * 256;
        int k = idx >> 5, n4 = (idx & 31) * 4;
        float4 w = *(const float4*)&Wb2[(size_t)k * LLSQ + n0 + n4];
        __nv_bfloat162 h0, l0, h1, l1;
        split2(w.x, w.y, h0, l0);
        split2(w.z, w.w, h1, l1);
        *(__nv_bfloat162*)&Whi[k * HPAD + n4]     = h0;
        *(__nv_bfloat162*)&Whi[k * HPAD + n4 + 2] = h1;
        *(__nv_bfloat162*)&Wlo[k * HPAD + n4]     = l0;
        *(__nv_bfloat162*)&Wlo[k * HPAD + n4 + 2] = l1;
    }
    __syncthreads();

    wmma::fragment<wmma::accumulator, 16, 16, 16, float> c2[2];
    wmma::fill_fragment(c2[0], 0.0f);
    wmma::fill_fragment(c2[1], 0.0f);

#pragma unroll
    for (int ks = 0; ks < 8; ks++) {
        wmma::fragment<wmma::matrix_a, 16, 16, 16, __nv_bfloat16,
                       wmma::row_major> ah, al;
        wmma::load_matrix_sync(ah, Ahh + (wm * 16) * HPAD + ks * 16, HPAD);
        wmma::load_matrix_sync(al, Ahl + (wm * 16) * HPAD + ks * 16, HPAD);
#pragma unroll
        for (int nf = 0; nf < 2; nf++) {
            wmma::fragment<wmma::matrix_b, 16, 16, 16, __nv_bfloat16,
                           wmma::row_major> bh, bl;
            const int nc = wn * 32 + nf * 16;
            wmma::load_matrix_sync(bh, Whi + (ks * 16) * HPAD + nc, HPAD);
            wmma::load_matrix_sync(bl, Wlo + (ks * 16) * HPAD + nc, HPAD);
            wmma::mma_sync(c2[nf], ah, bh, c2[nf]);
            wmma::mma_sync(c2[nf], ah, bl, c2[nf]);
            wmma::mma_sync(c2[nf], al, bh, c2[nf]);
        }
    }

    __syncthreads();
#pragma unroll
    for (int nf = 0; nf < 2; nf++)
        wmma::store_matrix_sync(Cs + (wm * 16) * HPAD + wn * 32 + nf * 16,
                                c2[nf], HPAD, wmma::mem_row_major);
    __syncthreads();

#pragma unroll
    for (int j = 0; j < 4; j++) {
        int idx = t + j * 256;
        int r = idx >> 5, c4 = (idx & 31) * 4;
        float4 v = *(float4*)&Cs[r * HPAD + c4];
        float4 b2 = *(const float4*)&bb2[n0 + c4];
        v.x += b2.x; v.y += b2.y; v.z += b2.z; v.w += b2.w;
        *(float4*)&g_bias[(size_t)r * LLSQ + n0 + c4] = v;
    }
}

// =====================================================================
// WMMA fused attention with register prefetch on K/V tiles (unchanged).
// =====================================================================
#define SSPAD 520
#define AT_KV   66560
#define AT_VLO  83968
#define AT_ABH  101376
#define AT_ABL  105984
#define ATTN_SMEM 110592
#define QPAD 136
#define APAD 72

__global__ __launch_bounds__(256, 2) void attn_wmma(const unsigned int* __restrict__ mask,
                                                    float* __restrict__ out) {
    extern __shared__ char sm[];
    float*         Ss   = (float*)sm;                     // [32][520]
    __nv_bfloat16* Qsm  = (__nv_bfloat16*)(sm + AT_KV);   // [32][136]
    __nv_bfloat16* Ksm  = (__nv_bfloat16*)(sm + AT_KV);   // [64][136]
    __nv_bfloat16* Vhi  = (__nv_bfloat16*)(sm + AT_KV);   // [64][136]
    __nv_bfloat16* Vlo  = (__nv_bfloat16*)(sm + AT_VLO);  // [64][136]
    __nv_bfloat16* Abhi = (__nv_bfloat16*)(sm + AT_ABH);  // [32][72]
    __nv_bfloat16* Ablo = (__nv_bfloat16*)(sm + AT_ABL);  // [32][72]

    const int t    = threadIdx.x;
    const int lane = t & 31;
    const int warp = t >> 5;
    const int b    = blockIdx.y;
    const int row0 = blockIdx.x * 32;

    const __nv_bfloat16* __restrict__ qb = g_qb + (size_t)(b * LL + row0) * DQK;
    const __nv_bfloat16* __restrict__ kb = g_kb + (size_t)b * LL * DQK;
    const __nv_bfloat16* __restrict__ vh = g_vhi + (size_t)b * LL * DQK;
    const __nv_bfloat16* __restrict__ vl = g_vlo + (size_t)b * LL * DQK;

#pragma unroll
    for (int j = 0; j < 2; j++) {
        int idx = t + j * 256;
        int r = idx >> 4, c8 = (idx & 15) * 8;
        *(uint4*)&Qsm[r * QPAD + c8] = *(const uint4*)&qb[r * DQK + c8];
    }
    __syncthreads();

    const int wm = warp & 1;
    const int wn = warp >> 1;
    wmma::fragment<wmma::matrix_a, 16, 16, 16, __nv_bfloat16,
                   wmma::row_major> qa[8];
#pragma unroll
    for (int ks = 0; ks < 8; ks++)
        wmma::load_matrix_sync(qa[ks], Qsm + (wm * 16) * QPAD + ks * 16, QPAD);

    uint4 kreg[4];
#pragma unroll
    for (int j = 0; j < 4; j++) {
        int idx = t + j * 256;
        int r = idx >> 4, c8 = (idx & 15) * 8;
        kreg[j] = *(const uint4*)&kb[(size_t)r * DQK + c8];
    }
    __syncthreads();

    for (int ct = 0; ct < 8; ct++) {
#pragma unroll
        for (int j = 0; j < 4; j++) {
            int idx = t + j * 256;
            int r = idx >> 4, c8 = (idx & 15) * 8;
            *(uint4*)&Ksm[r * QPAD + c8] = kreg[j];
        }
        __syncthreads();
        if (ct < 7) {
#pragma unroll
            for (int j = 0; j < 4; j++) {
                int idx = t + j * 256;
                int r = idx >> 4, c8 = (idx & 15) * 8;
                kreg[j] = *(const uint4*)&kb[(size_t)((ct + 1) * 64 + r) * DQK + c8];
            }
        }

        wmma::fragment<wmma::accumulator, 16, 16, 16, float> c1;
        wmma::fill_fragment(c1, 0.0f);
#pragma unroll
        for (int ks = 0; ks < 8; ks++) {
            wmma::fragment<wmma::matrix_b, 16, 16, 16, __nv_bfloat16,
                           wmma::col_major> kf;
            wmma::load_matrix_sync(kf, Ksm + (wn * 16) * QPAD + ks * 16, QPAD);
            wmma::mma_sync(c1, qa[ks], kf, c1);
        }
        wmma::store_matrix_sync(Ss + (wm * 16) * SSPAD + ct * 64 + wn * 16,
                                c1, SSPAD, wmma::mem_row_major);
        __syncthreads();
    }

    const float inv_scale = 0.08838834764831845f;   // 1/sqrt(128)
#pragma unroll
    for (int j = 0; j < 4; j++) {
        const int r = warp * 4 + j;
        const unsigned int* mrow = mask + (size_t)(b * LL + row0 + r) * LL;
        float mx = -1e30f;
        for (int m = lane; m < LL; m += 32) {
            float s = (mrow[m] != 0u) ? 1e-9f : Ss[r * SSPAD + m] * inv_scale;
            Ss[r * SSPAD + m] = s;
            mx = fmaxf(mx, s);
        }
#pragma unroll
        for (int o = 16; o > 0; o >>= 1) mx = fmaxf(mx, __shfl_xor_sync(0xffffffffu, mx, o));
        float sum = 0.f;
        for (int m = lane; m < LL; m += 32) {
            float e = __expf(Ss[r * SSPAD + m] - mx);
            Ss[r * SSPAD + m] = e;
            sum += e;
        }
#pragma unroll
        for (int o = 16; o > 0; o >>= 1) sum += __shfl_xor_sync(0xffffffffu, sum, o);
        const float inv = 1.0f / sum;
        const float* __restrict__ brow = g_bias + (size_t)(b * LL + row0 + r) * LL;
        for (int m = lane; m < LL; m += 32)
            Ss[r * SSPAD + m] = Ss[r * SSPAD + m] * inv + brow[m];
    }

    uint4 vhreg[4], vlreg[4];
#pragma unroll
    for (int j = 0; j < 4; j++) {
        int idx = t + j * 256;
        int r = idx >> 4, c8 = (idx & 15) * 8;
        vhreg[j] = *(const uint4*)&vh[(size_t)r * DQK + c8];
        vlreg[j] = *(const uint4*)&vl[(size_t)r * DQK + c8];
    }
    __syncthreads();

    const int wn2 = warp >> 1;
    wmma::fragment<wmma::accumulator, 16, 16, 16, float> o2[2];
    wmma::fill_fragment(o2[0], 0.0f);
    wmma::fill_fragment(o2[1], 0.0f);

    for (int mt = 0; mt < 8; mt++) {
#pragma unroll
        for (int j = 0; j < 4; j++) {
            int idx = t + j * 256;
            int r = idx >> 4, c8 = (idx & 15) * 8;
            *(uint4*)&Vhi[r * QPAD + c8] = vhreg[j];
            *(uint4*)&Vlo[r * QPAD + c8] = vlreg[j];
        }
#pragma unroll
        for (int j = 0; j < 4; j++) {
            int idx = t + j * 256;
            int r = idx >> 5, c2 = (idx & 31) * 2;
            float2 s2 = *(float2*)&Ss[r * SSPAD + mt * 64 + c2];
            __nv_bfloat162 hi, lo;
            split2(s2.x, s2.y, hi, lo);
            *(__nv_bfloat162*)&Abhi[r * APAD + c2] = hi;
            *(__nv_bfloat162*)&Ablo[r * APAD + c2] = lo;
        }
        __syncthreads();
        if (mt < 7) {
#pragma unroll
            for (int j = 0; j < 4; j++) {
                int idx = t + j * 256;
                int r = idx >> 4, c8 = (idx & 15) * 8;
                size_t o = (size_t)((mt + 1) * 64 + r) * DQK + c8;
                vhreg[j] = *(const uint4*)&vh[o];
                vlreg[j] = *(const uint4*)&vl[o];
            }
        }

#pragma unroll
        for (int ks = 0; ks < 4; ks++) {
            wmma::fragment<wmma::matrix_a, 16, 16, 16, __nv_bfloat16,
                           wmma::row_major> ah, al;
            wmma::load_matrix_sync(ah, Abhi + (wm * 16) * APAD + ks * 16, APAD);
            wmma::load_matrix_sync(al, Ablo + (wm * 16) * APAD + ks * 16, APAD);
#pragma unroll
            for (int nf = 0; nf < 2; nf++) {
                wmma::fragment<wmma::matrix_b, 16, 16, 16, __nv_bfloat16,
                               wmma::row_major> vhf, vlf;
                const int nc = wn2 * 32 + nf * 16;
                wmma::load_matrix_sync(vhf, Vhi + (ks * 16) * QPAD + nc, QPAD);
                wmma::load_matrix_sync(vlf, Vlo + (ks * 16) * QPAD + nc, QPAD);
                wmma::mma_sync(o2[nf], ah, vhf, o2[nf]);
                wmma::mma_sync(o2[nf], ah, vlf, o2[nf]);
                wmma::mma_sync(o2[nf], al, vhf, o2[nf]);
            }
        }
        __syncthreads();
    }

#pragma unroll
    for (int nf = 0; nf < 2; nf++)
        wmma::store_matrix_sync(
            &out[(size_t)(b * LL + row0 + wm * 16) * DQK + wn2 * 32 + nf * 16],
            o2[nf], DQK, wmma::mem_row_major);
}

// =====================================================================
// Launch: two-stream fork/join captured via events (unchanged).
// =====================================================================
static cudaStream_t g_s1 = nullptr;
static cudaEvent_t  g_evFork = nullptr, g_evJoin = nullptr;

extern "C" void kernel_launch(void* const* d_in, const int* in_sizes, int n_in,
                              void* d_out, int out_size) {
    const float* query = (const float*)d_in[0];
    const float* key_  = (const float*)d_in[1];
    const float* value = (const float*)d_in[2];
    const float* sf    = (const float*)d_in[3];
    const unsigned int* mask = (const unsigned int*)d_in[4];
    const float* Wq  = (const float*)d_in[5];
    const float* bq  = (const float*)d_in[6];
    const float* Wk  = (const float*)d_in[7];
    const float* bk  = (const float*)d_in[8];
    const float* Wv  = (const float*)d_in[9];
    const float* bv  = (const float*)d_in[10];
    const float* Wb1 = (const float*)d_in[11];
    const float* bb1 = (const float*)d_in[12];
    const float* Wb2 = (const float*)d_in[13];
    const float* bb2 = (const float*)d_in[14];
    float* out = (float*)d_out;

    (void)in_sizes; (void)n_in; (void)out_size;

    if (g_s1 == nullptr) {
        cudaStreamCreateWithFlags(&g_s1, cudaStreamNonBlocking);
        cudaEventCreateWithFlags(&g_evFork, cudaEventDisableTiming);
        cudaEventCreateWithFlags(&g_evJoin, cudaEventDisableTiming);
        cudaFuncSetAttribute(proj3_wmma,
                             cudaFuncAttributeMaxDynamicSharedMemorySize, PROJ_SMEM);
        cudaFuncSetAttribute(bias_wmma,
                             cudaFuncAttributeMaxDynamicSharedMemorySize, BW_SMEM);
        cudaFuncSetAttribute(attn_wmma,
                             cudaFuncAttributeMaxDynamicSharedMemorySize, ATTN_SMEM);
    }

    // fork: side chain mlp1 -> bias (independent of proj chain)
    cudaEventRecord(g_evFork, (cudaStream_t)0);
    cudaStreamWaitEvent(g_s1, g_evFork, 0);
    mlp1_kernel<<<512, 256, 0, g_s1>>>(sf, Wb1, bb1);
    bias_wmma<<<LLSQ / 128, 256, BW_SMEM, g_s1>>>(Wb2, bb2);
    cudaEventRecord(g_evJoin, g_s1);

    // main chain on capture-origin stream
    prep_w<<<dim3(256, 3), 256>>>(Wq, Wk, Wv);
    proj3_wmma<<<dim3(NB * LL / 64, 3), 256, PROJ_SMEM>>>(query, key_, value,
                                                          bq, bk, bv);

    // join, then attention
    cudaStreamWaitEvent((cudaStream_t)0, g_evJoin, 0);
    attn_wmma<<<dim3(LL / 32, NB), 256, ATTN_SMEM>>>(mask, out);
}

// round 16
// speedup vs baseline: 2.3798x; 1.0779x over previous
#include <cuda_runtime.h>
#include <cuda_bf16.h>
#include <mma.h>
#include <cstdint>

using namespace nvcuda;

#define NB   32      // batch
#define LL   512     // sequence length
#define DIN  512
#define DQK  128
#define DS   256
#define DMLP 128
#define LLSQ (LL*LL) // 262144

// ---------------- device scratch (static: allocation-free) ----------------
__device__ __nv_bfloat16 g_qb [NB * LL * DQK];   // bf16 q
__device__ __nv_bfloat16 g_kb [NB * LL * DQK];   // bf16 k
__device__ __nv_bfloat16 g_vhi[NB * LL * DQK];   // v hi
__device__ __nv_bfloat16 g_vlo[NB * LL * DQK];   // v lo
__device__ __nv_bfloat16 g_whi[3 * DIN * DQK];   // Wq|Wk|Wv hi
__device__ __nv_bfloat16 g_wlo[3 * DIN * DQK];   // Wq|Wk|Wv lo (only Wv used)
__device__ __nv_bfloat16 g_hhi[NB * DMLP];
__device__ __nv_bfloat16 g_hlo[NB * DMLP];
__device__ float g_bias[NB * LLSQ];              // 33.5 MB

__device__ __forceinline__ void split2(float x, float y,
                                       __nv_bfloat162& hi, __nv_bfloat162& lo) {
    __nv_bfloat16 hx = __float2bfloat16(x);
    __nv_bfloat16 hy = __float2bfloat16(y);
    hi = __halves2bfloat162(hx, hy);
    lo = __halves2bfloat162(__float2bfloat16(x - __bfloat162float(hx)),
                            __float2bfloat16(y - __bfloat162float(hy)));
}

// =====================================================================
// prep_w: split Wq/Wk/Wv fp32 -> bf16 hi (all) + lo (v only).
// =====================================================================
__global__ __launch_bounds__(256) void prep_w(const float* __restrict__ Wq,
                                              const float* __restrict__ Wk,
                                              const float* __restrict__ Wv) {
    const float* src = (blockIdx.y == 0) ? Wq : (blockIdx.y == 1) ? Wk : Wv;
    int i = blockIdx.x * 256 + threadIdx.x;          // 0..65535
    float v = src[i];
    __nv_bfloat16 h = __float2bfloat16(v);
    g_whi[blockIdx.y * (DIN * DQK) + i] = h;
    if (blockIdx.y == 2)
        g_wlo[blockIdx.y * (DIN * DQK) + i] =
            __float2bfloat16(v - __bfloat162float(h));
}

// =====================================================================
// WMMA bf16 projection, double-buffered, precision-tiered:
//   by<2 (q,k): plain bf16 single product (outputs are bf16 anyway)
//   by==2 (v) : full hi/lo 3-product split (feeds dominant bias@V path)
// Buffer layout per buffer (27648 B): Ahi@0 Alo@5120 Bhi@10240 Blo@18944
// =====================================================================
#define PAD_A 40
#define PAD_B 136
#define PAD_C 132
#define PROJ_BUF 27648
#define PROJ_SMEM (2 * PROJ_BUF)

__global__ __launch_bounds__(256, 2) void proj3_wmma(
        const float* __restrict__ Xq, const float* __restrict__ Xk,
        const float* __restrict__ Xv,
        const float* __restrict__ bq, const float* __restrict__ bk,
        const float* __restrict__ bv) {
    extern __shared__ char sm[];
    float* Cs = (float*)sm;                             // epilogue union

    const int by = blockIdx.y;
    const bool full = (by == 2);
    const float* X  = (by == 0) ? Xq : (by == 1) ? Xk : Xv;
    const float* Bb = (by == 0) ? bq : (by == 1) ? bk : bv;
    const __nv_bfloat16* whi = g_whi + by * (DIN * DQK);
    const __nv_bfloat16* wlo = g_wlo + by * (DIN * DQK);

    const int t = threadIdx.x;
    const int warp = t >> 5;
    const int wm = warp & 3;
    const int wn = warp >> 2;
    const int row0 = blockIdx.x * 64;

    wmma::fragment<wmma::accumulator, 16, 16, 16, float> c[4];
#pragma unroll
    for (int nf = 0; nf < 4; nf++) wmma::fill_fragment(c[nf], 0.0f);

    float4 xa[2];
    uint4 wh[2], wl[2];

    // ---- helpers as lambdas (block-uniform `full` branch)
    auto ldg_chunk = [&](int k0) {
#pragma unroll
        for (int j = 0; j < 2; j++) {
            int idx = t + j * 256;
            int r = idx >> 3, c4 = (idx & 7) * 4;
            xa[j] = *(const float4*)&X[(size_t)(row0 + r) * DIN + k0 + c4];
        }
#pragma unroll
        for (int j = 0; j < 2; j++) {
            int idx = t + j * 256;
            int k = idx >> 4, c8 = (idx & 15) * 8;
            wh[j] = *(const uint4*)&whi[(size_t)(k0 + k) * DQK + c8];
            if (full) wl[j] = *(const uint4*)&wlo[(size_t)(k0 + k) * DQK + c8];
        }
    };
    auto sts_chunk = [&](int buf) {
        __nv_bfloat16* Ahi = (__nv_bfloat16*)(sm + buf + 0);
        __nv_bfloat16* Alo = (__nv_bfloat16*)(sm + buf + 5120);
        __nv_bfloat16* Bhi = (__nv_bfloat16*)(sm + buf + 10240);
        __nv_bfloat16* Blo = (__nv_bfloat16*)(sm + buf + 18944);
#pragma unroll
        for (int j = 0; j < 2; j++) {
            int idx = t + j * 256;
            int r = idx >> 3, c4 = (idx & 7) * 4;
            if (full) {
                __nv_bfloat162 h0, l0, h1, l1;
                split2(xa[j].x, xa[j].y, h0, l0);
                split2(xa[j].z, xa[j].w, h1, l1);
                *(__nv_bfloat162*)&Ahi[r * PAD_A + c4]     = h0;
                *(__nv_bfloat162*)&Ahi[r * PAD_A + c4 + 2] = h1;
                *(__nv_bfloat162*)&Alo[r * PAD_A + c4]     = l0;
                *(__nv_bfloat162*)&Alo[r * PAD_A + c4 + 2] = l1;
            } else {
                *(__nv_bfloat162*)&Ahi[r * PAD_A + c4] =
                    __halves2bfloat162(__float2bfloat16(xa[j].x),
                                       __float2bfloat16(xa[j].y));
                *(__nv_bfloat162*)&Ahi[r * PAD_A + c4 + 2] =
                    __halves2bfloat162(__float2bfloat16(xa[j].z),
                                       __float2bfloat16(xa[j].w));
            }
        }
#pragma unroll
        for (int j = 0; j < 2; j++) {
            int idx = t + j * 256;
            int k = idx >> 4, c8 = (idx & 15) * 8;
            *(uint4*)&Bhi[k * PAD_B + c8] = wh[j];
            if (full) *(uint4*)&Blo[k * PAD_B + c8] = wl[j];
        }
    };
    auto mma_chunk = [&](int buf) {
        __nv_bfloat16* Ahi = (__nv_bfloat16*)(sm + buf + 0);
        __nv_bfloat16* Alo = (__nv_bfloat16*)(sm + buf + 5120);
        __nv_bfloat16* Bhi = (__nv_bfloat16*)(sm + buf + 10240);
        __nv_bfloat16* Blo = (__nv_bfloat16*)(sm + buf + 18944);
#pragma unroll
        for (int ks = 0; ks < 32; ks += 16) {
            wmma::fragment<wmma::matrix_a, 16, 16, 16, __nv_bfloat16,
                           wmma::row_major> ah, al;
            wmma::load_matrix_sync(ah, Ahi + (wm * 16) * PAD_A + ks, PAD_A);
            if (full)
                wmma::load_matrix_sync(al, Alo + (wm * 16) * PAD_A + ks, PAD_A);
#pragma unroll
            for (int nf = 0; nf < 4; nf++) {
                wmma::fragment<wmma::matrix_b, 16, 16, 16, __nv_bfloat16,
                               wmma::row_major> bh, bl;
                const int nc = wn * 64 + nf * 16;
                wmma::load_matrix_sync(bh, Bhi + ks * PAD_B + nc, PAD_B);
                wmma::mma_sync(c[nf], ah, bh, c[nf]);
                if (full) {
                    wmma::load_matrix_sync(bl, Blo + ks * PAD_B + nc, PAD_B);
                    wmma::mma_sync(c[nf], ah, bl, c[nf]);
                    wmma::mma_sync(c[nf], al, bh, c[nf]);
                }
            }
        }
    };

    // ---- prologue: chunk 0 -> buf0
    ldg_chunk(0);
    sts_chunk(0);
    __syncthreads();

    // ---- main loop: single sync per chunk
#pragma unroll 2
    for (int kc = 0; kc < 16; kc++) {
        const int cur = (kc & 1) * PROJ_BUF;
        const int nxt = ((kc + 1) & 1) * PROJ_BUF;
        if (kc < 15) ldg_chunk((kc + 1) * 32);
        mma_chunk(cur);
        if (kc < 15) sts_chunk(nxt);
        __syncthreads();
    }

    // ---- epilogue through smem: +bias, bf16 outputs
#pragma unroll
    for (int nf = 0; nf < 4; nf++)
        wmma::store_matrix_sync(Cs + (wm * 16) * PAD_C + wn * 64 + nf * 16,
                                c[nf], PAD_C, wmma::mem_row_major);
    __syncthreads();

#pragma unroll
    for (int j = 0; j < 8; j++) {
        int idx = t + j * 256;
        int r = idx >> 5, c4 = (idx & 31) * 4;
        float4 v = *(float4*)&Cs[r * PAD_C + c4];
        float4 bvv = *(const float4*)&Bb[c4];
        v.x += bvv.x; v.y += bvv.y; v.z += bvv.z; v.w += bvv.w;
        size_t o = (size_t)(row0 + r) * DQK + c4;
        if (full) {
            __nv_bfloat162 h0, l0, h1, l1;
            split2(v.x, v.y, h0, l0);
            split2(v.z, v.w, h1, l1);
            *(__nv_bfloat162*)&g_vhi[o]     = h0;
            *(__nv_bfloat162*)&g_vhi[o + 2] = h1;
            *(__nv_bfloat162*)&g_vlo[o]     = l0;
            *(__nv_bfloat162*)&g_vlo[o + 2] = l1;
        } else {
            __nv_bfloat16* Yb = (by == 0) ? g_qb : g_kb;
            *(__nv_bfloat162*)&Yb[o] =
                __halves2bfloat162(__float2bfloat16(v.x), __float2bfloat16(v.y));
            *(__nv_bfloat162*)&Yb[o + 2] =
                __halves2bfloat162(__float2bfloat16(v.z), __float2bfloat16(v.w));
        }
    }
}

// =====================================================================
// Bias MLP stage 1 (unchanged)
// =====================================================================
__global__ __launch_bounds__(256) void mlp1_kernel(const float* __restrict__ sf,
                                                   const float* __restrict__ Wb1,
                                                   const float* __restrict__ bb1) {
    const int gw   = blockIdx.x * 8 + (threadIdx.x >> 5);
    const int lane = threadIdx.x & 31;
    const int b    = gw >> 7;
    const int n    = gw & 127;

    float s = 0.f;
#pragma unroll
    for (int kk = 0; kk < 8; kk++) {
        int k = kk * 32 + lane;
        s = fmaf(sf[b * DS + k], Wb1[(size_t)k * DMLP + n], s);
    }
#pragma unroll
    for (int o = 16; o > 0; o >>= 1) s += __shfl_xor_sync(0xffffffffu, s, o);
    if (lane == 0) {
        float val = fmaxf(s + bb1[n], 0.f);
        __nv_bfloat16 h = __float2bfloat16(val);
        g_hhi[b * DMLP + n] = h;
        g_hlo[b * DMLP + n] = __float2bfloat16(val - __bfloat162float(h));
    }
}

// =====================================================================
// Bias MLP stage 2 via WMMA split (unchanged)
// =====================================================================
#define BW_WHI 0
#define BW_WLO 34816
#define BW_AHH 69632
#define BW_AHL 78336
#define BW_SMEM 87040
#define HPAD 136

__global__ __launch_bounds__(256, 2) void bias_wmma(const float* __restrict__ Wb2,
                                                    const float* __restrict__ bb2) {
    extern __shared__ char sm[];
    __nv_bfloat16* Whi = (__nv_bfloat16*)(sm + BW_WHI);
    __nv_bfloat16* Wlo = (__nv_bfloat16*)(sm + BW_WLO);
    __nv_bfloat16* Ahh = (__nv_bfloat16*)(sm + BW_AHH);
    __nv_bfloat16* Ahl = (__nv_bfloat16*)(sm + BW_AHL);
    float*         Cs  = (float*)(sm + BW_AHH);          // union, after MMA

    const int t = threadIdx.x;
    const int warp = t >> 5;
    const int wm = warp & 1;
    const int wn = warp >> 1;
    const int n0 = blockIdx.x * 128;

#pragma unroll
    for (int j = 0; j < 2; j++) {
        int idx = t + j * 256;
        int r = idx >> 4, c8 = (idx & 15) * 8;
        *(uint4*)&Ahh[r * HPAD + c8] = *(const uint4*)&g_hhi[r * DMLP + c8];
        *(uint4*)&Ahl[r * HPAD + c8] = *(const uint4*)&g_hlo[r * DMLP + c8];
    }
#pragma unroll
    for (int j = 0; j < 16; j++) {
        int idx = t + j * 256;
        int k = idx >> 5, n4 = (idx & 31) * 4;
        float4 w = *(const float4*)&Wb2[(size_t)k * LLSQ + n0 + n4];
        __nv_bfloat162 h0, l0, h1, l1;
        split2(w.x, w.y, h0, l0);
        split2(w.z, w.w, h1, l1);
        *(__nv_bfloat162*)&Whi[k * HPAD + n4]     = h0;
        *(__nv_bfloat162*)&Whi[k * HPAD + n4 + 2] = h1;
        *(__nv_bfloat162*)&Wlo[k * HPAD + n4]     = l0;
        *(__nv_bfloat162*)&Wlo[k * HPAD + n4 + 2] = l1;
    }
    __syncthreads();

    wmma::fragment<wmma::accumulator, 16, 16, 16, float> c2[2];
    wmma::fill_fragment(c2[0], 0.0f);
    wmma::fill_fragment(c2[1], 0.0f);

#pragma unroll
    for (int ks = 0; ks < 8; ks++) {
        wmma::fragment<wmma::matrix_a, 16, 16, 16, __nv_bfloat16,
                       wmma::row_major> ah, al;
        wmma::load_matrix_sync(ah, Ahh + (wm * 16) * HPAD + ks * 16, HPAD);
        wmma::load_matrix_sync(al, Ahl + (wm * 16) * HPAD + ks * 16, HPAD);
#pragma unroll
        for (int nf = 0; nf < 2; nf++) {
            wmma::fragment<wmma::matrix_b, 16, 16, 16, __nv_bfloat16,
                           wmma::row_major> bh, bl;
            const int nc = wn * 32 + nf * 16;
            wmma::load_matrix_sync(bh, Whi + (ks * 16) * HPAD + nc, HPAD);
            wmma::load_matrix_sync(bl, Wlo + (ks * 16) * HPAD + nc, HPAD);
            wmma::mma_sync(c2[nf], ah, bh, c2[nf]);
            wmma::mma_sync(c2[nf], ah, bl, c2[nf]);
            wmma::mma_sync(c2[nf], al, bh, c2[nf]);
        }
    }

    __syncthreads();
#pragma unroll
    for (int nf = 0; nf < 2; nf++)
        wmma::store_matrix_sync(Cs + (wm * 16) * HPAD + wn * 32 + nf * 16,
                                c2[nf], HPAD, wmma::mem_row_major);
    __syncthreads();

#pragma unroll
    for (int j = 0; j < 4; j++) {
        int idx = t + j * 256;
        int r = idx >> 5, c4 = (idx & 31) * 4;
        float4 v = *(float4*)&Cs[r * HPAD + c4];
        float4 b2 = *(const float4*)&bb2[n0 + c4];
        v.x += b2.x; v.y += b2.y; v.z += b2.z; v.w += b2.w;
        *(float4*)&g_bias[(size_t)r * LLSQ + n0 + c4] = v;
    }
}

// =====================================================================
// WMMA fused attention with register prefetch on K/V tiles (unchanged).
// =====================================================================
#define SSPAD 520
#define AT_KV   66560
#define AT_VLO  83968
#define AT_ABH  101376
#define AT_ABL  105984
#define ATTN_SMEM 110592
#define QPAD 136
#define APAD 72

__global__ __launch_bounds__(256, 2) void attn_wmma(const unsigned int* __restrict__ mask,
                                                    float* __restrict__ out) {
    extern __shared__ char sm[];
    float*         Ss   = (float*)sm;                     // [32][520]
    __nv_bfloat16* Qsm  = (__nv_bfloat16*)(sm + AT_KV);   // [32][136]
    __nv_bfloat16* Ksm  = (__nv_bfloat16*)(sm + AT_KV);   // [64][136]
    __nv_bfloat16* Vhi  = (__nv_bfloat16*)(sm + AT_KV);   // [64][136]
    __nv_bfloat16* Vlo  = (__nv_bfloat16*)(sm + AT_VLO);  // [64][136]
    __nv_bfloat16* Abhi = (__nv_bfloat16*)(sm + AT_ABH);  // [32][72]
    __nv_bfloat16* Ablo = (__nv_bfloat16*)(sm + AT_ABL);  // [32][72]

    const int t    = threadIdx.x;
    const int lane = t & 31;
    const int warp = t >> 5;
    const int b    = blockIdx.y;
    const int row0 = blockIdx.x * 32;

    const __nv_bfloat16* __restrict__ qb = g_qb + (size_t)(b * LL + row0) * DQK;
    const __nv_bfloat16* __restrict__ kb = g_kb + (size_t)b * LL * DQK;
    const __nv_bfloat16* __restrict__ vh = g_vhi + (size_t)b * LL * DQK;
    const __nv_bfloat16* __restrict__ vl = g_vlo + (size_t)b * LL * DQK;

#pragma unroll
    for (int j = 0; j < 2; j++) {
        int idx = t + j * 256;
        int r = idx >> 4, c8 = (idx & 15) * 8;
        *(uint4*)&Qsm[r * QPAD + c8] = *(const uint4*)&qb[r * DQK + c8];
    }
    __syncthreads();

    const int wm = warp & 1;
    const int wn = warp >> 1;
    wmma::fragment<wmma::matrix_a, 16, 16, 16, __nv_bfloat16,
                   wmma::row_major> qa[8];
#pragma unroll
    for (int ks = 0; ks < 8; ks++)
        wmma::load_matrix_sync(qa[ks], Qsm + (wm * 16) * QPAD + ks * 16, QPAD);

    uint4 kreg[4];
#pragma unroll
    for (int j = 0; j < 4; j++) {
        int idx = t + j * 256;
        int r = idx >> 4, c8 = (idx & 15) * 8;
        kreg[j] = *(const uint4*)&kb[(size_t)r * DQK + c8];
    }
    __syncthreads();

    for (int ct = 0; ct < 8; ct++) {
#pragma unroll
        for (int j = 0; j < 4; j++) {
            int idx = t + j * 256;
            int r = idx >> 4, c8 = (idx & 15) * 8;
            *(uint4*)&Ksm[r * QPAD + c8] = kreg[j];
        }
        __syncthreads();
        if (ct < 7) {
#pragma unroll
            for (int j = 0; j < 4; j++) {
                int idx = t + j * 256;
                int r = idx >> 4, c8 = (idx & 15) * 8;
                kreg[j] = *(const uint4*)&kb[(size_t)((ct + 1) * 64 + r) * DQK + c8];
            }
        }

        wmma::fragment<wmma::accumulator, 16, 16, 16, float> c1;
        wmma::fill_fragment(c1, 0.0f);
#pragma unroll
        for (int ks = 0; ks < 8; ks++) {
            wmma::fragment<wmma::matrix_b, 16, 16, 16, __nv_bfloat16,
                           wmma::col_major> kf;
            wmma::load_matrix_sync(kf, Ksm + (wn * 16) * QPAD + ks * 16, QPAD);
            wmma::mma_sync(c1, qa[ks], kf, c1);
        }
        wmma::store_matrix_sync(Ss + (wm * 16) * SSPAD + ct * 64 + wn * 16,
                                c1, SSPAD, wmma::mem_row_major);
        __syncthreads();
    }

    const float inv_scale = 0.08838834764831845f;   // 1/sqrt(128)
#pragma unroll
    for (int j = 0; j < 4; j++) {
        const int r = warp * 4 + j;
        const unsigned int* mrow = mask + (size_t)(b * LL + row0 + r) * LL;
        float mx = -1e30f;
        for (int m = lane; m < LL; m += 32) {
            float s = (mrow[m] != 0u) ? 1e-9f : Ss[r * SSPAD + m] * inv_scale;
            Ss[r * SSPAD + m] = s;
            mx = fmaxf(mx, s);
        }
#pragma unroll
        for (int o = 16; o > 0; o >>= 1) mx = fmaxf(mx, __shfl_xor_sync(0xffffffffu, mx, o));
        float sum = 0.f;
        for (int m = lane; m < LL; m += 32) {
            float e = __expf(Ss[r * SSPAD + m] - mx);
            Ss[r * SSPAD + m] = e;
            sum += e;
        }
#pragma unroll
        for (int o = 16; o > 0; o >>= 1) sum += __shfl_xor_sync(0xffffffffu, sum, o);
        const float inv = 1.0f / sum;
        const float* __restrict__ brow = g_bias + (size_t)(b * LL + row0 + r) * LL;
        for (int m = lane; m < LL; m += 32)
            Ss[r * SSPAD + m] = Ss[r * SSPAD + m] * inv + brow[m];
    }

    uint4 vhreg[4], vlreg[4];
#pragma unroll
    for (int j = 0; j < 4; j++) {
        int idx = t + j * 256;
        int r = idx >> 4, c8 = (idx & 15) * 8;
        vhreg[j] = *(const uint4*)&vh[(size_t)r * DQK + c8];
        vlreg[j] = *(const uint4*)&vl[(size_t)r * DQK + c8];
    }
    __syncthreads();

    const int wn2 = warp >> 1;
    wmma::fragment<wmma::accumulator, 16, 16, 16, float> o2[2];
    wmma::fill_fragment(o2[0], 0.0f);
    wmma::fill_fragment(o2[1], 0.0f);

    for (int mt = 0; mt < 8; mt++) {
#pragma unroll
        for (int j = 0; j < 4; j++) {
            int idx = t + j * 256;
            int r = idx >> 4, c8 = (idx & 15) * 8;
            *(uint4*)&Vhi[r * QPAD + c8] = vhreg[j];
            *(uint4*)&Vlo[r * QPAD + c8] = vlreg[j];
        }
#pragma unroll
        for (int j = 0; j < 4; j++) {
            int idx = t + j * 256;
            int r = idx >> 5, c2 = (idx & 31) * 2;
            float2 s2 = *(float2*)&Ss[r * SSPAD + mt * 64 + c2];
            __nv_bfloat162 hi, lo;
            split2(s2.x, s2.y, hi, lo);
            *(__nv_bfloat162*)&Abhi[r * APAD + c2] = hi;
            *(__nv_bfloat162*)&Ablo[r * APAD + c2] = lo;
        }
        __syncthreads();
        if (mt < 7) {
#pragma unroll
            for (int j = 0; j < 4; j++) {
                int idx = t + j * 256;
                int r = idx >> 4, c8 = (idx & 15) * 8;
                size_t o = (size_t)((mt + 1) * 64 + r) * DQK + c8;
                vhreg[j] = *(const uint4*)&vh[o];
                vlreg[j] = *(const uint4*)&vl[o];
            }
        }

#pragma unroll
        for (int ks = 0; ks < 4; ks++) {
            wmma::fragment<wmma::matrix_a, 16, 16, 16, __nv_bfloat16,
                           wmma::row_major> ah, al;
            wmma::load_matrix_sync(ah, Abhi + (wm * 16) * APAD + ks * 16, APAD);
            wmma::load_matrix_sync(al, Ablo + (wm * 16) * APAD + ks * 16, APAD);
#pragma unroll
            for (int nf = 0; nf < 2; nf++) {
                wmma::fragment<wmma::matrix_b, 16, 16, 16, __nv_bfloat16,
                               wmma::row_major> vhf, vlf;
                const int nc = wn2 * 32 + nf * 16;
                wmma::load_matrix_sync(vhf, Vhi + (ks * 16) * QPAD + nc, QPAD);
                wmma::load_matrix_sync(vlf, Vlo + (ks * 16) * QPAD + nc, QPAD);
                wmma::mma_sync(o2[nf], ah, vhf, o2[nf]);
                wmma::mma_sync(o2[nf], ah, vlf, o2[nf]);
                wmma::mma_sync(o2[nf], al, vhf, o2[nf]);
            }
        }
        __syncthreads();
    }

#pragma unroll
    for (int nf = 0; nf < 2; nf++)
        wmma::store_matrix_sync(
            &out[(size_t)(b * LL + row0 + wm * 16) * DQK + wn2 * 32 + nf * 16],
            o2[nf], DQK, wmma::mem_row_major);
}

// =====================================================================
// Launch: two-stream fork/join captured via events (unchanged).
// =====================================================================
static cudaStream_t g_s1 = nullptr;
static cudaEvent_t  g_evFork = nullptr, g_evJoin = nullptr;

extern "C" void kernel_launch(void* const* d_in, const int* in_sizes, int n_in,
                              void* d_out, int out_size) {
    const float* query = (const float*)d_in[0];
    const float* key_  = (const float*)d_in[1];
    const float* value = (const float*)d_in[2];
    const float* sf    = (const float*)d_in[3];
    const unsigned int* mask = (const unsigned int*)d_in[4];
    const float* Wq  = (const float*)d_in[5];
    const float* bq  = (const float*)d_in[6];
    const float* Wk  = (const float*)d_in[7];
    const float* bk  = (const float*)d_in[8];
    const float* Wv  = (const float*)d_in[9];
    const float* bv  = (const float*)d_in[10];
    const float* Wb1 = (const float*)d_in[11];
    const float* bb1 = (const float*)d_in[12];
    const float* Wb2 = (const float*)d_in[13];
    const float* bb2 = (const float*)d_in[14];
    float* out = (float*)d_out;

    (void)in_sizes; (void)n_in; (void)out_size;

    if (g_s1 == nullptr) {
        cudaStreamCreateWithFlags(&g_s1, cudaStreamNonBlocking);
        cudaEventCreateWithFlags(&g_evFork, cudaEventDisableTiming);
        cudaEventCreateWithFlags(&g_evJoin, cudaEventDisableTiming);
        cudaFuncSetAttribute(proj3_wmma,
                             cudaFuncAttributeMaxDynamicSharedMemorySize, PROJ_SMEM);
        cudaFuncSetAttribute(bias_wmma,
                             cudaFuncAttributeMaxDynamicSharedMemorySize, BW_SMEM);
        cudaFuncSetAttribute(attn_wmma,
                             cudaFuncAttributeMaxDynamicSharedMemorySize, ATTN_SMEM);
    }

    // fork: side chain mlp1 -> bias (independent of proj chain)
    cudaEventRecord(g_evFork, (cudaStream_t)0);
    cudaStreamWaitEvent(g_s1, g_evFork, 0);
    mlp1_kernel<<<512, 256, 0, g_s1>>>(sf, Wb1, bb1);
    bias_wmma<<<LLSQ / 128, 256, BW_SMEM, g_s1>>>(Wb2, bb2);
    cudaEventRecord(g_evJoin, g_s1);

    // main chain on capture-origin stream
    prep_w<<<dim3(256, 3), 256>>>(Wq, Wk, Wv);
    proj3_wmma<<<dim3(NB * LL / 64, 3), 256, PROJ_SMEM>>>(query, key_, value,
                                                          bq, bk, bv);

    // join, then attention
    cudaStreamWaitEvent((cudaStream_t)0, g_evJoin, 0);
    attn_wmma<<<dim3(LL / 32, NB), 256, ATTN_SMEM>>>(mask, out);
}

// round 17
// speedup vs baseline: 2.5286x; 1.0625x over previous
#include <cuda_runtime.h>
#include <cuda_bf16.h>
#include <mma.h>
#include <cstdint>

using namespace nvcuda;

#define NB   32      // batch
#define LL   512     // sequence length
#define DIN  512
#define DQK  128
#define DS   256
#define DMLP 128
#define LLSQ (LL*LL) // 262144

// ---------------- device scratch (static: allocation-free) ----------------
__device__ __nv_bfloat16 g_qb [NB * LL * DQK];   // bf16 q
__device__ __nv_bfloat16 g_kb [NB * LL * DQK];   // bf16 k
__device__ __nv_bfloat16 g_vhi[NB * LL * DQK];   // v hi
__device__ __nv_bfloat16 g_vlo[NB * LL * DQK];   // v lo
__device__ __nv_bfloat16 g_whi[3 * DIN * DQK];   // Wq|Wk|Wv hi
__device__ __nv_bfloat16 g_wlo[3 * DIN * DQK];   // Wq|Wk|Wv lo (only Wv used)
__device__ __nv_bfloat16 g_hhi[NB * DMLP];
__device__ __nv_bfloat16 g_hlo[NB * DMLP];
__device__ float g_bias[NB * LLSQ];              // 33.5 MB

__device__ __forceinline__ void split2(float x, float y,
                                       __nv_bfloat162& hi, __nv_bfloat162& lo) {
    __nv_bfloat16 hx = __float2bfloat16(x);
    __nv_bfloat16 hy = __float2bfloat16(y);
    hi = __halves2bfloat162(hx, hy);
    lo = __halves2bfloat162(__float2bfloat16(x - __bfloat162float(hx)),
                            __float2bfloat16(y - __bfloat162float(hy)));
}

// =====================================================================
// prep_w: split Wq/Wk/Wv fp32 -> bf16 hi (all) + lo (v only).
// =====================================================================
__global__ __launch_bounds__(256) void prep_w(const float* __restrict__ Wq,
                                              const float* __restrict__ Wk,
                                              const float* __restrict__ Wv) {
    const float* src = (blockIdx.y == 0) ? Wq : (blockIdx.y == 1) ? Wk : Wv;
    int i = blockIdx.x * 256 + threadIdx.x;          // 0..65535
    float v = src[i];
    __nv_bfloat16 h = __float2bfloat16(v);
    g_whi[blockIdx.y * (DIN * DQK) + i] = h;
    if (blockIdx.y == 2)
        g_wlo[blockIdx.y * (DIN * DQK) + i] =
            __float2bfloat16(v - __bfloat162float(h));
}

// =====================================================================
// WMMA bf16 projection, 128-row CTA tile, warp tile 32x64.
//   by<2 (q,k): plain bf16 single product
//   by==2 (v) : full hi/lo 3-product split
// grid (128, 3), 256 threads, 8 warps = 4(M) x 2(N).
// smem (single buffer): Ahi[128][40]@0 (10240) | Alo@10240 (10240)
//   Bhi[32][136]@20480 (8704) | Blo@29184 (8704)  -> 37888
// epilogue union: Cs f32 [128][132] = 67584  -> PROJ_SMEM 67584
// =====================================================================
#define PAD_A 40
#define PAD_B 136
#define PAD_C 132
#define P_ALO 10240
#define P_BHI 20480
#define P_BLO 29184
#define PROJ_SMEM 67584

__global__ __launch_bounds__(256, 2) void proj3_wmma(
        const float* __restrict__ Xq, const float* __restrict__ Xk,
        const float* __restrict__ Xv,
        const float* __restrict__ bq, const float* __restrict__ bk,
        const float* __restrict__ bv) {
    extern __shared__ char sm[];
    __nv_bfloat16* Ahi = (__nv_bfloat16*)(sm + 0);       // [128][40]
    __nv_bfloat16* Alo = (__nv_bfloat16*)(sm + P_ALO);   // [128][40]
    __nv_bfloat16* Bhi = (__nv_bfloat16*)(sm + P_BHI);   // [32][136]
    __nv_bfloat16* Blo = (__nv_bfloat16*)(sm + P_BLO);   // [32][136]
    float* Cs = (float*)sm;                              // epilogue union

    const int by = blockIdx.y;
    const bool full = (by == 2);
    const float* X  = (by == 0) ? Xq : (by == 1) ? Xk : Xv;
    const float* Bb = (by == 0) ? bq : (by == 1) ? bk : bv;
    const __nv_bfloat16* whi = g_whi + by * (DIN * DQK);
    const __nv_bfloat16* wlo = g_wlo + by * (DIN * DQK);

    const int t = threadIdx.x;
    const int warp = t >> 5;
    const int wm = warp & 3;        // M offset wm*32
    const int wn = warp >> 2;       // N offset wn*64
    const int row0 = blockIdx.x * 128;

    wmma::fragment<wmma::accumulator, 16, 16, 16, float> c[2][4];
#pragma unroll
    for (int ms = 0; ms < 2; ms++)
#pragma unroll
        for (int nf = 0; nf < 4; nf++) wmma::fill_fragment(c[ms][nf], 0.0f);

    float4 xa[4];
    uint4 wh[2], wl[2];

    for (int kc = 0; kc < 16; kc++) {
        const int k0 = kc * 32;

        // ---- LDG chunk (overlaps previous chunk's MMA)
#pragma unroll
        for (int j = 0; j < 4; j++) {
            int idx = t + j * 256;              // 0..1023 float4
            int r = idx >> 3, c4 = (idx & 7) * 4;
            xa[j] = *(const float4*)&X[(size_t)(row0 + r) * DIN + k0 + c4];
        }
#pragma unroll
        for (int j = 0; j < 2; j++) {
            int idx = t + j * 256;              // 0..511 uint4
            int k = idx >> 4, c8 = (idx & 15) * 8;
            wh[j] = *(const uint4*)&whi[(size_t)(k0 + k) * DQK + c8];
            if (full) wl[j] = *(const uint4*)&wlo[(size_t)(k0 + k) * DQK + c8];
        }

        __syncthreads();   // previous MMA reads done before overwrite

        // ---- STS (split A; copy/split W)
#pragma unroll
        for (int j = 0; j < 4; j++) {
            int idx = t + j * 256;
            int r = idx >> 3, c4 = (idx & 7) * 4;
            if (full) {
                __nv_bfloat162 h0, l0, h1, l1;
                split2(xa[j].x, xa[j].y, h0, l0);
                split2(xa[j].z, xa[j].w, h1, l1);
                *(__nv_bfloat162*)&Ahi[r * PAD_A + c4]     = h0;
                *(__nv_bfloat162*)&Ahi[r * PAD_A + c4 + 2] = h1;
                *(__nv_bfloat162*)&Alo[r * PAD_A + c4]     = l0;
                *(__nv_bfloat162*)&Alo[r * PAD_A + c4 + 2] = l1;
            } else {
                *(__nv_bfloat162*)&Ahi[r * PAD_A + c4] =
                    __halves2bfloat162(__float2bfloat16(xa[j].x),
                                       __float2bfloat16(xa[j].y));
                *(__nv_bfloat162*)&Ahi[r * PAD_A + c4 + 2] =
                    __halves2bfloat162(__float2bfloat16(xa[j].z),
                                       __float2bfloat16(xa[j].w));
            }
        }
#pragma unroll
        for (int j = 0; j < 2; j++) {
            int idx = t + j * 256;
            int k = idx >> 4, c8 = (idx & 15) * 8;
            *(uint4*)&Bhi[k * PAD_B + c8] = wh[j];
            if (full) *(uint4*)&Blo[k * PAD_B + c8] = wl[j];
        }
        __syncthreads();

        // ---- MMA: 2 k-steps; warp tile 32x64
#pragma unroll
        for (int ks = 0; ks < 32; ks += 16) {
            wmma::fragment<wmma::matrix_a, 16, 16, 16, __nv_bfloat16,
                           wmma::row_major> ah[2], al[2];
#pragma unroll
            for (int ms = 0; ms < 2; ms++) {
                const int ar = wm * 32 + ms * 16;
                wmma::load_matrix_sync(ah[ms], Ahi + ar * PAD_A + ks, PAD_A);
                if (full)
                    wmma::load_matrix_sync(al[ms], Alo + ar * PAD_A + ks, PAD_A);
            }
#pragma unroll
            for (int nf = 0; nf < 4; nf++) {
                wmma::fragment<wmma::matrix_b, 16, 16, 16, __nv_bfloat16,
                               wmma::row_major> bh, bl;
                const int nc = wn * 64 + nf * 16;
                wmma::load_matrix_sync(bh, Bhi + ks * PAD_B + nc, PAD_B);
                if (full) wmma::load_matrix_sync(bl, Blo + ks * PAD_B + nc, PAD_B);
#pragma unroll
                for (int ms = 0; ms < 2; ms++) {
                    wmma::mma_sync(c[ms][nf], ah[ms], bh, c[ms][nf]);
                    if (full) {
                        wmma::mma_sync(c[ms][nf], ah[ms], bl, c[ms][nf]);
                        wmma::mma_sync(c[ms][nf], al[ms], bh, c[ms][nf]);
                    }
                }
            }
        }
    }

    // ---- epilogue through smem: +bias, bf16 outputs
    __syncthreads();
#pragma unroll
    for (int ms = 0; ms < 2; ms++)
#pragma unroll
        for (int nf = 0; nf < 4; nf++)
            wmma::store_matrix_sync(
                Cs + (wm * 32 + ms * 16) * PAD_C + wn * 64 + nf * 16,
                c[ms][nf], PAD_C, wmma::mem_row_major);
    __syncthreads();

#pragma unroll
    for (int j = 0; j < 16; j++) {
        int idx = t + j * 256;                  // 0..4095 float4
        int r = idx >> 5, c4 = (idx & 31) * 4;
        float4 v = *(float4*)&Cs[r * PAD_C + c4];
        float4 bvv = *(const float4*)&Bb[c4];
        v.x += bvv.x; v.y += bvv.y; v.z += bvv.z; v.w += bvv.w;
        size_t o = (size_t)(row0 + r) * DQK + c4;
        if (full) {
            __nv_bfloat162 h0, l0, h1, l1;
            split2(v.x, v.y, h0, l0);
            split2(v.z, v.w, h1, l1);
            *(__nv_bfloat162*)&g_vhi[o]     = h0;
            *(__nv_bfloat162*)&g_vhi[o + 2] = h1;
            *(__nv_bfloat162*)&g_vlo[o]     = l0;
            *(__nv_bfloat162*)&g_vlo[o + 2] = l1;
        } else {
            __nv_bfloat16* Yb = (by == 0) ? g_qb : g_kb;
            *(__nv_bfloat162*)&Yb[o] =
                __halves2bfloat162(__float2bfloat16(v.x), __float2bfloat16(v.y));
            *(__nv_bfloat162*)&Yb[o + 2] =
                __halves2bfloat162(__float2bfloat16(v.z), __float2bfloat16(v.w));
        }
    }
}

// =====================================================================
// Bias MLP stage 1 (unchanged)
// =====================================================================
__global__ __launch_bounds__(256) void mlp1_kernel(const float* __restrict__ sf,
                                                   const float* __restrict__ Wb1,
                                                   const float* __restrict__ bb1) {
    const int gw   = blockIdx.x * 8 + (threadIdx.x >> 5);
    const int lane = threadIdx.x & 31;
    const int b    = gw >> 7;
    const int n    = gw & 127;

    float s = 0.f;
#pragma unroll
    for (int kk = 0; kk < 8; kk++) {
        int k = kk * 32 + lane;
        s = fmaf(sf[b * DS + k], Wb1[(size_t)k * DMLP + n], s);
    }
#pragma unroll
    for (int o = 16; o > 0; o >>= 1) s += __shfl_xor_sync(0xffffffffu, s, o);
    if (lane == 0) {
        float val = fmaxf(s + bb1[n], 0.f);
        __nv_bfloat16 h = __float2bfloat16(val);
        g_hhi[b * DMLP + n] = h;
        g_hlo[b * DMLP + n] = __float2bfloat16(val - __bfloat162float(h));
    }
}

// =====================================================================
// Bias MLP stage 2 via WMMA split (unchanged)
// =====================================================================
#define BW_WHI 0
#define BW_WLO 34816
#define BW_AHH 69632
#define BW_AHL 78336
#define BW_SMEM 87040
#define HPAD 136

__global__ __launch_bounds__(256, 2) void bias_wmma(const float* __restrict__ Wb2,
                                                    const float* __restrict__ bb2) {
    extern __shared__ char sm[];
    __nv_bfloat16* Whi = (__nv_bfloat16*)(sm + BW_WHI);
    __nv_bfloat16* Wlo = (__nv_bfloat16*)(sm + BW_WLO);
    __nv_bfloat16* Ahh = (__nv_bfloat16*)(sm + BW_AHH);
    __nv_bfloat16* Ahl = (__nv_bfloat16*)(sm + BW_AHL);
    float*         Cs  = (float*)(sm + BW_AHH);          // union, after MMA

    const int t = threadIdx.x;
    const int warp = t >> 5;
    const int wm = warp & 1;
    const int wn = warp >> 1;
    const int n0 = blockIdx.x * 128;

#pragma unroll
    for (int j = 0; j < 2; j++) {
        int idx = t + j * 256;
        int r = idx >> 4, c8 = (idx & 15) * 8;
        *(uint4*)&Ahh[r * HPAD + c8] = *(const uint4*)&g_hhi[r * DMLP + c8];
        *(uint4*)&Ahl[r * HPAD + c8] = *(const uint4*)&g_hlo[r * DMLP + c8];
    }
#pragma unroll
    for (int j = 0; j < 16; j++) {
        int idx = t + j * 256;
        int k = idx >> 5, n4 = (idx & 31) * 4;
        float4 w = *(const float4*)&Wb2[(size_t)k * LLSQ + n0 + n4];
        __nv_bfloat162 h0, l0, h1, l1;
        split2(w.x, w.y, h0, l0);
        split2(w.z, w.w, h1, l1);
        *(__nv_bfloat162*)&Whi[k * HPAD + n4]     = h0;
        *(__nv_bfloat162*)&Whi[k * HPAD + n4 + 2] = h1;
        *(__nv_bfloat162*)&Wlo[k * HPAD + n4]     = l0;
        *(__nv_bfloat162*)&Wlo[k * HPAD + n4 + 2] = l1;
    }
    __syncthreads();

    wmma::fragment<wmma::accumulator, 16, 16, 16, float> c2[2];
    wmma::fill_fragment(c2[0], 0.0f);
    wmma::fill_fragment(c2[1], 0.0f);

#pragma unroll
    for (int ks = 0; ks < 8; ks++) {
        wmma::fragment<wmma::matrix_a, 16, 16, 16, __nv_bfloat16,
                       wmma::row_major> ah, al;
        wmma::load_matrix_sync(ah, Ahh + (wm * 16) * HPAD + ks * 16, HPAD);
        wmma::load_matrix_sync(al, Ahl + (wm * 16) * HPAD + ks * 16, HPAD);
#pragma unroll
        for (int nf = 0; nf < 2; nf++) {
            wmma::fragment<wmma::matrix_b, 16, 16, 16, __nv_bfloat16,
                           wmma::row_major> bh, bl;
            const int nc = wn * 32 + nf * 16;
            wmma::load_matrix_sync(bh, Whi + (ks * 16) * HPAD + nc, HPAD);
            wmma::load_matrix_sync(bl, Wlo + (ks * 16) * HPAD + nc, HPAD);
            wmma::mma_sync(c2[nf], ah, bh, c2[nf]);
            wmma::mma_sync(c2[nf], ah, bl, c2[nf]);
            wmma::mma_sync(c2[nf], al, bh, c2[nf]);
        }
    }

    __syncthreads();
#pragma unroll
    for (int nf = 0; nf < 2; nf++)
        wmma::store_matrix_sync(Cs + (wm * 16) * HPAD + wn * 32 + nf * 16,
                                c2[nf], HPAD, wmma::mem_row_major);
    __syncthreads();

#pragma unroll
    for (int j = 0; j < 4; j++) {
        int idx = t + j * 256;
        int r = idx >> 5, c4 = (idx & 31) * 4;
        float4 v = *(float4*)&Cs[r * HPAD + c4];
        float4 b2 = *(const float4*)&bb2[n0 + c4];
        v.x += b2.x; v.y += b2.y; v.z += b2.z; v.w += b2.w;
        *(float4*)&g_bias[(size_t)r * LLSQ + n0 + c4] = v;
    }
}

// =====================================================================
// WMMA fused attention with register prefetch on K/V tiles (unchanged).
// =====================================================================
#define SSPAD 520
#define AT_KV   66560
#define AT_VLO  83968
#define AT_ABH  101376
#define AT_ABL  105984
#define ATTN_SMEM 110592
#define QPAD 136
#define APAD 72

__global__ __launch_bounds__(256, 2) void attn_wmma(const unsigned int* __restrict__ mask,
                                                    float* __restrict__ out) {
    extern __shared__ char sm[];
    float*         Ss   = (float*)sm;                     // [32][520]
    __nv_bfloat16* Qsm  = (__nv_bfloat16*)(sm + AT_KV);   // [32][136]
    __nv_bfloat16* Ksm  = (__nv_bfloat16*)(sm + AT_KV);   // [64][136]
    __nv_bfloat16* Vhi  = (__nv_bfloat16*)(sm + AT_KV);   // [64][136]
    __nv_bfloat16* Vlo  = (__nv_bfloat16*)(sm + AT_VLO);  // [64][136]
    __nv_bfloat16* Abhi = (__nv_bfloat16*)(sm + AT_ABH);  // [32][72]
    __nv_bfloat16* Ablo = (__nv_bfloat16*)(sm + AT_ABL);  // [32][72]

    const int t    = threadIdx.x;
    const int lane = t & 31;
    const int warp = t >> 5;
    const int b    = blockIdx.y;
    const int row0 = blockIdx.x * 32;

    const __nv_bfloat16* __restrict__ qb = g_qb + (size_t)(b * LL + row0) * DQK;
    const __nv_bfloat16* __restrict__ kb = g_kb + (size_t)b * LL * DQK;
    const __nv_bfloat16* __restrict__ vh = g_vhi + (size_t)b * LL * DQK;
    const __nv_bfloat16* __restrict__ vl = g_vlo + (size_t)b * LL * DQK;

#pragma unroll
    for (int j = 0; j < 2; j++) {
        int idx = t + j * 256;
        int r = idx >> 4, c8 = (idx & 15) * 8;
        *(uint4*)&Qsm[r * QPAD + c8] = *(const uint4*)&qb[r * DQK + c8];
    }
    __syncthreads();

    const int wm = warp & 1;
    const int wn = warp >> 1;
    wmma::fragment<wmma::matrix_a, 16, 16, 16, __nv_bfloat16,
                   wmma::row_major> qa[8];
#pragma unroll
    for (int ks = 0; ks < 8; ks++)
        wmma::load_matrix_sync(qa[ks], Qsm + (wm * 16) * QPAD + ks * 16, QPAD);

    uint4 kreg[4];
#pragma unroll
    for (int j = 0; j < 4; j++) {
        int idx = t + j * 256;
        int r = idx >> 4, c8 = (idx & 15) * 8;
        kreg[j] = *(const uint4*)&kb[(size_t)r * DQK + c8];
    }
    __syncthreads();

    for (int ct = 0; ct < 8; ct++) {
#pragma unroll
        for (int j = 0; j < 4; j++) {
            int idx = t + j * 256;
            int r = idx >> 4, c8 = (idx & 15) * 8;
            *(uint4*)&Ksm[r * QPAD + c8] = kreg[j];
        }
        __syncthreads();
        if (ct < 7) {
#pragma unroll
            for (int j = 0; j < 4; j++) {
                int idx = t + j * 256;
                int r = idx >> 4, c8 = (idx & 15) * 8;
                kreg[j] = *(const uint4*)&kb[(size_t)((ct + 1) * 64 + r) * DQK + c8];
            }
        }

        wmma::fragment<wmma::accumulator, 16, 16, 16, float> c1;
        wmma::fill_fragment(c1, 0.0f);
#pragma unroll
        for (int ks = 0; ks < 8; ks++) {
            wmma::fragment<wmma::matrix_b, 16, 16, 16, __nv_bfloat16,
                           wmma::col_major> kf;
            wmma::load_matrix_sync(kf, Ksm + (wn * 16) * QPAD + ks * 16, QPAD);
            wmma::mma_sync(c1, qa[ks], kf, c1);
        }
        wmma::store_matrix_sync(Ss + (wm * 16) * SSPAD + ct * 64 + wn * 16,
                                c1, SSPAD, wmma::mem_row_major);
        __syncthreads();
    }

    const float inv_scale = 0.08838834764831845f;   // 1/sqrt(128)
#pragma unroll
    for (int j = 0; j < 4; j++) {
        const int r = warp * 4 + j;
        const unsigned int* mrow = mask + (size_t)(b * LL + row0 + r) * LL;
        float mx = -1e30f;
        for (int m = lane; m < LL; m += 32) {
            float s = (mrow[m] != 0u) ? 1e-9f : Ss[r * SSPAD + m] * inv_scale;
            Ss[r * SSPAD + m] = s;
            mx = fmaxf(mx, s);
        }
#pragma unroll
        for (int o = 16; o > 0; o >>= 1) mx = fmaxf(mx, __shfl_xor_sync(0xffffffffu, mx, o));
        float sum = 0.f;
        for (int m = lane; m < LL; m += 32) {
            float e = __expf(Ss[r * SSPAD + m] - mx);
            Ss[r * SSPAD + m] = e;
            sum += e;
        }
#pragma unroll
        for (int o = 16; o > 0; o >>= 1) sum += __shfl_xor_sync(0xffffffffu, sum, o);
        const float inv = 1.0f / sum;
        const float* __restrict__ brow = g_bias + (size_t)(b * LL + row0 + r) * LL;
        for (int m = lane; m < LL; m += 32)
            Ss[r * SSPAD + m] = Ss[r * SSPAD + m] * inv + brow[m];
    }

    uint4 vhreg[4], vlreg[4];
#pragma unroll
    for (int j = 0; j < 4; j++) {
        int idx = t + j * 256;
        int r = idx >> 4, c8 = (idx & 15) * 8;
        vhreg[j] = *(const uint4*)&vh[(size_t)r * DQK + c8];
        vlreg[j] = *(const uint4*)&vl[(size_t)r * DQK + c8];
    }
    __syncthreads();

    const int wn2 = warp >> 1;
    wmma::fragment<wmma::accumulator, 16, 16, 16, float> o2[2];
    wmma::fill_fragment(o2[0], 0.0f);
    wmma::fill_fragment(o2[1], 0.0f);

    for (int mt = 0; mt < 8; mt++) {
#pragma unroll
        for (int j = 0; j < 4; j++) {
            int idx = t + j * 256;
            int r = idx >> 4, c8 = (idx & 15) * 8;
            *(uint4*)&Vhi[r * QPAD + c8] = vhreg[j];
            *(uint4*)&Vlo[r * QPAD + c8] = vlreg[j];
        }
#pragma unroll
        for (int j = 0; j < 4; j++) {
            int idx = t + j * 256;
            int r = idx >> 5, c2 = (idx & 31) * 2;
            float2 s2 = *(float2*)&Ss[r * SSPAD + mt * 64 + c2];
            __nv_bfloat162 hi, lo;
            split2(s2.x, s2.y, hi, lo);
            *(__nv_bfloat162*)&Abhi[r * APAD + c2] = hi;
            *(__nv_bfloat162*)&Ablo[r * APAD + c2] = lo;
        }
        __syncthreads();
        if (mt < 7) {
#pragma unroll
            for (int j = 0; j < 4; j++) {
                int idx = t + j * 256;
                int r = idx >> 4, c8 = (idx & 15) * 8;
                size_t o = (size_t)((mt + 1) * 64 + r) * DQK + c8;
                vhreg[j] = *(const uint4*)&vh[o];
                vlreg[j] = *(const uint4*)&vl[o];
            }
        }

#pragma unroll
        for (int ks = 0; ks < 4; ks++) {
            wmma::fragment<wmma::matrix_a, 16, 16, 16, __nv_bfloat16,
                           wmma::row_major> ah, al;
            wmma::load_matrix_sync(ah, Abhi + (wm * 16) * APAD + ks * 16, APAD);
            wmma::load_matrix_sync(al, Ablo + (wm * 16) * APAD + ks * 16, APAD);
#pragma unroll
            for (int nf = 0; nf < 2; nf++) {
                wmma::fragment<wmma::matrix_b, 16, 16, 16, __nv_bfloat16,
                               wmma::row_major> vhf, vlf;
                const int nc = wn2 * 32 + nf * 16;
                wmma::load_matrix_sync(vhf, Vhi + (ks * 16) * QPAD + nc, QPAD);
                wmma::load_matrix_sync(vlf, Vlo + (ks * 16) * QPAD + nc, QPAD);
                wmma::mma_sync(o2[nf], ah, vhf, o2[nf]);
                wmma::mma_sync(o2[nf], ah, vlf, o2[nf]);
                wmma::mma_sync(o2[nf], al, vhf, o2[nf]);
            }
        }
        __syncthreads();
    }

#pragma unroll
    for (int nf = 0; nf < 2; nf++)
        wmma::store_matrix_sync(
            &out[(size_t)(b * LL + row0 + wm * 16) * DQK + wn2 * 32 + nf * 16],
            o2[nf], DQK, wmma::mem_row_major);
}

// =====================================================================
// Launch: two-stream fork/join captured via events (unchanged).
// =====================================================================
static cudaStream_t g_s1 = nullptr;
static cudaEvent_t  g_evFork = nullptr, g_evJoin = nullptr;

extern "C" void kernel_launch(void* const* d_in, const int* in_sizes, int n_in,
                              void* d_out, int out_size) {
    const float* query = (const float*)d_in[0];
    const float* key_  = (const float*)d_in[1];
    const float* value = (const float*)d_in[2];
    const float* sf    = (const float*)d_in[3];
    const unsigned int* mask = (const unsigned int*)d_in[4];
    const float* Wq  = (const float*)d_in[5];
    const float* bq  = (const float*)d_in[6];
    const float* Wk  = (const float*)d_in[7];
    const float* bk  = (const float*)d_in[8];
    const float* Wv  = (const float*)d_in[9];
    const float* bv  = (const float*)d_in[10];
    const float* Wb1 = (const float*)d_in[11];
    const float* bb1 = (const float*)d_in[12];
    const float* Wb2 = (const float*)d_in[13];
    const float* bb2 = (const float*)d_in[14];
    float* out = (float*)d_out;

    (void)in_sizes; (void)n_in; (void)out_size;

    if (g_s1 == nullptr) {
        cudaStreamCreateWithFlags(&g_s1, cudaStreamNonBlocking);
        cudaEventCreateWithFlags(&g_evFork, cudaEventDisableTiming);
        cudaEventCreateWithFlags(&g_evJoin, cudaEventDisableTiming);
        cudaFuncSetAttribute(proj3_wmma,
                             cudaFuncAttributeMaxDynamicSharedMemorySize, PROJ_SMEM);
        cudaFuncSetAttribute(bias_wmma,
                             cudaFuncAttributeMaxDynamicSharedMemorySize, BW_SMEM);
        cudaFuncSetAttribute(attn_wmma,
                             cudaFuncAttributeMaxDynamicSharedMemorySize, ATTN_SMEM);
    }

    // fork: side chain mlp1 -> bias (independent of proj chain)
    cudaEventRecord(g_evFork, (cudaStream_t)0);
    cudaStreamWaitEvent(g_s1, g_evFork, 0);
    mlp1_kernel<<<512, 256, 0, g_s1>>>(sf, Wb1, bb1);
    bias_wmma<<<LLSQ / 128, 256, BW_SMEM, g_s1>>>(Wb2, bb2);
    cudaEventRecord(g_evJoin, g_s1);

    // main chain on capture-origin stream
    prep_w<<<dim3(256, 3), 256>>>(Wq, Wk, Wv);
    proj3_wmma<<<dim3(NB * LL / 128, 3), 256, PROJ_SMEM>>>(query, key_, value,
                                                           bq, bk, bv);

    // join, then attention
    cudaStreamWaitEvent((cudaStream_t)0, g_evJoin, 0);
    attn_wmma<<<dim3(LL / 32, NB), 256, ATTN_SMEM>>>(mask, out);
}